// round 1
// baseline (speedup 1.0000x reference)
#include <cuda_runtime.h>
#include <cuda_bf16.h>
#include <math.h>

// ---------------------------------------------------------------------------
// Problem constants
// ---------------------------------------------------------------------------
#define Bz   4
#define Sz   1024
#define Dz   1024
#define Hh   16
#define Gg   8
#define HDz  64
#define Ez   8
#define TOPK 2
#define EDz  2048
#define GHz  512
#define Tz   (Bz*Sz)          // 4096 tokens

// ---------------------------------------------------------------------------
// Scratch (static device memory; no allocations allowed)
// ---------------------------------------------------------------------------
__device__ float g_h1 [Tz*Dz];        // LN1 out
__device__ float g_q  [Tz*(Gg*HDz)];  // Q  [T,512]
__device__ float g_k  [Tz*Dz];        // K  [T,1024]
__device__ float g_v  [Tz*Dz];        // V  [T,1024]
__device__ float g_ao [Tz*Dz];        // attention out (pre-Wo)
__device__ float g_x1 [Tz*Dz];        // x + attn
__device__ float g_h2 [Tz*Dz];        // LN2 out
__device__ float g_gh [Tz*GHz];       // gate hidden
__device__ float g_w  [Tz*TOPK];      // top-k renormalized weights
__device__ int   g_cnt[Ez];           // per-expert assignment counts
__device__ int   g_elist[Ez*Tz];      // per-expert assignment ids (a = 2t+k)
__device__ float g_hid[Tz*TOPK*EDz];  // expert hidden, indexed by assignment id
__device__ float g_eo [Tz*TOPK*Dz];   // expert out, indexed by assignment id

// ---------------------------------------------------------------------------
// LayerNorm: one block per token row of 1024
// ---------------------------------------------------------------------------
__global__ __launch_bounds__(256) void ln_kernel(
    const float* __restrict__ X, const float* __restrict__ g,
    const float* __restrict__ b, float* __restrict__ O)
{
    int t = blockIdx.x;
    int tid = threadIdx.x;
    const float4* x4 = (const float4*)(X + (size_t)t * Dz);
    float4 xv = x4[tid];
    float s  = xv.x + xv.y + xv.z + xv.w;
    float ss = xv.x*xv.x + xv.y*xv.y + xv.z*xv.z + xv.w*xv.w;
    #pragma unroll
    for (int off = 16; off; off >>= 1) {
        s  += __shfl_xor_sync(0xffffffffu, s,  off);
        ss += __shfl_xor_sync(0xffffffffu, ss, off);
    }
    __shared__ float sh_s[8], sh_ss[8];
    if ((tid & 31) == 0) { sh_s[tid >> 5] = s; sh_ss[tid >> 5] = ss; }
    __syncthreads();
    if (tid < 32) {
        float a = (tid < 8) ? sh_s[tid]  : 0.f;
        float c = (tid < 8) ? sh_ss[tid] : 0.f;
        #pragma unroll
        for (int off = 4; off; off >>= 1) {
            a += __shfl_xor_sync(0xffffffffu, a, off);
            c += __shfl_xor_sync(0xffffffffu, c, off);
        }
        if (tid == 0) { sh_s[0] = a; sh_ss[0] = c; }
    }
    __syncthreads();
    float mu  = sh_s[0]  * (1.f / Dz);
    float var = sh_ss[0] * (1.f / Dz) - mu * mu;
    float inv = rsqrtf(var + 1e-5f);
    float4 gv = ((const float4*)g)[tid];
    float4 bv = ((const float4*)b)[tid];
    float4 o;
    o.x = (xv.x - mu) * inv * gv.x + bv.x;
    o.y = (xv.y - mu) * inv * gv.y + bv.y;
    o.z = (xv.z - mu) * inv * gv.z + bv.z;
    o.w = (xv.w - mu) * inv * gv.w + bv.w;
    ((float4*)(O + (size_t)t * Dz))[tid] = o;
}

// ---------------------------------------------------------------------------
// Generic tiled SGEMM: C[M,N] = act(A[M,K] @ B[K,N] + bias) (+ resid)
// BM=BN=128, BK=16, 256 threads, 8x8 per thread.
// GATHER: rows come from elist (per blockIdx.z expert); A row = a>>ashift,
//         C row = a. Dense path: blockIdx.z==0, row = m.
// ---------------------------------------------------------------------------
template<int ACT, bool GATHER, bool RESID>
__global__ __launch_bounds__(256) void gemm_kernel(
    const float* __restrict__ A, const float* __restrict__ B,
    const float* __restrict__ bias, float* __restrict__ C,
    int M, int N, int K,
    const float* __restrict__ resid,
    const int* __restrict__ elist, const int* __restrict__ cnt, int ashift)
{
    __shared__ float As[16][128];
    __shared__ float Bs[16][128];

    int e = blockIdx.z;
    const float* Bp = B    + (size_t)e * K * N;
    const float* bp = bias + (size_t)e * N;
    int mcount = GATHER ? cnt[e] : M;
    int m0 = blockIdx.y * 128;
    if (m0 >= mcount) return;
    int n0 = blockIdx.x * 128;
    const int* lst = GATHER ? (elist + e * Tz) : (const int*)nullptr;

    int tid  = threadIdx.x;
    int arow = tid >> 1;
    int acol = (tid & 1) * 8;
    int am   = m0 + arow;
    bool avalid = am < mcount;
    size_t arowg = 0;
    if (GATHER) {
        int a = avalid ? lst[am] : 0;
        arowg = (size_t)(a >> ashift);
    } else {
        arowg = (size_t)(avalid ? am : 0);
    }
    const float* Aptr = A + arowg * (size_t)K + acol;

    int brow = tid >> 4;
    int bcol = (tid & 15) * 8;
    const float* Bptr = Bp + (size_t)brow * N + n0 + bcol;

    float acc[8][8];
    #pragma unroll
    for (int i = 0; i < 8; i++)
        #pragma unroll
        for (int j = 0; j < 8; j++) acc[i][j] = 0.f;

    int ty = tid >> 4, tx = tid & 15;

    for (int k0 = 0; k0 < K; k0 += 16) {
        float4 a0, a1;
        if (avalid) {
            a0 = *(const float4*)(Aptr + k0);
            a1 = *(const float4*)(Aptr + k0 + 4);
        } else {
            a0 = make_float4(0.f,0.f,0.f,0.f);
            a1 = make_float4(0.f,0.f,0.f,0.f);
        }
        As[acol+0][arow] = a0.x; As[acol+1][arow] = a0.y;
        As[acol+2][arow] = a0.z; As[acol+3][arow] = a0.w;
        As[acol+4][arow] = a1.x; As[acol+5][arow] = a1.y;
        As[acol+6][arow] = a1.z; As[acol+7][arow] = a1.w;

        float4 b0 = *(const float4*)(Bptr + (size_t)k0 * N);
        float4 b1 = *(const float4*)(Bptr + (size_t)k0 * N + 4);
        *(float4*)&Bs[brow][bcol]     = b0;
        *(float4*)&Bs[brow][bcol + 4] = b1;
        __syncthreads();

        #pragma unroll
        for (int kk = 0; kk < 16; kk++) {
            float ar[8], br[8];
            *(float4*)(ar)     = *(const float4*)&As[kk][ty*8];
            *(float4*)(ar + 4) = *(const float4*)&As[kk][ty*8 + 4];
            *(float4*)(br)     = *(const float4*)&Bs[kk][tx*8];
            *(float4*)(br + 4) = *(const float4*)&Bs[kk][tx*8 + 4];
            #pragma unroll
            for (int i = 0; i < 8; i++)
                #pragma unroll
                for (int j = 0; j < 8; j++)
                    acc[i][j] += ar[i] * br[j];
        }
        __syncthreads();
    }

    #pragma unroll
    for (int i = 0; i < 8; i++) {
        int m = m0 + ty*8 + i;
        if (m >= mcount) continue;
        size_t crow = GATHER ? (size_t)lst[m] : (size_t)m;
        float* Cp = C + crow * (size_t)N + n0 + tx*8;
        const float* bb = bp + n0 + tx*8;
        const float* rp = RESID ? (resid + crow * (size_t)N + n0 + tx*8) : (const float*)nullptr;
        #pragma unroll
        for (int j = 0; j < 8; j++) {
            float v = acc[i][j] + bb[j];
            if (ACT == 1) v = fmaxf(v, 0.f);
            if (ACT == 2) v = 0.5f * v * (1.f + erff(v * 0.70710678118654752f));
            if (RESID)    v += rp[j];
            Cp[j] = v;
        }
    }
}

// ---------------------------------------------------------------------------
// Flash-style attention. grid = (S/64, H, B), 256 threads.
// Thread (r = tid/4, sub = tid%4): owns Q row r, score cols sub*16..+16,
// output cols sub*16..+16. Online softmax, K/V tiles of 64 in smem.
// ---------------------------------------------------------------------------
__global__ __launch_bounds__(256, 2) void attn_kernel(
    const float* __restrict__ Q, const float* __restrict__ K,
    const float* __restrict__ V, float* __restrict__ O)
{
    __shared__ float sm[2 * 64 * 65];   // staging: Q first, then K | V
    float* Ks = sm;
    float* Vs = sm + 64 * 65;

    int h = blockIdx.y, b = blockIdx.z, g = h >> 1;
    int q0 = blockIdx.x * 64;
    int tid = threadIdx.x;
    int r = tid >> 2, sub = tid & 3;

    // stage Q into smem (scaled by 1/sqrt(HD)), then into registers
    for (int i = tid; i < 64 * 64; i += 256) {
        int row = i >> 6, col = i & 63;
        Ks[row * 65 + col] =
            Q[((size_t)(b * Sz + q0 + row)) * (Gg * HDz) + g * HDz + col] * 0.125f;
    }
    __syncthreads();
    float qr[64];
    #pragma unroll
    for (int d = 0; d < 64; d++) qr[d] = Ks[r * 65 + d];
    __syncthreads();

    float mrow = -INFINITY, lrow = 0.f;
    float acc[16];
    #pragma unroll
    for (int c = 0; c < 16; c++) acc[c] = 0.f;

    for (int kt = 0; kt < Sz / 64; kt++) {
        for (int i = tid; i < 64 * 64; i += 256) {
            int row = i >> 6, col = i & 63;
            size_t tt = (size_t)(b * Sz + kt * 64 + row);
            Ks[row * 65 + col] = K[tt * Dz + h * HDz + col];
            Vs[row * 65 + col] = V[tt * Dz + h * HDz + col];
        }
        __syncthreads();

        float p[16];
        float mnew = mrow;
        #pragma unroll
        for (int jj = 0; jj < 16; jj++) {
            int j = sub * 16 + jj;
            float s = 0.f;
            #pragma unroll
            for (int d = 0; d < 64; d++) s += qr[d] * Ks[j * 65 + d];
            p[jj] = s;
            mnew = fmaxf(mnew, s);
        }
        mnew = fmaxf(mnew, __shfl_xor_sync(0xffffffffu, mnew, 1));
        mnew = fmaxf(mnew, __shfl_xor_sync(0xffffffffu, mnew, 2));

        float scale = expf(mrow - mnew);   // 0 on first tile (mrow = -inf)
        float ls = 0.f;
        #pragma unroll
        for (int jj = 0; jj < 16; jj++) {
            p[jj] = expf(p[jj] - mnew);
            ls += p[jj];
        }
        ls += __shfl_xor_sync(0xffffffffu, ls, 1);
        ls += __shfl_xor_sync(0xffffffffu, ls, 2);
        lrow = lrow * scale + ls;
        mrow = mnew;
        #pragma unroll
        for (int c = 0; c < 16; c++) acc[c] *= scale;

        #pragma unroll
        for (int src = 0; src < 4; src++) {
            #pragma unroll
            for (int jj = 0; jj < 16; jj++) {
                float pv = __shfl_sync(0xffffffffu, p[jj], src, 4);
                int j = src * 16 + jj;
                #pragma unroll
                for (int cc = 0; cc < 16; cc++)
                    acc[cc] += pv * Vs[j * 65 + sub * 16 + cc];
            }
        }
        __syncthreads();
    }

    float inv = 1.f / lrow;
    size_t t = (size_t)(b * Sz + q0 + r);
    #pragma unroll
    for (int cc = 0; cc < 16; cc++)
        O[t * Dz + h * HDz + sub * 16 + cc] = acc[cc] * inv;
}

// ---------------------------------------------------------------------------
// Gate head (N=8) + softmax + top-2 + renorm + routing. One warp per token.
// ---------------------------------------------------------------------------
__global__ __launch_bounds__(256) void gate_route_kernel(
    const float* __restrict__ GH, const float* __restrict__ gw2,
    const float* __restrict__ gb2,
    float* __restrict__ wout, int* __restrict__ cnt, int* __restrict__ elist)
{
    int warp = threadIdx.x >> 5;
    int lane = threadIdx.x & 31;
    int t = blockIdx.x * 8 + warp;
    if (t >= Tz) return;

    float logit[Ez];
    #pragma unroll
    for (int o = 0; o < Ez; o++) {
        float s = 0.f;
        for (int i = lane; i < GHz; i += 32)
            s += GH[(size_t)t * GHz + i] * gw2[(size_t)i * Ez + o];
        #pragma unroll
        for (int off = 16; off; off >>= 1)
            s += __shfl_xor_sync(0xffffffffu, s, off);
        logit[o] = s + gb2[o];
    }
    if (lane == 0) {
        float m = logit[0];
        #pragma unroll
        for (int o = 1; o < Ez; o++) m = fmaxf(m, logit[o]);
        float w[Ez], sum = 0.f;
        #pragma unroll
        for (int o = 0; o < Ez; o++) { w[o] = expf(logit[o] - m); sum += w[o]; }
        float invs = 1.f / sum;
        #pragma unroll
        for (int o = 0; o < Ez; o++) w[o] *= invs;
        int i0 = 0; float v0 = w[0];
        #pragma unroll
        for (int o = 1; o < Ez; o++) if (w[o] > v0) { v0 = w[o]; i0 = o; }
        int i1 = -1; float v1 = -1.f;
        #pragma unroll
        for (int o = 0; o < Ez; o++)
            if (o != i0 && w[o] > v1) { v1 = w[o]; i1 = o; }
        // renormalizing softmax over the two selected probabilities
        float e1 = expf(v1 - v0);
        float den = 1.f + e1;
        wout[2*t + 0] = 1.f / den;
        wout[2*t + 1] = e1 / den;
        int p0 = atomicAdd(&cnt[i0], 1);
        elist[i0 * Tz + p0] = 2*t + 0;
        int p1 = atomicAdd(&cnt[i1], 1);
        elist[i1 * Tz + p1] = 2*t + 1;
    }
}

__global__ void zero_counts_kernel(int* cnt)
{
    if (threadIdx.x < Ez) cnt[threadIdx.x] = 0;
}

// ---------------------------------------------------------------------------
// Final combine: out = x1 + w0*eo[2t] + w1*eo[2t+1]
// ---------------------------------------------------------------------------
__global__ __launch_bounds__(256) void combine_kernel(
    const float* __restrict__ x1, const float* __restrict__ eo,
    const float* __restrict__ w, float* __restrict__ out)
{
    int idx = blockIdx.x * 256 + threadIdx.x;   // float4 index, Tz*Dz/4 total
    int t = idx >> 8;                            // 256 float4 per row
    int c = idx & 255;
    float w0 = w[2*t], w1 = w[2*t + 1];
    float4 a  = ((const float4*)x1)[idx];
    float4 e0 = ((const float4*)(eo + (size_t)(2*t)     * Dz))[c];
    float4 e1 = ((const float4*)(eo + (size_t)(2*t + 1) * Dz))[c];
    float4 r;
    r.x = a.x + w0 * e0.x + w1 * e1.x;
    r.y = a.y + w0 * e0.y + w1 * e1.y;
    r.z = a.z + w0 * e0.z + w1 * e1.z;
    r.w = a.w + w0 * e0.w + w1 * e1.w;
    ((float4*)out)[idx] = r;
}

// ---------------------------------------------------------------------------
// Host launch
// ---------------------------------------------------------------------------
extern "C" void kernel_launch(void* const* d_in, const int* in_sizes, int n_in,
                              void* d_out, int out_size)
{
    const float* x    = (const float*)d_in[0];
    const float* wq   = (const float*)d_in[1];
    const float* bq   = (const float*)d_in[2];
    const float* wk   = (const float*)d_in[3];
    const float* bk   = (const float*)d_in[4];
    const float* wv   = (const float*)d_in[5];
    const float* bv   = (const float*)d_in[6];
    const float* wo   = (const float*)d_in[7];
    const float* bo   = (const float*)d_in[8];
    const float* ln1g = (const float*)d_in[9];
    const float* ln1b = (const float*)d_in[10];
    const float* ln2g = (const float*)d_in[11];
    const float* ln2b = (const float*)d_in[12];
    const float* gw1  = (const float*)d_in[13];
    const float* gb1  = (const float*)d_in[14];
    const float* gw2  = (const float*)d_in[15];
    const float* gb2  = (const float*)d_in[16];
    const float* ew1  = (const float*)d_in[17];
    const float* eb1  = (const float*)d_in[18];
    const float* ew2  = (const float*)d_in[19];
    const float* eb2  = (const float*)d_in[20];
    float* out = (float*)d_out;

    float *h1, *q, *k, *v, *ao, *x1, *h2, *gh, *w, *hid, *eo;
    int *cnt, *elist;
    cudaGetSymbolAddress((void**)&h1,   g_h1);
    cudaGetSymbolAddress((void**)&q,    g_q);
    cudaGetSymbolAddress((void**)&k,    g_k);
    cudaGetSymbolAddress((void**)&v,    g_v);
    cudaGetSymbolAddress((void**)&ao,   g_ao);
    cudaGetSymbolAddress((void**)&x1,   g_x1);
    cudaGetSymbolAddress((void**)&h2,   g_h2);
    cudaGetSymbolAddress((void**)&gh,   g_gh);
    cudaGetSymbolAddress((void**)&w,    g_w);
    cudaGetSymbolAddress((void**)&hid,  g_hid);
    cudaGetSymbolAddress((void**)&eo,   g_eo);
    cudaGetSymbolAddress((void**)&cnt,  g_cnt);
    cudaGetSymbolAddress((void**)&elist,g_elist);

    zero_counts_kernel<<<1, 32>>>(cnt);

    // LN1
    ln_kernel<<<Tz, 256>>>(x, ln1g, ln1b, h1);

    // QKV projections
    gemm_kernel<0,false,false><<<dim3(4, 32, 1), 256>>>(
        h1, wq, bq, q, Tz, Gg*HDz, Dz, nullptr, nullptr, nullptr, 0);
    gemm_kernel<0,false,false><<<dim3(8, 32, 1), 256>>>(
        h1, wk, bk, k, Tz, Dz, Dz, nullptr, nullptr, nullptr, 0);
    gemm_kernel<0,false,false><<<dim3(8, 32, 1), 256>>>(
        h1, wv, bv, v, Tz, Dz, Dz, nullptr, nullptr, nullptr, 0);

    // Attention
    attn_kernel<<<dim3(Sz/64, Hh, Bz), 256>>>(q, k, v, ao);

    // Output projection + residual
    gemm_kernel<0,false,true><<<dim3(8, 32, 1), 256>>>(
        ao, wo, bo, x1, Tz, Dz, Dz, x, nullptr, nullptr, 0);

    // LN2
    ln_kernel<<<Tz, 256>>>(x1, ln2g, ln2b, h2);

    // Gate MLP layer 1 (ReLU)
    gemm_kernel<1,false,false><<<dim3(4, 32, 1), 256>>>(
        h2, gw1, gb1, gh, Tz, GHz, Dz, nullptr, nullptr, nullptr, 0);

    // Gate head + top-2 routing
    gate_route_kernel<<<Tz/8, 256>>>(gh, gw2, gb2, w, cnt, elist);

    // Expert FFN layer 1 (GELU), gathered by assignment lists
    gemm_kernel<2,true,false><<<dim3(EDz/128, Tz/128, Ez), 256>>>(
        h2, ew1, eb1, hid, Tz, EDz, Dz, nullptr, elist, cnt, 1);

    // Expert FFN layer 2
    gemm_kernel<0,true,false><<<dim3(Dz/128, Tz/128, Ez), 256>>>(
        hid, ew2, eb2, eo, Tz, Dz, EDz, nullptr, elist, cnt, 0);

    // Combine + residual -> output
    combine_kernel<<<(Tz*Dz/4)/256, 256>>>(x1, eo, w, out);
}

// round 2
// speedup vs baseline: 3.7418x; 3.7418x over previous
#include <cuda_runtime.h>
#include <math.h>
#include <stdint.h>

// ---------------------------------------------------------------------------
// Problem constants
// ---------------------------------------------------------------------------
#define Bz   4
#define Sz   1024
#define Dz   1024
#define Hh   16
#define Gg   8
#define HDz  64
#define Ez   8
#define EDz  2048
#define GHz  512
#define Tz   (Bz*Sz)          // 4096 tokens

// ---------------------------------------------------------------------------
// Scratch (static device memory)
// ---------------------------------------------------------------------------
__device__ float g_h1 [Tz*Dz];
__device__ float g_q  [Tz*512];
__device__ float g_k  [Tz*Dz];
__device__ float g_v  [Tz*Dz];
__device__ float g_sc [(size_t)Bz*Hh*Sz*Sz];   // 256 MB scores/probs
__device__ float g_ao [Tz*Dz];
__device__ float g_x1 [Tz*Dz];
__device__ float g_h2 [Tz*Dz];
__device__ float g_gh [Tz*GHz];
__device__ float g_w  [Tz*2];
__device__ int   g_cnt[Ez];
__device__ int   g_elist[Ez*Tz];
__device__ float g_hid[(size_t)Tz*2*EDz];
__device__ float g_eo [(size_t)Tz*2*Dz];

// ---------------------------------------------------------------------------
// Helpers
// ---------------------------------------------------------------------------
__device__ __forceinline__ uint32_t s2u(const void* p){
    return (uint32_t)__cvta_generic_to_shared(p);
}
__device__ __forceinline__ void cpa16(uint32_t d, const void* s, bool v){
    asm volatile("cp.async.cg.shared.global [%0], [%1], 16, %2;\n"
                 :: "r"(d), "l"(s), "r"(v ? 16 : 0));
}
__device__ __forceinline__ void cp_commit(){ asm volatile("cp.async.commit_group;\n"); }
__device__ __forceinline__ void cp_wait0(){ asm volatile("cp.async.wait_group 0;\n"); }
__device__ __forceinline__ uint32_t f2tf(float x){
    uint32_t r; asm("cvt.rna.tf32.f32 %0, %1;" : "=r"(r) : "f"(x)); return r;
}
__device__ __forceinline__ void mma8(float* c, const uint32_t* a, const uint32_t* b){
    asm volatile("mma.sync.aligned.m16n8k8.row.col.f32.tf32.tf32.f32 "
        "{%0,%1,%2,%3},{%4,%5,%6,%7},{%8,%9},{%0,%1,%2,%3};\n"
        : "+f"(c[0]),"+f"(c[1]),"+f"(c[2]),"+f"(c[3])
        : "r"(a[0]),"r"(a[1]),"r"(a[2]),"r"(a[3]),"r"(b[0]),"r"(b[1]));
}

// ---------------------------------------------------------------------------
// LayerNorm: one block per token row of 1024
// ---------------------------------------------------------------------------
__global__ __launch_bounds__(256) void ln_kernel(
    const float* __restrict__ X, const float* __restrict__ g,
    const float* __restrict__ b, float* __restrict__ O)
{
    int t = blockIdx.x;
    int tid = threadIdx.x;
    const float4* x4 = (const float4*)(X + (size_t)t * Dz);
    float4 xv = x4[tid];
    float s  = xv.x + xv.y + xv.z + xv.w;
    float ss = xv.x*xv.x + xv.y*xv.y + xv.z*xv.z + xv.w*xv.w;
    #pragma unroll
    for (int off = 16; off; off >>= 1) {
        s  += __shfl_xor_sync(0xffffffffu, s,  off);
        ss += __shfl_xor_sync(0xffffffffu, ss, off);
    }
    __shared__ float sh_s[8], sh_ss[8];
    if ((tid & 31) == 0) { sh_s[tid >> 5] = s; sh_ss[tid >> 5] = ss; }
    __syncthreads();
    if (tid < 32) {
        float a = (tid < 8) ? sh_s[tid]  : 0.f;
        float c = (tid < 8) ? sh_ss[tid] : 0.f;
        #pragma unroll
        for (int off = 4; off; off >>= 1) {
            a += __shfl_xor_sync(0xffffffffu, a, off);
            c += __shfl_xor_sync(0xffffffffu, c, off);
        }
        if (tid == 0) { sh_s[0] = a; sh_ss[0] = c; }
    }
    __syncthreads();
    float mu  = sh_s[0]  * (1.f / Dz);
    float var = sh_ss[0] * (1.f / Dz) - mu * mu;
    float inv = rsqrtf(var + 1e-5f);
    float4 gv = ((const float4*)g)[tid];
    float4 bv = ((const float4*)b)[tid];
    float4 o;
    o.x = (xv.x - mu) * inv * gv.x + bv.x;
    o.y = (xv.y - mu) * inv * gv.y + bv.y;
    o.z = (xv.z - mu) * inv * gv.z + bv.z;
    o.w = (xv.w - mu) * inv * gv.w + bv.w;
    ((float4*)(O + (size_t)t * Dz))[tid] = o;
}

// ---------------------------------------------------------------------------
// Tensor-core tf32 GEMM: C[M,N] = act(A @ B + bias) (+resid), optional gather.
// BM=128, BN=128, BK=32, 256 threads, 8 warps (2 M x 4 N), warp tile 64x32.
// NMMA=3: split hi/lo tf32 (near-fp32 accuracy).
// smem: As[2][128][36], Bs[2][32][132]  (70656 B dynamic)
// ---------------------------------------------------------------------------
#define GEMM_SMEM 70656
template<int ACT, bool GATHER, bool RESID, int NMMA>
__global__ void __launch_bounds__(256) gemm_tc(
    const float* __restrict__ A, const float* __restrict__ B,
    const float* __restrict__ bias, float* __restrict__ C,
    int M, int N, int K,
    const float* __restrict__ resid,
    const int* __restrict__ elist, const int* __restrict__ cnt, int ashift)
{
    extern __shared__ float sm[];
    float* As = sm;                 // 2*128*36 = 9216 floats
    float* Bs = sm + 2*128*36;      // 2*32*132 = 8448 floats

    int e = blockIdx.z;
    const float* Bp = B + (size_t)e * K * N;
    const float* bp = bias + (size_t)e * N;
    int mcount = GATHER ? cnt[e] : M;
    int m0 = blockIdx.y * 128;
    if (m0 >= mcount) return;
    int n0 = blockIdx.x * 128;
    const int* lst = GATHER ? (elist + e * Tz) : (const int*)nullptr;

    int tid = threadIdx.x;
    int lane = tid & 31, wid = tid >> 5;
    int warpM = wid >> 2, warpN = wid & 3;

    // A staging: thread -> rows (tid>>3)+32i, cols (tid&7)*4 .. +3
    int aq = (tid & 7) * 4;
    const float* aptr[4];
    bool aval[4];
    uint32_t adst[4];
    #pragma unroll
    for (int i = 0; i < 4; i++) {
        int r = (tid >> 3) + 32 * i;
        int m = m0 + r;
        bool v = (m < mcount);
        size_t rowg;
        if (GATHER) rowg = v ? (size_t)(lst[m] >> ashift) : 0;
        else        rowg = v ? (size_t)m : 0;
        aptr[i] = A + rowg * (size_t)K + aq;
        aval[i] = v;
        adst[i] = s2u(&As[r * 36 + aq]);
    }
    // B staging: thread -> rows (tid>>5)+8i, cols (tid&31)*4 .. +3
    const float* bptr = Bp + (size_t)(tid >> 5) * N + n0 + (tid & 31) * 4;
    uint32_t bdst = s2u(&Bs[(tid >> 5) * 132 + (tid & 31) * 4]);
    const uint32_t abuf = 128*36*4, bbuf = 32*132*4;

    float acc[4][4][4];
    #pragma unroll
    for (int i=0;i<4;i++)
        #pragma unroll
        for (int j=0;j<4;j++)
            #pragma unroll
            for (int l=0;l<4;l++) acc[i][j][l] = 0.f;

    int KT = K / 32;
    // prologue: stage tile 0 -> buffer 0
    #pragma unroll
    for (int i=0;i<4;i++) cpa16(adst[i], aptr[i], aval[i]);
    #pragma unroll
    for (int i=0;i<4;i++) cpa16(bdst + i*(8*132*4), bptr + (size_t)(8*i)*N, true);
    cp_commit();

    for (int kt = 0; kt < KT; kt++) {
        cp_wait0();
        __syncthreads();
        if (kt + 1 < KT) {
            int buf = (kt+1)&1;
            int k0 = (kt+1)*32;
            #pragma unroll
            for (int i=0;i<4;i++) cpa16(adst[i] + buf*abuf, aptr[i] + k0, aval[i]);
            #pragma unroll
            for (int i=0;i<4;i++) cpa16(bdst + buf*bbuf + i*(8*132*4),
                                        bptr + (size_t)(k0 + 8*i)*N, true);
            cp_commit();
        }
        const float* Ab = As + (kt&1)*(128*36) + (warpM*64 + (lane>>2))*36 + (lane&3);
        const float* Bb = Bs + (kt&1)*(32*132) + (lane&3)*132 + warpN*32 + (lane>>2);
        #pragma unroll
        for (int ks = 0; ks < 4; ks++) {
            uint32_t ah[4][4], al[4][4];
            #pragma unroll
            for (int mt = 0; mt < 4; mt++) {
                float v0 = Ab[(mt*16  )*36 + ks*8    ];
                float v1 = Ab[(mt*16+8)*36 + ks*8    ];
                float v2 = Ab[(mt*16  )*36 + ks*8 + 4];
                float v3 = Ab[(mt*16+8)*36 + ks*8 + 4];
                ah[mt][0]=f2tf(v0); ah[mt][1]=f2tf(v1);
                ah[mt][2]=f2tf(v2); ah[mt][3]=f2tf(v3);
                if (NMMA==3){
                    al[mt][0]=f2tf(v0-__uint_as_float(ah[mt][0]));
                    al[mt][1]=f2tf(v1-__uint_as_float(ah[mt][1]));
                    al[mt][2]=f2tf(v2-__uint_as_float(ah[mt][2]));
                    al[mt][3]=f2tf(v3-__uint_as_float(ah[mt][3]));
                }
            }
            uint32_t bh[4][2], bl[4][2];
            #pragma unroll
            for (int nt = 0; nt < 4; nt++) {
                float w0 = Bb[(ks*8  )*132 + nt*8];
                float w1 = Bb[(ks*8+4)*132 + nt*8];
                bh[nt][0]=f2tf(w0); bh[nt][1]=f2tf(w1);
                if (NMMA==3){
                    bl[nt][0]=f2tf(w0-__uint_as_float(bh[nt][0]));
                    bl[nt][1]=f2tf(w1-__uint_as_float(bh[nt][1]));
                }
            }
            #pragma unroll
            for (int mt = 0; mt < 4; mt++)
                #pragma unroll
                for (int nt = 0; nt < 4; nt++) {
                    mma8(acc[mt][nt], ah[mt], bh[nt]);
                    if (NMMA==3){
                        mma8(acc[mt][nt], al[mt], bh[nt]);
                        mma8(acc[mt][nt], ah[mt], bl[nt]);
                    }
                }
        }
        __syncthreads();
    }

    // epilogue
    float2 bv[4];
    #pragma unroll
    for (int nt = 0; nt < 4; nt++)
        bv[nt] = *(const float2*)(bp + n0 + warpN*32 + (lane&3)*2 + nt*8);

    #pragma unroll
    for (int mt = 0; mt < 4; mt++) {
        #pragma unroll
        for (int hf = 0; hf < 2; hf++) {
            int r = m0 + warpM*64 + mt*16 + (lane>>2) + hf*8;
            if (r >= mcount) continue;
            size_t crow = GATHER ? (size_t)lst[r] : (size_t)r;
            float* Cr = C + crow*(size_t)N + n0 + warpN*32 + (lane&3)*2;
            const float* Rr = RESID ? (resid + crow*(size_t)N + n0 + warpN*32 + (lane&3)*2)
                                    : (const float*)nullptr;
            #pragma unroll
            for (int nt = 0; nt < 4; nt++) {
                float v0 = acc[mt][nt][hf*2+0] + bv[nt].x;
                float v1 = acc[mt][nt][hf*2+1] + bv[nt].y;
                if (ACT == 1) { v0 = fmaxf(v0, 0.f); v1 = fmaxf(v1, 0.f); }
                if (ACT == 2) {
                    v0 = 0.5f*v0*(1.f + erff(v0*0.70710678118654752f));
                    v1 = 0.5f*v1*(1.f + erff(v1*0.70710678118654752f));
                }
                if (RESID) { v0 += Rr[nt*8]; v1 += Rr[nt*8+1]; }
                float2 o; o.x = v0; o.y = v1;
                *(float2*)(Cr + nt*8) = o;
            }
        }
    }
}

// ---------------------------------------------------------------------------
// Attention scores: P[bh][q][k] = 0.125 * Q[q]·K[k].  K-dim = 64, single stage.
// grid (8, 8, 64). smem: Qs[128][68] + Ks[128][68] = 69632 B.
// ---------------------------------------------------------------------------
#define SC_SMEM 69632
__global__ void __launch_bounds__(256) scores_tc(
    const float* __restrict__ Q, const float* __restrict__ Kg, float* __restrict__ P)
{
    extern __shared__ float sm[];
    float* Qs = sm;             // [128][68]
    float* Ks = sm + 128*68;    // [128][68]
    int bh = blockIdx.z, b = bh >> 4, h = bh & 15, g = h >> 1;
    int m0 = blockIdx.y * 128, n0 = blockIdx.x * 128;
    const float* Qb = Q + (size_t)(b*Sz + m0) * 512 + g*64;
    const float* Kb = Kg + (size_t)(b*Sz + n0) * 1024 + h*64;
    int tid = threadIdx.x, lane = tid & 31, wid = tid >> 5;
    int warpM = wid >> 2, warpN = wid & 3;

    #pragma unroll
    for (int i = 0; i < 8; i++) {
        int idx = i*256 + tid;
        int row = idx >> 4, c4 = (idx & 15) * 4;
        float4 qv = *(const float4*)(Qb + (size_t)row*512 + c4);
        Qs[row*68+c4+0]=qv.x*0.125f; Qs[row*68+c4+1]=qv.y*0.125f;
        Qs[row*68+c4+2]=qv.z*0.125f; Qs[row*68+c4+3]=qv.w*0.125f;
        float4 kv = *(const float4*)(Kb + (size_t)row*1024 + c4);
        Ks[row*68+c4+0]=kv.x; Ks[row*68+c4+1]=kv.y;
        Ks[row*68+c4+2]=kv.z; Ks[row*68+c4+3]=kv.w;
    }
    __syncthreads();

    float acc[4][4][4];
    #pragma unroll
    for (int i=0;i<4;i++)
        #pragma unroll
        for (int j=0;j<4;j++)
            #pragma unroll
            for (int l=0;l<4;l++) acc[i][j][l] = 0.f;

    const float* Ab = Qs + (warpM*64 + (lane>>2))*68 + (lane&3);
    const float* Bb = Ks + (warpN*32 + (lane>>2))*68 + (lane&3);
    #pragma unroll
    for (int ks = 0; ks < 8; ks++) {
        uint32_t ah[4][4], bh2[4][2];
        #pragma unroll
        for (int mt = 0; mt < 4; mt++) {
            ah[mt][0] = f2tf(Ab[(mt*16  )*68 + ks*8    ]);
            ah[mt][1] = f2tf(Ab[(mt*16+8)*68 + ks*8    ]);
            ah[mt][2] = f2tf(Ab[(mt*16  )*68 + ks*8 + 4]);
            ah[mt][3] = f2tf(Ab[(mt*16+8)*68 + ks*8 + 4]);
        }
        #pragma unroll
        for (int nt = 0; nt < 4; nt++) {
            bh2[nt][0] = f2tf(Bb[(nt*8)*68 + ks*8    ]);
            bh2[nt][1] = f2tf(Bb[(nt*8)*68 + ks*8 + 4]);
        }
        #pragma unroll
        for (int mt = 0; mt < 4; mt++)
            #pragma unroll
            for (int nt = 0; nt < 4; nt++)
                mma8(acc[mt][nt], ah[mt], bh2[nt]);
    }

    float* Pb = P + (size_t)bh * Sz * Sz;
    #pragma unroll
    for (int mt = 0; mt < 4; mt++)
        #pragma unroll
        for (int hf = 0; hf < 2; hf++) {
            int r = m0 + warpM*64 + mt*16 + (lane>>2) + hf*8;
            float* row = Pb + (size_t)r*Sz + n0 + warpN*32 + (lane&3)*2;
            #pragma unroll
            for (int nt = 0; nt < 4; nt++) {
                float2 o; o.x = acc[mt][nt][hf*2]; o.y = acc[mt][nt][hf*2+1];
                *(float2*)(row + nt*8) = o;
            }
        }
}

// ---------------------------------------------------------------------------
// Row softmax in place over 1024 (exact fp32). grid = 65536 rows.
// ---------------------------------------------------------------------------
__global__ __launch_bounds__(256) void softmax_kernel(float* __restrict__ P)
{
    size_t row = blockIdx.x;
    float* p = P + row * 1024;
    int tid = threadIdx.x;
    float4 v = ((float4*)p)[tid];
    float m = fmaxf(fmaxf(v.x, v.y), fmaxf(v.z, v.w));
    #pragma unroll
    for (int off = 16; off; off >>= 1)
        m = fmaxf(m, __shfl_xor_sync(0xffffffffu, m, off));
    __shared__ float shm[8], shs[8];
    if ((tid & 31) == 0) shm[tid >> 5] = m;
    __syncthreads();
    if (tid < 32) {
        float a = (tid < 8) ? shm[tid] : -INFINITY;
        #pragma unroll
        for (int off = 4; off; off >>= 1)
            a = fmaxf(a, __shfl_xor_sync(0xffffffffu, a, off));
        if (tid == 0) shm[0] = a;
    }
    __syncthreads();
    m = shm[0];
    v.x = expf(v.x - m); v.y = expf(v.y - m);
    v.z = expf(v.z - m); v.w = expf(v.w - m);
    float s = v.x + v.y + v.z + v.w;
    #pragma unroll
    for (int off = 16; off; off >>= 1)
        s += __shfl_xor_sync(0xffffffffu, s, off);
    if ((tid & 31) == 0) shs[tid >> 5] = s;
    __syncthreads();
    if (tid < 32) {
        float a = (tid < 8) ? shs[tid] : 0.f;
        #pragma unroll
        for (int off = 4; off; off >>= 1)
            a += __shfl_xor_sync(0xffffffffu, a, off);
        if (tid == 0) shs[0] = a;
    }
    __syncthreads();
    float inv = 1.f / shs[0];
    v.x *= inv; v.y *= inv; v.z *= inv; v.w *= inv;
    ((float4*)p)[tid] = v;
}

// ---------------------------------------------------------------------------
// PV: O[bh][q][d] = P[bh] @ V_head.  BM=128, BN=64, BK=32.
// warp grid 2(M) x 4(N), warp tile 64x16. grid (1, 8, 64).
// smem: As[2][128][36] + Bs[2][32][68] = 54272 B.
// ---------------------------------------------------------------------------
#define PV_SMEM 54272
__global__ void __launch_bounds__(256) pv_tc(
    const float* __restrict__ P, const float* __restrict__ V, float* __restrict__ O)
{
    extern __shared__ float sm[];
    float* As = sm;                // 2*128*36
    float* Bs = sm + 2*128*36;     // 2*32*68
    int bh = blockIdx.z, b = bh >> 4, h = bh & 15;
    int m0 = blockIdx.y * 128;
    const float* Pb = P + (size_t)bh * Sz * Sz;
    const float* Vb = V + (size_t)(b*Sz) * Dz + h*64;

    int tid = threadIdx.x, lane = tid & 31, wid = tid >> 5;
    int warpM = wid >> 2, warpN = wid & 3;

    int aq = (tid & 7) * 4;
    const float* aptr[4];
    uint32_t adst[4];
    #pragma unroll
    for (int i = 0; i < 4; i++) {
        int r = (tid >> 3) + 32 * i;
        aptr[i] = Pb + (size_t)(m0 + r) * Sz + aq;
        adst[i] = s2u(&As[r * 36 + aq]);
    }
    const float* vptr = Vb + (size_t)(tid >> 4) * Dz + (tid & 15) * 4;
    uint32_t bdst = s2u(&Bs[(tid >> 4) * 68 + (tid & 15) * 4]);
    const uint32_t abuf = 128*36*4, bbuf = 32*68*4;

    float acc[4][2][4];
    #pragma unroll
    for (int i=0;i<4;i++)
        #pragma unroll
        for (int j=0;j<2;j++)
            #pragma unroll
            for (int l=0;l<4;l++) acc[i][j][l] = 0.f;

    const int KT = Sz / 32;
    #pragma unroll
    for (int i=0;i<4;i++) cpa16(adst[i], aptr[i], true);
    #pragma unroll
    for (int i=0;i<2;i++) cpa16(bdst + i*(16*68*4), vptr + (size_t)(16*i)*Dz, true);
    cp_commit();

    for (int kt = 0; kt < KT; kt++) {
        cp_wait0();
        __syncthreads();
        if (kt + 1 < KT) {
            int buf = (kt+1)&1;
            int k0 = (kt+1)*32;
            #pragma unroll
            for (int i=0;i<4;i++) cpa16(adst[i] + buf*abuf, aptr[i] + k0, true);
            #pragma unroll
            for (int i=0;i<2;i++) cpa16(bdst + buf*bbuf + i*(16*68*4),
                                        vptr + (size_t)(k0 + 16*i)*Dz, true);
            cp_commit();
        }
        const float* Ab = As + (kt&1)*(128*36) + (warpM*64 + (lane>>2))*36 + (lane&3);
        const float* Bb = Bs + (kt&1)*(32*68) + (lane&3)*68 + warpN*16 + (lane>>2);
        #pragma unroll
        for (int ks = 0; ks < 4; ks++) {
            uint32_t ah[4][4], bh2[2][2];
            #pragma unroll
            for (int mt = 0; mt < 4; mt++) {
                ah[mt][0] = f2tf(Ab[(mt*16  )*36 + ks*8    ]);
                ah[mt][1] = f2tf(Ab[(mt*16+8)*36 + ks*8    ]);
                ah[mt][2] = f2tf(Ab[(mt*16  )*36 + ks*8 + 4]);
                ah[mt][3] = f2tf(Ab[(mt*16+8)*36 + ks*8 + 4]);
            }
            #pragma unroll
            for (int nt = 0; nt < 2; nt++) {
                bh2[nt][0] = f2tf(Bb[(ks*8  )*68 + nt*8]);
                bh2[nt][1] = f2tf(Bb[(ks*8+4)*68 + nt*8]);
            }
            #pragma unroll
            for (int mt = 0; mt < 4; mt++)
                #pragma unroll
                for (int nt = 0; nt < 2; nt++)
                    mma8(acc[mt][nt], ah[mt], bh2[nt]);
        }
        __syncthreads();
    }

    #pragma unroll
    for (int mt = 0; mt < 4; mt++)
        #pragma unroll
        for (int hf = 0; hf < 2; hf++) {
            int r = m0 + warpM*64 + mt*16 + (lane>>2) + hf*8;
            float* Or = O + (size_t)(b*Sz + r) * Dz + h*64 + warpN*16 + (lane&3)*2;
            #pragma unroll
            for (int nt = 0; nt < 2; nt++) {
                float2 o; o.x = acc[mt][nt][hf*2]; o.y = acc[mt][nt][hf*2+1];
                *(float2*)(Or + nt*8) = o;
            }
        }
}

// ---------------------------------------------------------------------------
// Gate head + softmax + top-2 + renorm + routing. One warp per token.
// ---------------------------------------------------------------------------
__global__ __launch_bounds__(256) void gate_route_kernel(
    const float* __restrict__ GH, const float* __restrict__ gw2,
    const float* __restrict__ gb2,
    float* __restrict__ wout, int* __restrict__ cnt, int* __restrict__ elist)
{
    int warp = threadIdx.x >> 5;
    int lane = threadIdx.x & 31;
    int t = blockIdx.x * 8 + warp;
    if (t >= Tz) return;

    float logit[Ez];
    #pragma unroll
    for (int o = 0; o < Ez; o++) {
        float s = 0.f;
        for (int i = lane; i < GHz; i += 32)
            s += GH[(size_t)t * GHz + i] * gw2[(size_t)i * Ez + o];
        #pragma unroll
        for (int off = 16; off; off >>= 1)
            s += __shfl_xor_sync(0xffffffffu, s, off);
        logit[o] = s + gb2[o];
    }
    if (lane == 0) {
        float m = logit[0];
        #pragma unroll
        for (int o = 1; o < Ez; o++) m = fmaxf(m, logit[o]);
        float w[Ez], sum = 0.f;
        #pragma unroll
        for (int o = 0; o < Ez; o++) { w[o] = expf(logit[o] - m); sum += w[o]; }
        float invs = 1.f / sum;
        #pragma unroll
        for (int o = 0; o < Ez; o++) w[o] *= invs;
        int i0 = 0; float v0 = w[0];
        #pragma unroll
        for (int o = 1; o < Ez; o++) if (w[o] > v0) { v0 = w[o]; i0 = o; }
        int i1 = -1; float v1 = -1.f;
        #pragma unroll
        for (int o = 0; o < Ez; o++)
            if (o != i0 && w[o] > v1) { v1 = w[o]; i1 = o; }
        float e1 = expf(v1 - v0);
        float den = 1.f + e1;
        wout[2*t + 0] = 1.f / den;
        wout[2*t + 1] = e1 / den;
        int p0 = atomicAdd(&cnt[i0], 1);
        elist[i0 * Tz + p0] = 2*t + 0;
        int p1 = atomicAdd(&cnt[i1], 1);
        elist[i1 * Tz + p1] = 2*t + 1;
    }
}

__global__ void zero_counts_kernel(int* cnt)
{
    if (threadIdx.x < Ez) cnt[threadIdx.x] = 0;
}

// ---------------------------------------------------------------------------
// Final combine: out = x1 + w0*eo[2t] + w1*eo[2t+1]
// ---------------------------------------------------------------------------
__global__ __launch_bounds__(256) void combine_kernel(
    const float* __restrict__ x1, const float* __restrict__ eo,
    const float* __restrict__ w, float* __restrict__ out)
{
    int idx = blockIdx.x * 256 + threadIdx.x;
    int t = idx >> 8;
    int c = idx & 255;
    float w0 = w[2*t], w1 = w[2*t + 1];
    float4 a  = ((const float4*)x1)[idx];
    float4 e0 = ((const float4*)(eo + (size_t)(2*t)     * Dz))[c];
    float4 e1 = ((const float4*)(eo + (size_t)(2*t + 1) * Dz))[c];
    float4 r;
    r.x = a.x + w0 * e0.x + w1 * e1.x;
    r.y = a.y + w0 * e0.y + w1 * e1.y;
    r.z = a.z + w0 * e0.z + w1 * e1.z;
    r.w = a.w + w0 * e0.w + w1 * e1.w;
    ((float4*)out)[idx] = r;
}

// ---------------------------------------------------------------------------
// Host launch
// ---------------------------------------------------------------------------
extern "C" void kernel_launch(void* const* d_in, const int* in_sizes, int n_in,
                              void* d_out, int out_size)
{
    const float* x    = (const float*)d_in[0];
    const float* wq   = (const float*)d_in[1];
    const float* bq   = (const float*)d_in[2];
    const float* wk   = (const float*)d_in[3];
    const float* bk   = (const float*)d_in[4];
    const float* wv   = (const float*)d_in[5];
    const float* bv   = (const float*)d_in[6];
    const float* wo   = (const float*)d_in[7];
    const float* bo   = (const float*)d_in[8];
    const float* ln1g = (const float*)d_in[9];
    const float* ln1b = (const float*)d_in[10];
    const float* ln2g = (const float*)d_in[11];
    const float* ln2b = (const float*)d_in[12];
    const float* gw1  = (const float*)d_in[13];
    const float* gb1  = (const float*)d_in[14];
    const float* gw2  = (const float*)d_in[15];
    const float* gb2  = (const float*)d_in[16];
    const float* ew1  = (const float*)d_in[17];
    const float* eb1  = (const float*)d_in[18];
    const float* ew2  = (const float*)d_in[19];
    const float* eb2  = (const float*)d_in[20];
    float* out = (float*)d_out;

    float *h1, *q, *k, *v, *sc, *ao, *x1, *h2, *gh, *w, *hid, *eo;
    int *cnt, *elist;
    cudaGetSymbolAddress((void**)&h1,   g_h1);
    cudaGetSymbolAddress((void**)&q,    g_q);
    cudaGetSymbolAddress((void**)&k,    g_k);
    cudaGetSymbolAddress((void**)&v,    g_v);
    cudaGetSymbolAddress((void**)&sc,   g_sc);
    cudaGetSymbolAddress((void**)&ao,   g_ao);
    cudaGetSymbolAddress((void**)&x1,   g_x1);
    cudaGetSymbolAddress((void**)&h2,   g_h2);
    cudaGetSymbolAddress((void**)&gh,   g_gh);
    cudaGetSymbolAddress((void**)&w,    g_w);
    cudaGetSymbolAddress((void**)&hid,  g_hid);
    cudaGetSymbolAddress((void**)&eo,   g_eo);
    cudaGetSymbolAddress((void**)&cnt,  g_cnt);
    cudaGetSymbolAddress((void**)&elist,g_elist);

    cudaFuncSetAttribute(gemm_tc<0,false,false,1>, cudaFuncAttributeMaxDynamicSharedMemorySize, GEMM_SMEM);
    cudaFuncSetAttribute(gemm_tc<0,false,true,1>,  cudaFuncAttributeMaxDynamicSharedMemorySize, GEMM_SMEM);
    cudaFuncSetAttribute(gemm_tc<1,false,false,3>, cudaFuncAttributeMaxDynamicSharedMemorySize, GEMM_SMEM);
    cudaFuncSetAttribute(gemm_tc<2,true,false,1>,  cudaFuncAttributeMaxDynamicSharedMemorySize, GEMM_SMEM);
    cudaFuncSetAttribute(gemm_tc<0,true,false,1>,  cudaFuncAttributeMaxDynamicSharedMemorySize, GEMM_SMEM);
    cudaFuncSetAttribute(scores_tc, cudaFuncAttributeMaxDynamicSharedMemorySize, SC_SMEM);
    cudaFuncSetAttribute(pv_tc,     cudaFuncAttributeMaxDynamicSharedMemorySize, PV_SMEM);

    zero_counts_kernel<<<1, 32>>>(cnt);
    ln_kernel<<<Tz, 256>>>(x, ln1g, ln1b, h1);

    gemm_tc<0,false,false,1><<<dim3(4, 32, 1), 256, GEMM_SMEM>>>(
        h1, wq, bq, q, Tz, 512, Dz, nullptr, nullptr, nullptr, 0);
    gemm_tc<0,false,false,1><<<dim3(8, 32, 1), 256, GEMM_SMEM>>>(
        h1, wk, bk, k, Tz, Dz, Dz, nullptr, nullptr, nullptr, 0);
    gemm_tc<0,false,false,1><<<dim3(8, 32, 1), 256, GEMM_SMEM>>>(
        h1, wv, bv, v, Tz, Dz, Dz, nullptr, nullptr, nullptr, 0);

    scores_tc<<<dim3(8, 8, Bz*Hh), 256, SC_SMEM>>>(q, k, sc);
    softmax_kernel<<<Bz*Hh*Sz, 256>>>(sc);
    pv_tc<<<dim3(1, 8, Bz*Hh), 256, PV_SMEM>>>(sc, v, ao);

    gemm_tc<0,false,true,1><<<dim3(8, 32, 1), 256, GEMM_SMEM>>>(
        ao, wo, bo, x1, Tz, Dz, Dz, x, nullptr, nullptr, 0);

    ln_kernel<<<Tz, 256>>>(x1, ln2g, ln2b, h2);

    // gate layer 1 in split-tf32 (near-fp32) to protect top-2 selection
    gemm_tc<1,false,false,3><<<dim3(4, 32, 1), 256, GEMM_SMEM>>>(
        h2, gw1, gb1, gh, Tz, GHz, Dz, nullptr, nullptr, nullptr, 0);

    gate_route_kernel<<<Tz/8, 256>>>(gh, gw2, gb2, w, cnt, elist);

    gemm_tc<2,true,false,1><<<dim3(EDz/128, Tz/128, Ez), 256, GEMM_SMEM>>>(
        h2, ew1, eb1, hid, Tz, EDz, Dz, nullptr, elist, cnt, 1);
    gemm_tc<0,true,false,1><<<dim3(Dz/128, Tz/128, Ez), 256, GEMM_SMEM>>>(
        hid, ew2, eb2, eo, Tz, Dz, EDz, nullptr, elist, cnt, 0);

    combine_kernel<<<(Tz*Dz/4)/256, 256>>>(x1, eo, w, out);
}

// round 3
// speedup vs baseline: 4.5189x; 1.2077x over previous
#include <cuda_runtime.h>
#include <math.h>
#include <stdint.h>

// ---------------------------------------------------------------------------
// Problem constants
// ---------------------------------------------------------------------------
#define Bz   4
#define Sz   1024
#define Dz   1024
#define Hh   16
#define Gg   8
#define HDz  64
#define Ez   8
#define EDz  2048
#define GHz  512
#define Tz   (Bz*Sz)          // 4096 tokens

// ---------------------------------------------------------------------------
// Scratch (static device memory)
// ---------------------------------------------------------------------------
__device__ float g_h1 [Tz*Dz];
__device__ float g_q  [Tz*512];
__device__ float g_k  [Tz*Dz];
__device__ float g_v  [Tz*Dz];
__device__ float g_sc [(size_t)Bz*Hh*Sz*Sz];   // 256 MB scores/probs
__device__ float g_ao [Tz*Dz];
__device__ float g_x1 [Tz*Dz];
__device__ float g_h2 [Tz*Dz];
__device__ float g_gh [Tz*GHz];
__device__ float g_w  [Tz*2];
__device__ int   g_cnt[Ez];
__device__ int   g_elist[Ez*Tz];
__device__ float g_hid[(size_t)Tz*2*EDz];
__device__ float g_eo [(size_t)Tz*2*Dz];

// ---------------------------------------------------------------------------
// Helpers
// ---------------------------------------------------------------------------
__device__ __forceinline__ uint32_t s2u(const void* p){
    return (uint32_t)__cvta_generic_to_shared(p);
}
__device__ __forceinline__ void cpa16(uint32_t d, const void* s, bool v){
    asm volatile("cp.async.cg.shared.global [%0], [%1], 16, %2;\n"
                 :: "r"(d), "l"(s), "r"(v ? 16 : 0));
}
__device__ __forceinline__ void cp_commit(){ asm volatile("cp.async.commit_group;\n"); }
__device__ __forceinline__ void cp_wait0(){ asm volatile("cp.async.wait_group 0;\n"); }
__device__ __forceinline__ uint32_t f2tf(float x){
    uint32_t r; asm("cvt.rna.tf32.f32 %0, %1;" : "=r"(r) : "f"(x)); return r;
}
__device__ __forceinline__ void mma8(float* c, const uint32_t* a, const uint32_t* b){
    asm volatile("mma.sync.aligned.m16n8k8.row.col.f32.tf32.tf32.f32 "
        "{%0,%1,%2,%3},{%4,%5,%6,%7},{%8,%9},{%0,%1,%2,%3};\n"
        : "+f"(c[0]),"+f"(c[1]),"+f"(c[2]),"+f"(c[3])
        : "r"(a[0]),"r"(a[1]),"r"(a[2]),"r"(a[3]),"r"(b[0]),"r"(b[1]));
}
__device__ __forceinline__ void ldm4(uint32_t* r, uint32_t addr){
    asm volatile("ldmatrix.sync.aligned.m8n8.x4.shared.b16 {%0,%1,%2,%3}, [%4];"
        : "=r"(r[0]),"=r"(r[1]),"=r"(r[2]),"=r"(r[3]) : "r"(addr));
}

// ---------------------------------------------------------------------------
// LayerNorm: one block per token row of 1024
// ---------------------------------------------------------------------------
__global__ __launch_bounds__(256) void ln_kernel(
    const float* __restrict__ X, const float* __restrict__ g,
    const float* __restrict__ b, float* __restrict__ O)
{
    int t = blockIdx.x;
    int tid = threadIdx.x;
    const float4* x4 = (const float4*)(X + (size_t)t * Dz);
    float4 xv = x4[tid];
    float s  = xv.x + xv.y + xv.z + xv.w;
    float ss = xv.x*xv.x + xv.y*xv.y + xv.z*xv.z + xv.w*xv.w;
    #pragma unroll
    for (int off = 16; off; off >>= 1) {
        s  += __shfl_xor_sync(0xffffffffu, s,  off);
        ss += __shfl_xor_sync(0xffffffffu, ss, off);
    }
    __shared__ float sh_s[8], sh_ss[8];
    if ((tid & 31) == 0) { sh_s[tid >> 5] = s; sh_ss[tid >> 5] = ss; }
    __syncthreads();
    if (tid < 32) {
        float a = (tid < 8) ? sh_s[tid]  : 0.f;
        float c = (tid < 8) ? sh_ss[tid] : 0.f;
        #pragma unroll
        for (int off = 4; off; off >>= 1) {
            a += __shfl_xor_sync(0xffffffffu, a, off);
            c += __shfl_xor_sync(0xffffffffu, c, off);
        }
        if (tid == 0) { sh_s[0] = a; sh_ss[0] = c; }
    }
    __syncthreads();
    float mu  = sh_s[0]  * (1.f / Dz);
    float var = sh_ss[0] * (1.f / Dz) - mu * mu;
    float inv = rsqrtf(var + 1e-5f);
    float4 gv = ((const float4*)g)[tid];
    float4 bv = ((const float4*)b)[tid];
    float4 o;
    o.x = (xv.x - mu) * inv * gv.x + bv.x;
    o.y = (xv.y - mu) * inv * gv.y + bv.y;
    o.z = (xv.z - mu) * inv * gv.z + bv.z;
    o.w = (xv.w - mu) * inv * gv.w + bv.w;
    ((float4*)(O + (size_t)t * Dz))[tid] = o;
}

// ---------------------------------------------------------------------------
// Tensor-core tf32 GEMM: C[M,N] = act(A @ B + bias) (+resid), optional gather.
// BM=128, BN=128, BK=32, 256 threads, 8 warps (2 M x 4 N), warp tile 64x32.
// A fragments via ldmatrix.x4 on raw fp32 (truncated tf32);
// NMMA=3: split hi/lo tf32 with rna rounding (near-fp32, gate path).
// smem: As[2][128][36], Bs[2][32][136]  -> 71680 B dynamic.
// ---------------------------------------------------------------------------
#define GEMM_SMEM (2*128*36*4 + 2*32*136*4)
template<int ACT, bool GATHER, bool RESID, int NMMA>
__global__ void __launch_bounds__(256,2) gemm_tc(
    const float* __restrict__ A, const float* __restrict__ B,
    const float* __restrict__ bias, float* __restrict__ C,
    int M, int N, int K,
    const float* __restrict__ resid,
    const int* __restrict__ elist, const int* __restrict__ cnt, int ashift)
{
    extern __shared__ float sm[];
    float* As = sm;                 // [2][128][36]
    float* Bs = sm + 2*128*36;      // [2][32][136]

    int e = blockIdx.z;
    const float* Bp = B + (size_t)e * K * N;
    const float* bp = bias + (size_t)e * N;
    int mcount = GATHER ? cnt[e] : M;
    int m0 = blockIdx.y * 128;
    if (m0 >= mcount) return;
    int n0 = blockIdx.x * 128;
    const int* lst = GATHER ? (elist + e * Tz) : (const int*)nullptr;

    int tid = threadIdx.x;
    int lane = tid & 31, wid = tid >> 5;
    int warpM = wid >> 2, warpN = wid & 3;

    // A staging: thread -> rows (tid>>3)+32i, cols (tid&7)*4
    int aq = (tid & 7) * 4;
    const float* aptr[4];
    bool aval[4];
    uint32_t adst[4];
    #pragma unroll
    for (int i = 0; i < 4; i++) {
        int r = (tid >> 3) + 32 * i;
        int m = m0 + r;
        bool v = (m < mcount);
        size_t rowg;
        if (GATHER) rowg = v ? (size_t)(lst[m] >> ashift) : 0;
        else        rowg = v ? (size_t)m : 0;
        aptr[i] = A + rowg * (size_t)K + aq;
        aval[i] = v;
        adst[i] = s2u(&As[r * 36 + aq]);
    }
    // B staging: thread -> rows (tid>>5)+8i, cols (tid&31)*4
    const float* bptr = Bp + (size_t)(tid >> 5) * N + n0 + (tid & 31) * 4;
    uint32_t bdst = s2u(&Bs[(tid >> 5) * 136 + (tid & 31) * 4]);
    const uint32_t abuf = 128*36*4, bbuf = 32*136*4;

    // ldmatrix lane mapping for A (4x m8n8.b16 blocks == 16x8 tf32 tile)
    uint32_t a_lrow = lane & 15;
    uint32_t a_lcol = (lane & 16) ? 4 : 0;
    uint32_t as_u = s2u(As);

    float acc[4][4][4];
    #pragma unroll
    for (int i=0;i<4;i++)
        #pragma unroll
        for (int j=0;j<4;j++)
            #pragma unroll
            for (int l=0;l<4;l++) acc[i][j][l] = 0.f;

    int KT = K / 32;
    #pragma unroll
    for (int i=0;i<4;i++) cpa16(adst[i], aptr[i], aval[i]);
    #pragma unroll
    for (int i=0;i<4;i++) cpa16(bdst + i*(8*136*4), bptr + (size_t)(8*i)*N, true);
    cp_commit();

    for (int kt = 0; kt < KT; kt++) {
        cp_wait0();
        __syncthreads();
        if (kt + 1 < KT) {
            int buf = (kt+1)&1;
            int k0 = (kt+1)*32;
            #pragma unroll
            for (int i=0;i<4;i++) cpa16(adst[i] + buf*abuf, aptr[i] + k0, aval[i]);
            #pragma unroll
            for (int i=0;i<4;i++) cpa16(bdst + buf*bbuf + i*(8*136*4),
                                        bptr + (size_t)(k0 + 8*i)*N, true);
            cp_commit();
        }
        uint32_t abase = as_u + ((kt&1)*(128*36) + (warpM*64 + a_lrow)*36 + a_lcol)*4;
        const float* Bb = Bs + (kt&1)*(32*136) + (lane&3)*136 + warpN*32 + (lane>>2);
        #pragma unroll
        for (int ks = 0; ks < 4; ks++) {
            uint32_t ah[4][4];
            #pragma unroll
            for (int mt = 0; mt < 4; mt++)
                ldm4(ah[mt], abase + (mt*16*36 + ks*8)*4);
            uint32_t bh[4][2];
            #pragma unroll
            for (int nt = 0; nt < 4; nt++) {
                bh[nt][0] = __float_as_uint(Bb[(ks*8  )*136 + nt*8]);
                bh[nt][1] = __float_as_uint(Bb[(ks*8+4)*136 + nt*8]);
            }
            if (NMMA == 3) {
                uint32_t al[4][4], bl[4][2];
                #pragma unroll
                for (int mt = 0; mt < 4; mt++)
                    #pragma unroll
                    for (int j = 0; j < 4; j++) {
                        float v = __uint_as_float(ah[mt][j]);
                        uint32_t hi = f2tf(v);
                        al[mt][j] = f2tf(v - __uint_as_float(hi));
                        ah[mt][j] = hi;
                    }
                #pragma unroll
                for (int nt = 0; nt < 4; nt++)
                    #pragma unroll
                    for (int j = 0; j < 2; j++) {
                        float v = __uint_as_float(bh[nt][j]);
                        uint32_t hi = f2tf(v);
                        bl[nt][j] = f2tf(v - __uint_as_float(hi));
                        bh[nt][j] = hi;
                    }
                #pragma unroll
                for (int mt = 0; mt < 4; mt++)
                    #pragma unroll
                    for (int nt = 0; nt < 4; nt++) {
                        mma8(acc[mt][nt], ah[mt], bh[nt]);
                        mma8(acc[mt][nt], al[mt], bh[nt]);
                        mma8(acc[mt][nt], ah[mt], bl[nt]);
                    }
            } else {
                #pragma unroll
                for (int mt = 0; mt < 4; mt++)
                    #pragma unroll
                    for (int nt = 0; nt < 4; nt++)
                        mma8(acc[mt][nt], ah[mt], bh[nt]);
            }
        }
        __syncthreads();
    }

    // epilogue
    float2 bv[4];
    #pragma unroll
    for (int nt = 0; nt < 4; nt++)
        bv[nt] = *(const float2*)(bp + n0 + warpN*32 + (lane&3)*2 + nt*8);

    #pragma unroll
    for (int mt = 0; mt < 4; mt++) {
        #pragma unroll
        for (int hf = 0; hf < 2; hf++) {
            int r = m0 + warpM*64 + mt*16 + (lane>>2) + hf*8;
            if (r >= mcount) continue;
            size_t crow = GATHER ? (size_t)lst[r] : (size_t)r;
            float* Cr = C + crow*(size_t)N + n0 + warpN*32 + (lane&3)*2;
            const float* Rr = RESID ? (resid + crow*(size_t)N + n0 + warpN*32 + (lane&3)*2)
                                    : (const float*)nullptr;
            #pragma unroll
            for (int nt = 0; nt < 4; nt++) {
                float v0 = acc[mt][nt][hf*2+0] + bv[nt].x;
                float v1 = acc[mt][nt][hf*2+1] + bv[nt].y;
                if (ACT == 1) { v0 = fmaxf(v0, 0.f); v1 = fmaxf(v1, 0.f); }
                if (ACT == 2) {
                    v0 = 0.5f*v0*(1.f + erff(v0*0.70710678118654752f));
                    v1 = 0.5f*v1*(1.f + erff(v1*0.70710678118654752f));
                }
                if (RESID) { v0 += Rr[nt*8]; v1 += Rr[nt*8+1]; }
                float2 o; o.x = v0; o.y = v1;
                *(float2*)(Cr + nt*8) = o;
            }
        }
    }
}

// ---------------------------------------------------------------------------
// Attention scores: P[bh][q][k] = 0.125 * Q[q]·K[k]. Fully ldmatrix (A and B:
// Ks is [kv][hd] = [n][k], k-contiguous). grid (8, 8, 64).
// smem: Qs[128][68] + Ks[128][68] = 69632 B.
// ---------------------------------------------------------------------------
#define SC_SMEM 69632
__global__ void __launch_bounds__(256) scores_tc(
    const float* __restrict__ Q, const float* __restrict__ Kg, float* __restrict__ P)
{
    extern __shared__ float sm[];
    float* Qs = sm;             // [128][68]
    float* Ks = sm + 128*68;    // [128][68]
    int bh = blockIdx.z, b = bh >> 4, h = bh & 15, g = h >> 1;
    int m0 = blockIdx.y * 128, n0 = blockIdx.x * 128;
    const float* Qb = Q + (size_t)(b*Sz + m0) * 512 + g*64;
    const float* Kb = Kg + (size_t)(b*Sz + n0) * 1024 + h*64;
    int tid = threadIdx.x, lane = tid & 31, wid = tid >> 5;
    int warpM = wid >> 2, warpN = wid & 3;

    #pragma unroll
    for (int i = 0; i < 8; i++) {
        int idx = i*256 + tid;
        int row = idx >> 4, c4 = (idx & 15) * 4;
        float4 qv = *(const float4*)(Qb + (size_t)row*512 + c4);
        qv.x *= 0.125f; qv.y *= 0.125f; qv.z *= 0.125f; qv.w *= 0.125f;
        *(float4*)&Qs[row*68+c4] = qv;
        float4 kv = *(const float4*)(Kb + (size_t)row*1024 + c4);
        *(float4*)&Ks[row*68+c4] = kv;
    }
    __syncthreads();

    float acc[4][4][4];
    #pragma unroll
    for (int i=0;i<4;i++)
        #pragma unroll
        for (int j=0;j<4;j++)
            #pragma unroll
            for (int l=0;l<4;l++) acc[i][j][l] = 0.f;

    uint32_t a_lrow = lane & 15;
    uint32_t a_lcol = (lane & 16) ? 4 : 0;
    uint32_t b_lrow = ((lane >> 4) << 3) + (lane & 7);
    uint32_t b_lcol = (lane & 8) ? 4 : 0;
    uint32_t qs_u = s2u(Qs), ks_u = s2u(Ks);
    uint32_t abase = qs_u + ((warpM*64 + a_lrow)*68 + a_lcol)*4;
    uint32_t bbase = ks_u + ((warpN*32 + b_lrow)*68 + b_lcol)*4;

    #pragma unroll
    for (int ks = 0; ks < 8; ks++) {
        uint32_t ah[4][4], bh2[4][2];
        #pragma unroll
        for (int mt = 0; mt < 4; mt++)
            ldm4(ah[mt], abase + (mt*16*68 + ks*8)*4);
        #pragma unroll
        for (int np = 0; np < 2; np++) {
            uint32_t r[4];
            ldm4(r, bbase + (np*16*68 + ks*8)*4);
            bh2[2*np  ][0] = r[0]; bh2[2*np  ][1] = r[1];
            bh2[2*np+1][0] = r[2]; bh2[2*np+1][1] = r[3];
        }
        #pragma unroll
        for (int mt = 0; mt < 4; mt++)
            #pragma unroll
            for (int nt = 0; nt < 4; nt++)
                mma8(acc[mt][nt], ah[mt], bh2[nt]);
    }

    float* Pb = P + (size_t)bh * Sz * Sz;
    #pragma unroll
    for (int mt = 0; mt < 4; mt++)
        #pragma unroll
        for (int hf = 0; hf < 2; hf++) {
            int r = m0 + warpM*64 + mt*16 + (lane>>2) + hf*8;
            float* row = Pb + (size_t)r*Sz + n0 + warpN*32 + (lane&3)*2;
            #pragma unroll
            for (int nt = 0; nt < 4; nt++) {
                float2 o; o.x = acc[mt][nt][hf*2]; o.y = acc[mt][nt][hf*2+1];
                *(float2*)(row + nt*8) = o;
            }
        }
}

// ---------------------------------------------------------------------------
// Row softmax in place over 1024 (exact fp32). grid = 65536 rows.
// ---------------------------------------------------------------------------
__global__ __launch_bounds__(256) void softmax_kernel(float* __restrict__ P)
{
    size_t row = blockIdx.x;
    float* p = P + row * 1024;
    int tid = threadIdx.x;
    float4 v = ((float4*)p)[tid];
    float m = fmaxf(fmaxf(v.x, v.y), fmaxf(v.z, v.w));
    #pragma unroll
    for (int off = 16; off; off >>= 1)
        m = fmaxf(m, __shfl_xor_sync(0xffffffffu, m, off));
    __shared__ float shm[8], shs[8];
    if ((tid & 31) == 0) shm[tid >> 5] = m;
    __syncthreads();
    if (tid < 32) {
        float a = (tid < 8) ? shm[tid] : -INFINITY;
        #pragma unroll
        for (int off = 4; off; off >>= 1)
            a = fmaxf(a, __shfl_xor_sync(0xffffffffu, a, off));
        if (tid == 0) shm[0] = a;
    }
    __syncthreads();
    m = shm[0];
    v.x = expf(v.x - m); v.y = expf(v.y - m);
    v.z = expf(v.z - m); v.w = expf(v.w - m);
    float s = v.x + v.y + v.z + v.w;
    #pragma unroll
    for (int off = 16; off; off >>= 1)
        s += __shfl_xor_sync(0xffffffffu, s, off);
    if ((tid & 31) == 0) shs[tid >> 5] = s;
    __syncthreads();
    if (tid < 32) {
        float a = (tid < 8) ? shs[tid] : 0.f;
        #pragma unroll
        for (int off = 4; off; off >>= 1)
            a += __shfl_xor_sync(0xffffffffu, a, off);
        if (tid == 0) shs[0] = a;
    }
    __syncthreads();
    float inv = 1.f / shs[0];
    v.x *= inv; v.y *= inv; v.z *= inv; v.w *= inv;
    ((float4*)p)[tid] = v;
}

// ---------------------------------------------------------------------------
// PV: O[bh][q][d] = P[bh] @ V_head.  BM=128, BN=64, BK=32.
// A via ldmatrix; warp grid 2(M) x 4(N), warp tile 64x16. grid (1, 8, 64).
// smem: As[2][128][36] + Vs[2][32][72] = 55296 B.
// ---------------------------------------------------------------------------
#define PV_SMEM (2*128*36*4 + 2*32*72*4)
__global__ void __launch_bounds__(256,2) pv_tc(
    const float* __restrict__ P, const float* __restrict__ V, float* __restrict__ O)
{
    extern __shared__ float sm[];
    float* As = sm;                // [2][128][36]
    float* Vs = sm + 2*128*36;     // [2][32][72]
    int bh = blockIdx.z, b = bh >> 4, h = bh & 15;
    int m0 = blockIdx.y * 128;
    const float* Pb = P + (size_t)bh * Sz * Sz;
    const float* Vb = V + (size_t)(b*Sz) * Dz + h*64;

    int tid = threadIdx.x, lane = tid & 31, wid = tid >> 5;
    int warpM = wid >> 2, warpN = wid & 3;

    int aq = (tid & 7) * 4;
    const float* aptr[4];
    uint32_t adst[4];
    #pragma unroll
    for (int i = 0; i < 4; i++) {
        int r = (tid >> 3) + 32 * i;
        aptr[i] = Pb + (size_t)(m0 + r) * Sz + aq;
        adst[i] = s2u(&As[r * 36 + aq]);
    }
    const float* vptr = Vb + (size_t)(tid >> 4) * Dz + (tid & 15) * 4;
    uint32_t bdst = s2u(&Vs[(tid >> 4) * 72 + (tid & 15) * 4]);
    const uint32_t abuf = 128*36*4, bbuf = 32*72*4;

    uint32_t a_lrow = lane & 15;
    uint32_t a_lcol = (lane & 16) ? 4 : 0;
    uint32_t as_u = s2u(As);

    float acc[4][2][4];
    #pragma unroll
    for (int i=0;i<4;i++)
        #pragma unroll
        for (int j=0;j<2;j++)
            #pragma unroll
            for (int l=0;l<4;l++) acc[i][j][l] = 0.f;

    const int KT = Sz / 32;
    #pragma unroll
    for (int i=0;i<4;i++) cpa16(adst[i], aptr[i], true);
    #pragma unroll
    for (int i=0;i<2;i++) cpa16(bdst + i*(16*72*4), vptr + (size_t)(16*i)*Dz, true);
    cp_commit();

    for (int kt = 0; kt < KT; kt++) {
        cp_wait0();
        __syncthreads();
        if (kt + 1 < KT) {
            int buf = (kt+1)&1;
            int k0 = (kt+1)*32;
            #pragma unroll
            for (int i=0;i<4;i++) cpa16(adst[i] + buf*abuf, aptr[i] + k0, true);
            #pragma unroll
            for (int i=0;i<2;i++) cpa16(bdst + buf*bbuf + i*(16*72*4),
                                        vptr + (size_t)(k0 + 16*i)*Dz, true);
            cp_commit();
        }
        uint32_t abase = as_u + ((kt&1)*(128*36) + (warpM*64 + a_lrow)*36 + a_lcol)*4;
        const float* Bb = Vs + (kt&1)*(32*72) + (lane&3)*72 + warpN*16 + (lane>>2);
        #pragma unroll
        for (int ks = 0; ks < 4; ks++) {
            uint32_t ah[4][4], bh2[2][2];
            #pragma unroll
            for (int mt = 0; mt < 4; mt++)
                ldm4(ah[mt], abase + (mt*16*36 + ks*8)*4);
            #pragma unroll
            for (int nt = 0; nt < 2; nt++) {
                bh2[nt][0] = __float_as_uint(Bb[(ks*8  )*72 + nt*8]);
                bh2[nt][1] = __float_as_uint(Bb[(ks*8+4)*72 + nt*8]);
            }
            #pragma unroll
            for (int mt = 0; mt < 4; mt++)
                #pragma unroll
                for (int nt = 0; nt < 2; nt++)
                    mma8(acc[mt][nt], ah[mt], bh2[nt]);
        }
        __syncthreads();
    }

    #pragma unroll
    for (int mt = 0; mt < 4; mt++)
        #pragma unroll
        for (int hf = 0; hf < 2; hf++) {
            int r = m0 + warpM*64 + mt*16 + (lane>>2) + hf*8;
            float* Or = O + (size_t)(b*Sz + r) * Dz + h*64 + warpN*16 + (lane&3)*2;
            #pragma unroll
            for (int nt = 0; nt < 2; nt++) {
                float2 o; o.x = acc[mt][nt][hf*2]; o.y = acc[mt][nt][hf*2+1];
                *(float2*)(Or + nt*8) = o;
            }
        }
}

// ---------------------------------------------------------------------------
// Gate head + softmax + top-2 + renorm + routing. One warp per token.
// ---------------------------------------------------------------------------
__global__ __launch_bounds__(256) void gate_route_kernel(
    const float* __restrict__ GH, const float* __restrict__ gw2,
    const float* __restrict__ gb2,
    float* __restrict__ wout, int* __restrict__ cnt, int* __restrict__ elist)
{
    int warp = threadIdx.x >> 5;
    int lane = threadIdx.x & 31;
    int t = blockIdx.x * 8 + warp;
    if (t >= Tz) return;

    float logit[Ez];
    #pragma unroll
    for (int o = 0; o < Ez; o++) {
        float s = 0.f;
        for (int i = lane; i < GHz; i += 32)
            s += GH[(size_t)t * GHz + i] * gw2[(size_t)i * Ez + o];
        #pragma unroll
        for (int off = 16; off; off >>= 1)
            s += __shfl_xor_sync(0xffffffffu, s, off);
        logit[o] = s + gb2[o];
    }
    if (lane == 0) {
        float m = logit[0];
        #pragma unroll
        for (int o = 1; o < Ez; o++) m = fmaxf(m, logit[o]);
        float w[Ez], sum = 0.f;
        #pragma unroll
        for (int o = 0; o < Ez; o++) { w[o] = expf(logit[o] - m); sum += w[o]; }
        float invs = 1.f / sum;
        #pragma unroll
        for (int o = 0; o < Ez; o++) w[o] *= invs;
        int i0 = 0; float v0 = w[0];
        #pragma unroll
        for (int o = 1; o < Ez; o++) if (w[o] > v0) { v0 = w[o]; i0 = o; }
        int i1 = -1; float v1 = -1.f;
        #pragma unroll
        for (int o = 0; o < Ez; o++)
            if (o != i0 && w[o] > v1) { v1 = w[o]; i1 = o; }
        float e1 = expf(v1 - v0);
        float den = 1.f + e1;
        wout[2*t + 0] = 1.f / den;
        wout[2*t + 1] = e1 / den;
        int p0 = atomicAdd(&cnt[i0], 1);
        elist[i0 * Tz + p0] = 2*t + 0;
        int p1 = atomicAdd(&cnt[i1], 1);
        elist[i1 * Tz + p1] = 2*t + 1;
    }
}

__global__ void zero_counts_kernel(int* cnt)
{
    if (threadIdx.x < Ez) cnt[threadIdx.x] = 0;
}

// ---------------------------------------------------------------------------
// Final combine: out = x1 + w0*eo[2t] + w1*eo[2t+1]
// ---------------------------------------------------------------------------
__global__ __launch_bounds__(256) void combine_kernel(
    const float* __restrict__ x1, const float* __restrict__ eo,
    const float* __restrict__ w, float* __restrict__ out)
{
    int idx = blockIdx.x * 256 + threadIdx.x;
    int t = idx >> 8;
    int c = idx & 255;
    float w0 = w[2*t], w1 = w[2*t + 1];
    float4 a  = ((const float4*)x1)[idx];
    float4 e0 = ((const float4*)(eo + (size_t)(2*t)     * Dz))[c];
    float4 e1 = ((const float4*)(eo + (size_t)(2*t + 1) * Dz))[c];
    float4 r;
    r.x = a.x + w0 * e0.x + w1 * e1.x;
    r.y = a.y + w0 * e0.y + w1 * e1.y;
    r.z = a.z + w0 * e0.z + w1 * e1.z;
    r.w = a.w + w0 * e0.w + w1 * e1.w;
    ((float4*)out)[idx] = r;
}

// ---------------------------------------------------------------------------
// Host launch
// ---------------------------------------------------------------------------
extern "C" void kernel_launch(void* const* d_in, const int* in_sizes, int n_in,
                              void* d_out, int out_size)
{
    const float* x    = (const float*)d_in[0];
    const float* wq   = (const float*)d_in[1];
    const float* bq   = (const float*)d_in[2];
    const float* wk   = (const float*)d_in[3];
    const float* bk   = (const float*)d_in[4];
    const float* wv   = (const float*)d_in[5];
    const float* bv   = (const float*)d_in[6];
    const float* wo   = (const float*)d_in[7];
    const float* bo   = (const float*)d_in[8];
    const float* ln1g = (const float*)d_in[9];
    const float* ln1b = (const float*)d_in[10];
    const float* ln2g = (const float*)d_in[11];
    const float* ln2b = (const float*)d_in[12];
    const float* gw1  = (const float*)d_in[13];
    const float* gb1  = (const float*)d_in[14];
    const float* gw2  = (const float*)d_in[15];
    const float* gb2  = (const float*)d_in[16];
    const float* ew1  = (const float*)d_in[17];
    const float* eb1  = (const float*)d_in[18];
    const float* ew2  = (const float*)d_in[19];
    const float* eb2  = (const float*)d_in[20];
    float* out = (float*)d_out;

    float *h1, *q, *k, *v, *sc, *ao, *x1, *h2, *gh, *w, *hid, *eo;
    int *cnt, *elist;
    cudaGetSymbolAddress((void**)&h1,   g_h1);
    cudaGetSymbolAddress((void**)&q,    g_q);
    cudaGetSymbolAddress((void**)&k,    g_k);
    cudaGetSymbolAddress((void**)&v,    g_v);
    cudaGetSymbolAddress((void**)&sc,   g_sc);
    cudaGetSymbolAddress((void**)&ao,   g_ao);
    cudaGetSymbolAddress((void**)&x1,   g_x1);
    cudaGetSymbolAddress((void**)&h2,   g_h2);
    cudaGetSymbolAddress((void**)&gh,   g_gh);
    cudaGetSymbolAddress((void**)&w,    g_w);
    cudaGetSymbolAddress((void**)&hid,  g_hid);
    cudaGetSymbolAddress((void**)&eo,   g_eo);
    cudaGetSymbolAddress((void**)&cnt,  g_cnt);
    cudaGetSymbolAddress((void**)&elist,g_elist);

    cudaFuncSetAttribute(gemm_tc<0,false,false,1>, cudaFuncAttributeMaxDynamicSharedMemorySize, GEMM_SMEM);
    cudaFuncSetAttribute(gemm_tc<0,false,true,1>,  cudaFuncAttributeMaxDynamicSharedMemorySize, GEMM_SMEM);
    cudaFuncSetAttribute(gemm_tc<1,false,false,3>, cudaFuncAttributeMaxDynamicSharedMemorySize, GEMM_SMEM);
    cudaFuncSetAttribute(gemm_tc<2,true,false,1>,  cudaFuncAttributeMaxDynamicSharedMemorySize, GEMM_SMEM);
    cudaFuncSetAttribute(gemm_tc<0,true,false,1>,  cudaFuncAttributeMaxDynamicSharedMemorySize, GEMM_SMEM);
    cudaFuncSetAttribute(scores_tc, cudaFuncAttributeMaxDynamicSharedMemorySize, SC_SMEM);
    cudaFuncSetAttribute(pv_tc,     cudaFuncAttributeMaxDynamicSharedMemorySize, PV_SMEM);

    zero_counts_kernel<<<1, 32>>>(cnt);
    ln_kernel<<<Tz, 256>>>(x, ln1g, ln1b, h1);

    gemm_tc<0,false,false,1><<<dim3(4, 32, 1), 256, GEMM_SMEM>>>(
        h1, wq, bq, q, Tz, 512, Dz, nullptr, nullptr, nullptr, 0);
    gemm_tc<0,false,false,1><<<dim3(8, 32, 1), 256, GEMM_SMEM>>>(
        h1, wk, bk, k, Tz, Dz, Dz, nullptr, nullptr, nullptr, 0);
    gemm_tc<0,false,false,1><<<dim3(8, 32, 1), 256, GEMM_SMEM>>>(
        h1, wv, bv, v, Tz, Dz, Dz, nullptr, nullptr, nullptr, 0);

    scores_tc<<<dim3(8, 8, Bz*Hh), 256, SC_SMEM>>>(q, k, sc);
    softmax_kernel<<<Bz*Hh*Sz, 256>>>(sc);
    pv_tc<<<dim3(1, 8, Bz*Hh), 256, PV_SMEM>>>(sc, v, ao);

    gemm_tc<0,false,true,1><<<dim3(8, 32, 1), 256, GEMM_SMEM>>>(
        ao, wo, bo, x1, Tz, Dz, Dz, x, nullptr, nullptr, 0);

    ln_kernel<<<Tz, 256>>>(x1, ln2g, ln2b, h2);

    // gate layer 1 in split-tf32 (rna, near-fp32) to protect top-2 selection
    gemm_tc<1,false,false,3><<<dim3(4, 32, 1), 256, GEMM_SMEM>>>(
        h2, gw1, gb1, gh, Tz, GHz, Dz, nullptr, nullptr, nullptr, 0);

    gate_route_kernel<<<Tz/8, 256>>>(gh, gw2, gb2, w, cnt, elist);

    gemm_tc<2,true,false,1><<<dim3(EDz/128, Tz/128, Ez), 256, GEMM_SMEM>>>(
        h2, ew1, eb1, hid, Tz, EDz, Dz, nullptr, elist, cnt, 1);
    gemm_tc<0,true,false,1><<<dim3(Dz/128, Tz/128, Ez), 256, GEMM_SMEM>>>(
        hid, ew2, eb2, eo, Tz, Dz, EDz, nullptr, elist, cnt, 0);

    combine_kernel<<<(Tz*Dz/4)/256, 256>>>(x1, eo, w, out);
}

// round 4
// speedup vs baseline: 5.3398x; 1.1817x over previous
#include <cuda_runtime.h>
#include <math.h>
#include <stdint.h>

// ---------------------------------------------------------------------------
// Problem constants
// ---------------------------------------------------------------------------
#define Bz   4
#define Sz   1024
#define Dz   1024
#define Hh   16
#define Gg   8
#define HDz  64
#define Ez   8
#define EDz  2048
#define GHz  512
#define Tz   (Bz*Sz)          // 4096 tokens

// ---------------------------------------------------------------------------
// Scratch (static device memory)
// ---------------------------------------------------------------------------
__device__ float g_h1 [Tz*Dz];
__device__ float g_q  [Tz*512];
__device__ float g_k  [Tz*Dz];
__device__ float g_v  [Tz*Dz];
__device__ float g_ao [Tz*Dz];
__device__ float g_x1 [Tz*Dz];
__device__ float g_h2 [Tz*Dz];
__device__ float g_gh [Tz*GHz];
__device__ float g_w  [Tz*2];
__device__ int   g_cnt[Ez];
__device__ int   g_elist[Ez*Tz];
__device__ float g_hid[(size_t)Tz*2*EDz];
__device__ float g_eo [(size_t)Tz*2*Dz];

// ---------------------------------------------------------------------------
// Helpers
// ---------------------------------------------------------------------------
__device__ __forceinline__ uint32_t s2u(const void* p){
    return (uint32_t)__cvta_generic_to_shared(p);
}
__device__ __forceinline__ void cpa16(uint32_t d, const void* s, bool v){
    asm volatile("cp.async.cg.shared.global [%0], [%1], 16, %2;\n"
                 :: "r"(d), "l"(s), "r"(v ? 16 : 0));
}
__device__ __forceinline__ void cp_commit(){ asm volatile("cp.async.commit_group;\n"); }
__device__ __forceinline__ void cp_wait0(){ asm volatile("cp.async.wait_group 0;\n"); }
__device__ __forceinline__ void cp_wait1(){ asm volatile("cp.async.wait_group 1;\n"); }
__device__ __forceinline__ uint32_t f2tf(float x){
    uint32_t r; asm("cvt.rna.tf32.f32 %0, %1;" : "=r"(r) : "f"(x)); return r;
}
__device__ __forceinline__ void mma8(float* c, const uint32_t* a, const uint32_t* b){
    asm volatile("mma.sync.aligned.m16n8k8.row.col.f32.tf32.tf32.f32 "
        "{%0,%1,%2,%3},{%4,%5,%6,%7},{%8,%9},{%0,%1,%2,%3};\n"
        : "+f"(c[0]),"+f"(c[1]),"+f"(c[2]),"+f"(c[3])
        : "r"(a[0]),"r"(a[1]),"r"(a[2]),"r"(a[3]),"r"(b[0]),"r"(b[1]));
}
__device__ __forceinline__ void ldm4(uint32_t* r, uint32_t addr){
    asm volatile("ldmatrix.sync.aligned.m8n8.x4.shared.b16 {%0,%1,%2,%3}, [%4];"
        : "=r"(r[0]),"=r"(r[1]),"=r"(r[2]),"=r"(r[3]) : "r"(addr));
}

// ---------------------------------------------------------------------------
// LayerNorm: one block per token row of 1024
// ---------------------------------------------------------------------------
__global__ __launch_bounds__(256) void ln_kernel(
    const float* __restrict__ X, const float* __restrict__ g,
    const float* __restrict__ b, float* __restrict__ O)
{
    int t = blockIdx.x;
    int tid = threadIdx.x;
    const float4* x4 = (const float4*)(X + (size_t)t * Dz);
    float4 xv = x4[tid];
    float s  = xv.x + xv.y + xv.z + xv.w;
    float ss = xv.x*xv.x + xv.y*xv.y + xv.z*xv.z + xv.w*xv.w;
    #pragma unroll
    for (int off = 16; off; off >>= 1) {
        s  += __shfl_xor_sync(0xffffffffu, s,  off);
        ss += __shfl_xor_sync(0xffffffffu, ss, off);
    }
    __shared__ float sh_s[8], sh_ss[8];
    if ((tid & 31) == 0) { sh_s[tid >> 5] = s; sh_ss[tid >> 5] = ss; }
    __syncthreads();
    if (tid < 32) {
        float a = (tid < 8) ? sh_s[tid]  : 0.f;
        float c = (tid < 8) ? sh_ss[tid] : 0.f;
        #pragma unroll
        for (int off = 4; off; off >>= 1) {
            a += __shfl_xor_sync(0xffffffffu, a, off);
            c += __shfl_xor_sync(0xffffffffu, c, off);
        }
        if (tid == 0) { sh_s[0] = a; sh_ss[0] = c; }
    }
    __syncthreads();
    float mu  = sh_s[0]  * (1.f / Dz);
    float var = sh_ss[0] * (1.f / Dz) - mu * mu;
    float inv = rsqrtf(var + 1e-5f);
    float4 gv = ((const float4*)g)[tid];
    float4 bv = ((const float4*)b)[tid];
    float4 o;
    o.x = (xv.x - mu) * inv * gv.x + bv.x;
    o.y = (xv.y - mu) * inv * gv.y + bv.y;
    o.z = (xv.z - mu) * inv * gv.z + bv.z;
    o.w = (xv.w - mu) * inv * gv.w + bv.w;
    ((float4*)(O + (size_t)t * Dz))[tid] = o;
}

// ---------------------------------------------------------------------------
// Tensor-core tf32 GEMM: C[M,N] = act(A @ B + bias) (+resid), optional gather.
// BM=128, BN=128, BK=32, 256 threads, 8 warps (2 M x 4 N), warp tile 64x32.
// 3-stage cp.async pipeline; A via ldmatrix.x4 (truncated tf32);
// NMMA=3: split hi/lo tf32 with rna rounding (near-fp32, gate path).
// smem: As[3][128][36], Bs[3][32][136]  -> 107520 B dynamic.
// ---------------------------------------------------------------------------
#define GEMM_SMEM (3*128*36*4 + 3*32*136*4)
template<int ACT, bool GATHER, bool RESID, int NMMA>
__global__ void __launch_bounds__(256,2) gemm_tc(
    const float* __restrict__ A, const float* __restrict__ B,
    const float* __restrict__ bias, float* __restrict__ C,
    int M, int N, int K,
    const float* __restrict__ resid,
    const int* __restrict__ elist, const int* __restrict__ cnt, int ashift)
{
    extern __shared__ float sm[];
    float* As = sm;                 // [3][128][36]
    float* Bs = sm + 3*128*36;      // [3][32][136]

    int e = blockIdx.z;
    const float* Bp = B + (size_t)e * K * N;
    const float* bp = bias + (size_t)e * N;
    int mcount = GATHER ? cnt[e] : M;
    int m0 = blockIdx.y * 128;
    if (m0 >= mcount) return;
    int n0 = blockIdx.x * 128;
    const int* lst = GATHER ? (elist + e * Tz) : (const int*)nullptr;

    int tid = threadIdx.x;
    int lane = tid & 31, wid = tid >> 5;
    int warpM = wid >> 2, warpN = wid & 3;

    // A staging: thread -> rows (tid>>3)+32i, cols (tid&7)*4
    int aq = (tid & 7) * 4;
    const float* aptr[4];
    bool aval[4];
    uint32_t adst[4];
    #pragma unroll
    for (int i = 0; i < 4; i++) {
        int r = (tid >> 3) + 32 * i;
        int m = m0 + r;
        bool v = (m < mcount);
        size_t rowg;
        if (GATHER) rowg = v ? (size_t)(lst[m] >> ashift) : 0;
        else        rowg = v ? (size_t)m : 0;
        aptr[i] = A + rowg * (size_t)K + aq;
        aval[i] = v;
        adst[i] = s2u(&As[r * 36 + aq]);
    }
    // B staging: thread -> rows (tid>>5)+8i, cols (tid&31)*4
    const float* bptr = Bp + (size_t)(tid >> 5) * N + n0 + (tid & 31) * 4;
    uint32_t bdst = s2u(&Bs[(tid >> 5) * 136 + (tid & 31) * 4]);
    const uint32_t abuf = 128*36*4, bbuf = 32*136*4;

    uint32_t a_lrow = lane & 15;
    uint32_t a_lcol = (lane & 16) ? 4 : 0;
    uint32_t as_u = s2u(As);

    float acc[4][4][4];
    #pragma unroll
    for (int i=0;i<4;i++)
        #pragma unroll
        for (int j=0;j<4;j++)
            #pragma unroll
            for (int l=0;l<4;l++) acc[i][j][l] = 0.f;

    int KT = K / 32;

    auto stageTile = [&](int kt2, int buf){
        int k0 = kt2 * 32;
        #pragma unroll
        for (int i=0;i<4;i++) cpa16(adst[i] + buf*abuf, aptr[i] + k0, aval[i]);
        #pragma unroll
        for (int i=0;i<4;i++) cpa16(bdst + buf*bbuf + i*(8*136*4),
                                    bptr + (size_t)(k0 + 8*i)*N, true);
    };

    stageTile(0, 0); cp_commit();
    if (KT > 1) stageTile(1, 1);
    cp_commit();

    int bufc = 0, bufs = 2;
    for (int kt = 0; kt < KT; kt++) {
        cp_wait1();
        __syncthreads();
        if (kt + 2 < KT) stageTile(kt+2, bufs);
        cp_commit();

        uint32_t abase = as_u + ((uint32_t)bufc*(128*36) + (warpM*64 + a_lrow)*36 + a_lcol)*4;
        const float* Bb = Bs + bufc*(32*136) + (lane&3)*136 + warpN*32 + (lane>>2);
        #pragma unroll
        for (int ks = 0; ks < 4; ks++) {
            uint32_t ah[4][4];
            #pragma unroll
            for (int mt = 0; mt < 4; mt++)
                ldm4(ah[mt], abase + (mt*16*36 + ks*8)*4);
            uint32_t bh[4][2];
            #pragma unroll
            for (int nt = 0; nt < 4; nt++) {
                bh[nt][0] = __float_as_uint(Bb[(ks*8  )*136 + nt*8]);
                bh[nt][1] = __float_as_uint(Bb[(ks*8+4)*136 + nt*8]);
            }
            if (NMMA == 3) {
                uint32_t al[4][4], bl[4][2];
                #pragma unroll
                for (int mt = 0; mt < 4; mt++)
                    #pragma unroll
                    for (int j = 0; j < 4; j++) {
                        float v = __uint_as_float(ah[mt][j]);
                        uint32_t hi = f2tf(v);
                        al[mt][j] = f2tf(v - __uint_as_float(hi));
                        ah[mt][j] = hi;
                    }
                #pragma unroll
                for (int nt = 0; nt < 4; nt++)
                    #pragma unroll
                    for (int j = 0; j < 2; j++) {
                        float v = __uint_as_float(bh[nt][j]);
                        uint32_t hi = f2tf(v);
                        bl[nt][j] = f2tf(v - __uint_as_float(hi));
                        bh[nt][j] = hi;
                    }
                #pragma unroll
                for (int mt = 0; mt < 4; mt++)
                    #pragma unroll
                    for (int nt = 0; nt < 4; nt++) {
                        mma8(acc[mt][nt], ah[mt], bh[nt]);
                        mma8(acc[mt][nt], al[mt], bh[nt]);
                        mma8(acc[mt][nt], ah[mt], bl[nt]);
                    }
            } else {
                #pragma unroll
                for (int mt = 0; mt < 4; mt++)
                    #pragma unroll
                    for (int nt = 0; nt < 4; nt++)
                        mma8(acc[mt][nt], ah[mt], bh[nt]);
            }
        }
        bufc = (bufc == 2) ? 0 : bufc + 1;
        bufs = (bufs == 2) ? 0 : bufs + 1;
    }

    // epilogue
    float2 bv[4];
    #pragma unroll
    for (int nt = 0; nt < 4; nt++)
        bv[nt] = *(const float2*)(bp + n0 + warpN*32 + (lane&3)*2 + nt*8);

    #pragma unroll
    for (int mt = 0; mt < 4; mt++) {
        #pragma unroll
        for (int hf = 0; hf < 2; hf++) {
            int r = m0 + warpM*64 + mt*16 + (lane>>2) + hf*8;
            if (r >= mcount) continue;
            size_t crow = GATHER ? (size_t)lst[r] : (size_t)r;
            float* Cr = C + crow*(size_t)N + n0 + warpN*32 + (lane&3)*2;
            const float* Rr = RESID ? (resid + crow*(size_t)N + n0 + warpN*32 + (lane&3)*2)
                                    : (const float*)nullptr;
            #pragma unroll
            for (int nt = 0; nt < 4; nt++) {
                float v0 = acc[mt][nt][hf*2+0] + bv[nt].x;
                float v1 = acc[mt][nt][hf*2+1] + bv[nt].y;
                if (ACT == 1) { v0 = fmaxf(v0, 0.f); v1 = fmaxf(v1, 0.f); }
                if (ACT == 2) {
                    v0 = 0.5f*v0*(1.f + erff(v0*0.70710678118654752f));
                    v1 = 0.5f*v1*(1.f + erff(v1*0.70710678118654752f));
                }
                if (RESID) { v0 += Rr[nt*8]; v1 += Rr[nt*8+1]; }
                float2 o; o.x = v0; o.y = v1;
                *(float2*)(Cr + nt*8) = o;
            }
        }
    }
}

// ---------------------------------------------------------------------------
// Fused flash attention (tf32 tensor cores, online softmax).
// grid (Sz/128, B*H) = (8, 64), 256 threads = 8 warps; warp owns 16 Q rows.
// Per KV tile 128: S = Q@K^T (mma), online softmax in regs, P -> smem,
// O += P@V (mma). K/V double-buffered cp.async.
// smem floats: Ps[128][140] (aliases Qs[128][68]) | Ks[2][128][68] | Vs[2][128][72]
// ---------------------------------------------------------------------------
#define FA_SMEM 215040
__global__ void __launch_bounds__(256,1) fa_tc(
    const float* __restrict__ Q, const float* __restrict__ Kg,
    const float* __restrict__ Vg, float* __restrict__ O)
{
    extern __shared__ float sm[];
    float* Ps  = sm;                 // [128][140], aliases Qs [128][68]
    float* Ks0 = sm + 17920;
    float* Ks1 = sm + 26624;
    float* Vs0 = sm + 35328;
    float* Vs1 = sm + 44544;

    int bh = blockIdx.y, b = bh >> 4, h = bh & 15, g = h >> 1;
    int q0 = blockIdx.x * 128;
    int tid = threadIdx.x, lane = tid & 31, w = tid >> 5;

    // Q tile -> Qs (=Ps alias) [128][68], pre-scaled
    const float* Qb = Q + (size_t)(b*Sz + q0) * 512 + g*64;
    #pragma unroll
    for (int i = 0; i < 8; i++) {
        int idx = i*256 + tid;
        int row = idx >> 4, c4 = (idx & 15) * 4;
        float4 qv = *(const float4*)(Qb + (size_t)row*512 + c4);
        qv.x *= 0.125f; qv.y *= 0.125f; qv.z *= 0.125f; qv.w *= 0.125f;
        *(float4*)&Ps[row*68 + c4] = qv;
    }

    const float* Kb = Kg + (size_t)(b*Sz)*1024 + h*64;
    const float* Vb = Vg + (size_t)(b*Sz)*1024 + h*64;
    int srow = tid >> 4, sc4 = (tid & 15) * 4;

    auto stageKV = [&](int kt, int buf){
        const float* kp = Kb + (size_t)(kt*128 + srow)*1024 + sc4;
        const float* vp = Vb + (size_t)(kt*128 + srow)*1024 + sc4;
        uint32_t kd = s2u((buf ? Ks1 : Ks0) + srow*68 + sc4);
        uint32_t vd = s2u((buf ? Vs1 : Vs0) + srow*72 + sc4);
        #pragma unroll
        for (int i = 0; i < 8; i++) {
            cpa16(kd + i*(16*68*4), kp + (size_t)i*16*1024, true);
            cpa16(vd + i*(16*72*4), vp + (size_t)i*16*1024, true);
        }
    };
    stageKV(0, 0); cp_commit();
    __syncthreads();                        // Q visible

    // Q A-fragments to registers (rows w*16..+15, 8 ksteps)
    uint32_t a_lrow = lane & 15;
    uint32_t a_lcol = (lane & 16) ? 4 : 0;
    uint32_t qbase = s2u(Ps) + ((w*16 + a_lrow)*68 + a_lcol)*4;
    uint32_t qf[8][4];
    #pragma unroll
    for (int ks = 0; ks < 8; ks++) ldm4(qf[ks], qbase + ks*8*4);
    __syncthreads();                        // all warps have Q; Ps reusable

    float m0 = -INFINITY, m1 = -INFINITY, l0 = 0.f, l1 = 0.f;
    float oacc[8][4];
    #pragma unroll
    for (int i=0;i<8;i++)
        #pragma unroll
        for (int j=0;j<4;j++) oacc[i][j] = 0.f;

    uint32_t b_lrow = ((lane >> 4) << 3) + (lane & 7);
    uint32_t b_lcol = (lane & 8) ? 4 : 0;
    uint32_t pabase = s2u(Ps) + ((w*16 + a_lrow)*140 + a_lcol)*4;
    float* prow = Ps + (size_t)(w*16 + (lane>>2))*140 + (lane&3)*2;

    for (int kt = 0; kt < 8; kt++) {
        int buf = kt & 1;
        cp_wait0();
        __syncthreads();
        if (kt + 1 < 8) stageKV(kt+1, buf ^ 1);
        cp_commit();

        // ---- S = Q @ K^T (warp: 16 x 128) ----
        float sacc[16][4];
        #pragma unroll
        for (int i=0;i<16;i++)
            #pragma unroll
            for (int j=0;j<4;j++) sacc[i][j] = 0.f;
        uint32_t kbase = s2u(buf ? Ks1 : Ks0) + (b_lrow*68 + b_lcol)*4;
        #pragma unroll
        for (int ks = 0; ks < 8; ks++) {
            #pragma unroll
            for (int np = 0; np < 8; np++) {
                uint32_t r[4];
                ldm4(r, kbase + (np*16*68 + ks*8)*4);
                mma8(sacc[2*np  ], qf[ks], r);
                mma8(sacc[2*np+1], qf[ks], r+2);
            }
        }

        // ---- online softmax (rows lane>>2 and +8) ----
        float t0 = -INFINITY, t1 = -INFINITY;
        #pragma unroll
        for (int nt = 0; nt < 16; nt++) {
            t0 = fmaxf(t0, fmaxf(sacc[nt][0], sacc[nt][1]));
            t1 = fmaxf(t1, fmaxf(sacc[nt][2], sacc[nt][3]));
        }
        t0 = fmaxf(t0, __shfl_xor_sync(0xffffffffu, t0, 1));
        t0 = fmaxf(t0, __shfl_xor_sync(0xffffffffu, t0, 2));
        t1 = fmaxf(t1, __shfl_xor_sync(0xffffffffu, t1, 1));
        t1 = fmaxf(t1, __shfl_xor_sync(0xffffffffu, t1, 2));
        float mn0 = fmaxf(m0, t0), mn1 = fmaxf(m1, t1);
        float sc0 = __expf(m0 - mn0), sc1 = __expf(m1 - mn1);
        float s0 = 0.f, s1 = 0.f;
        #pragma unroll
        for (int nt = 0; nt < 16; nt++) {
            sacc[nt][0] = __expf(sacc[nt][0] - mn0);
            sacc[nt][1] = __expf(sacc[nt][1] - mn0);
            sacc[nt][2] = __expf(sacc[nt][2] - mn1);
            sacc[nt][3] = __expf(sacc[nt][3] - mn1);
            s0 += sacc[nt][0] + sacc[nt][1];
            s1 += sacc[nt][2] + sacc[nt][3];
        }
        s0 += __shfl_xor_sync(0xffffffffu, s0, 1);
        s0 += __shfl_xor_sync(0xffffffffu, s0, 2);
        s1 += __shfl_xor_sync(0xffffffffu, s1, 1);
        s1 += __shfl_xor_sync(0xffffffffu, s1, 2);
        l0 = l0*sc0 + s0; l1 = l1*sc1 + s1;
        m0 = mn0; m1 = mn1;
        #pragma unroll
        for (int nt = 0; nt < 8; nt++) {
            oacc[nt][0] *= sc0; oacc[nt][1] *= sc0;
            oacc[nt][2] *= sc1; oacc[nt][3] *= sc1;
        }

        // ---- P -> smem (own rows only) ----
        #pragma unroll
        for (int nt = 0; nt < 16; nt++) {
            float2 p0; p0.x = sacc[nt][0]; p0.y = sacc[nt][1];
            float2 p1; p1.x = sacc[nt][2]; p1.y = sacc[nt][3];
            *(float2*)(prow + nt*8) = p0;
            *(float2*)(prow + 8*140 + nt*8) = p1;
        }
        __syncwarp();

        // ---- O += P @ V ----
        const float* Bb = (buf ? Vs1 : Vs0) + (lane&3)*72 + (lane>>2);
        #pragma unroll
        for (int k2 = 0; k2 < 16; k2++) {
            uint32_t af[4];
            ldm4(af, pabase + k2*8*4);
            #pragma unroll
            for (int nt = 0; nt < 8; nt++) {
                uint32_t bb[2];
                bb[0] = __float_as_uint(Bb[(k2*8  )*72 + nt*8]);
                bb[1] = __float_as_uint(Bb[(k2*8+4)*72 + nt*8]);
                mma8(oacc[nt], af, bb);
            }
        }
    }

    // epilogue
    float i0 = 1.f / l0, i1 = 1.f / l1;
    int r0 = q0 + w*16 + (lane >> 2);
    float* Op = O + (size_t)(b*Sz + r0)*1024 + h*64 + (lane&3)*2;
    #pragma unroll
    for (int nt = 0; nt < 8; nt++) {
        float2 o0; o0.x = oacc[nt][0]*i0; o0.y = oacc[nt][1]*i0;
        float2 o1; o1.x = oacc[nt][2]*i1; o1.y = oacc[nt][3]*i1;
        *(float2*)(Op + nt*8) = o0;
        *(float2*)(Op + 8*1024 + nt*8) = o1;
    }
}

// ---------------------------------------------------------------------------
// Gate head + softmax + top-2 + renorm + routing. One warp per token.
// ---------------------------------------------------------------------------
__global__ __launch_bounds__(256) void gate_route_kernel(
    const float* __restrict__ GH, const float* __restrict__ gw2,
    const float* __restrict__ gb2,
    float* __restrict__ wout, int* __restrict__ cnt, int* __restrict__ elist)
{
    int warp = threadIdx.x >> 5;
    int lane = threadIdx.x & 31;
    int t = blockIdx.x * 8 + warp;
    if (t >= Tz) return;

    float logit[Ez];
    #pragma unroll
    for (int o = 0; o < Ez; o++) {
        float s = 0.f;
        for (int i = lane; i < GHz; i += 32)
            s += GH[(size_t)t * GHz + i] * gw2[(size_t)i * Ez + o];
        #pragma unroll
        for (int off = 16; off; off >>= 1)
            s += __shfl_xor_sync(0xffffffffu, s, off);
        logit[o] = s + gb2[o];
    }
    if (lane == 0) {
        float m = logit[0];
        #pragma unroll
        for (int o = 1; o < Ez; o++) m = fmaxf(m, logit[o]);
        float w[Ez], sum = 0.f;
        #pragma unroll
        for (int o = 0; o < Ez; o++) { w[o] = expf(logit[o] - m); sum += w[o]; }
        float invs = 1.f / sum;
        #pragma unroll
        for (int o = 0; o < Ez; o++) w[o] *= invs;
        int i0 = 0; float v0 = w[0];
        #pragma unroll
        for (int o = 1; o < Ez; o++) if (w[o] > v0) { v0 = w[o]; i0 = o; }
        int i1 = -1; float v1 = -1.f;
        #pragma unroll
        for (int o = 0; o < Ez; o++)
            if (o != i0 && w[o] > v1) { v1 = w[o]; i1 = o; }
        float e1 = expf(v1 - v0);
        float den = 1.f + e1;
        wout[2*t + 0] = 1.f / den;
        wout[2*t + 1] = e1 / den;
        int p0 = atomicAdd(&cnt[i0], 1);
        elist[i0 * Tz + p0] = 2*t + 0;
        int p1 = atomicAdd(&cnt[i1], 1);
        elist[i1 * Tz + p1] = 2*t + 1;
    }
}

__global__ void zero_counts_kernel(int* cnt)
{
    if (threadIdx.x < Ez) cnt[threadIdx.x] = 0;
}

// ---------------------------------------------------------------------------
// Final combine: out = x1 + w0*eo[2t] + w1*eo[2t+1]
// ---------------------------------------------------------------------------
__global__ __launch_bounds__(256) void combine_kernel(
    const float* __restrict__ x1, const float* __restrict__ eo,
    const float* __restrict__ w, float* __restrict__ out)
{
    int idx = blockIdx.x * 256 + threadIdx.x;
    int t = idx >> 8;
    int c = idx & 255;
    float w0 = w[2*t], w1 = w[2*t + 1];
    float4 a  = ((const float4*)x1)[idx];
    float4 e0 = ((const float4*)(eo + (size_t)(2*t)     * Dz))[c];
    float4 e1 = ((const float4*)(eo + (size_t)(2*t + 1) * Dz))[c];
    float4 r;
    r.x = a.x + w0 * e0.x + w1 * e1.x;
    r.y = a.y + w0 * e0.y + w1 * e1.y;
    r.z = a.z + w0 * e0.z + w1 * e1.z;
    r.w = a.w + w0 * e0.w + w1 * e1.w;
    ((float4*)out)[idx] = r;
}

// ---------------------------------------------------------------------------
// Host launch
// ---------------------------------------------------------------------------
extern "C" void kernel_launch(void* const* d_in, const int* in_sizes, int n_in,
                              void* d_out, int out_size)
{
    const float* x    = (const float*)d_in[0];
    const float* wq   = (const float*)d_in[1];
    const float* bq   = (const float*)d_in[2];
    const float* wk   = (const float*)d_in[3];
    const float* bk   = (const float*)d_in[4];
    const float* wv   = (const float*)d_in[5];
    const float* bv   = (const float*)d_in[6];
    const float* wo   = (const float*)d_in[7];
    const float* bo   = (const float*)d_in[8];
    const float* ln1g = (const float*)d_in[9];
    const float* ln1b = (const float*)d_in[10];
    const float* ln2g = (const float*)d_in[11];
    const float* ln2b = (const float*)d_in[12];
    const float* gw1  = (const float*)d_in[13];
    const float* gb1  = (const float*)d_in[14];
    const float* gw2  = (const float*)d_in[15];
    const float* gb2  = (const float*)d_in[16];
    const float* ew1  = (const float*)d_in[17];
    const float* eb1  = (const float*)d_in[18];
    const float* ew2  = (const float*)d_in[19];
    const float* eb2  = (const float*)d_in[20];
    float* out = (float*)d_out;

    float *h1, *q, *k, *v, *ao, *x1, *h2, *gh, *w, *hid, *eo;
    int *cnt, *elist;
    cudaGetSymbolAddress((void**)&h1,   g_h1);
    cudaGetSymbolAddress((void**)&q,    g_q);
    cudaGetSymbolAddress((void**)&k,    g_k);
    cudaGetSymbolAddress((void**)&v,    g_v);
    cudaGetSymbolAddress((void**)&ao,   g_ao);
    cudaGetSymbolAddress((void**)&x1,   g_x1);
    cudaGetSymbolAddress((void**)&h2,   g_h2);
    cudaGetSymbolAddress((void**)&gh,   g_gh);
    cudaGetSymbolAddress((void**)&w,    g_w);
    cudaGetSymbolAddress((void**)&hid,  g_hid);
    cudaGetSymbolAddress((void**)&eo,   g_eo);
    cudaGetSymbolAddress((void**)&cnt,  g_cnt);
    cudaGetSymbolAddress((void**)&elist,g_elist);

    cudaFuncSetAttribute(gemm_tc<0,false,false,1>, cudaFuncAttributeMaxDynamicSharedMemorySize, GEMM_SMEM);
    cudaFuncSetAttribute(gemm_tc<0,false,true,1>,  cudaFuncAttributeMaxDynamicSharedMemorySize, GEMM_SMEM);
    cudaFuncSetAttribute(gemm_tc<1,false,false,3>, cudaFuncAttributeMaxDynamicSharedMemorySize, GEMM_SMEM);
    cudaFuncSetAttribute(gemm_tc<2,true,false,1>,  cudaFuncAttributeMaxDynamicSharedMemorySize, GEMM_SMEM);
    cudaFuncSetAttribute(gemm_tc<0,true,false,1>,  cudaFuncAttributeMaxDynamicSharedMemorySize, GEMM_SMEM);
    cudaFuncSetAttribute(fa_tc, cudaFuncAttributeMaxDynamicSharedMemorySize, FA_SMEM);

    zero_counts_kernel<<<1, 32>>>(cnt);
    ln_kernel<<<Tz, 256>>>(x, ln1g, ln1b, h1);

    gemm_tc<0,false,false,1><<<dim3(4, 32, 1), 256, GEMM_SMEM>>>(
        h1, wq, bq, q, Tz, 512, Dz, nullptr, nullptr, nullptr, 0);
    gemm_tc<0,false,false,1><<<dim3(8, 32, 1), 256, GEMM_SMEM>>>(
        h1, wk, bk, k, Tz, Dz, Dz, nullptr, nullptr, nullptr, 0);
    gemm_tc<0,false,false,1><<<dim3(8, 32, 1), 256, GEMM_SMEM>>>(
        h1, wv, bv, v, Tz, Dz, Dz, nullptr, nullptr, nullptr, 0);

    fa_tc<<<dim3(Sz/128, Bz*Hh), 256, FA_SMEM>>>(q, k, v, ao);

    gemm_tc<0,false,true,1><<<dim3(8, 32, 1), 256, GEMM_SMEM>>>(
        ao, wo, bo, x1, Tz, Dz, Dz, x, nullptr, nullptr, 0);

    ln_kernel<<<Tz, 256>>>(x1, ln2g, ln2b, h2);

    // gate layer 1 in split-tf32 (rna, near-fp32) to protect top-2 selection
    gemm_tc<1,false,false,3><<<dim3(4, 32, 1), 256, GEMM_SMEM>>>(
        h2, gw1, gb1, gh, Tz, GHz, Dz, nullptr, nullptr, nullptr, 0);

    gate_route_kernel<<<Tz/8, 256>>>(gh, gw2, gb2, w, cnt, elist);

    gemm_tc<2,true,false,1><<<dim3(EDz/128, Tz/128, Ez), 256, GEMM_SMEM>>>(
        h2, ew1, eb1, hid, Tz, EDz, Dz, nullptr, elist, cnt, 1);
    gemm_tc<0,true,false,1><<<dim3(Dz/128, Tz/128, Ez), 256, GEMM_SMEM>>>(
        hid, ew2, eb2, eo, Tz, Dz, EDz, nullptr, elist, cnt, 0);

    combine_kernel<<<(Tz*Dz/4)/256, 256>>>(x1, eo, w, out);
}

// round 6
// speedup vs baseline: 7.1922x; 1.3469x over previous
#include <cuda_runtime.h>
#include <cuda_fp16.h>
#include <math.h>
#include <stdint.h>

// ---------------------------------------------------------------------------
// Problem constants
// ---------------------------------------------------------------------------
#define Bz   4
#define Sz   1024
#define Dz   1024
#define Hh   16
#define Gg   8
#define HDz  64
#define Ez   8
#define EDz  2048
#define GHz  512
#define Tz   (Bz*Sz)          // 4096 tokens

// ---------------------------------------------------------------------------
// Scratch (static device memory)
// ---------------------------------------------------------------------------
__device__ __half g_h1h [Tz*Dz];
__device__ __half g_qh  [Tz*512];
__device__ __half g_kh  [Tz*Dz];
__device__ __half g_vh  [Tz*Dz];
__device__ __half g_aoh [Tz*Dz];
__device__ float  g_x1  [Tz*Dz];
__device__ float  g_h2  [Tz*Dz];
__device__ __half g_h2h [Tz*Dz];
__device__ float  g_gh  [Tz*GHz];
__device__ float  g_w   [Tz*2];
__device__ int    g_cnt [Ez];
__device__ int    g_elist[Ez*Tz];
__device__ __half g_hidh[(size_t)Tz*2*EDz];
__device__ float  g_eo  [(size_t)Tz*2*Dz];
// fp16 weight copies (converted per launch)
__device__ __half g_wqh [Dz*512];
__device__ __half g_wkh [Dz*Dz];
__device__ __half g_wvh [Dz*Dz];
__device__ __half g_woh [Dz*Dz];
__device__ __half g_ew1h[(size_t)Ez*Dz*EDz];
__device__ __half g_ew2h[(size_t)Ez*EDz*Dz];

// ---------------------------------------------------------------------------
// Helpers
// ---------------------------------------------------------------------------
__device__ __forceinline__ uint32_t s2u(const void* p){
    return (uint32_t)__cvta_generic_to_shared(p);
}
__device__ __forceinline__ void cpa16(uint32_t d, const void* s, bool v){
    asm volatile("cp.async.cg.shared.global [%0], [%1], 16, %2;\n"
                 :: "r"(d), "l"(s), "r"(v ? 16 : 0));
}
__device__ __forceinline__ void cp_commit(){ asm volatile("cp.async.commit_group;\n"); }
__device__ __forceinline__ void cp_wait0(){ asm volatile("cp.async.wait_group 0;\n"); }
__device__ __forceinline__ void cp_wait1(){ asm volatile("cp.async.wait_group 1;\n"); }
__device__ __forceinline__ uint32_t f2tf(float x){
    uint32_t r; asm("cvt.rna.tf32.f32 %0, %1;" : "=r"(r) : "f"(x)); return r;
}
__device__ __forceinline__ void mma8(float* c, const uint32_t* a, const uint32_t* b){
    asm volatile("mma.sync.aligned.m16n8k8.row.col.f32.tf32.tf32.f32 "
        "{%0,%1,%2,%3},{%4,%5,%6,%7},{%8,%9},{%0,%1,%2,%3};\n"
        : "+f"(c[0]),"+f"(c[1]),"+f"(c[2]),"+f"(c[3])
        : "r"(a[0]),"r"(a[1]),"r"(a[2]),"r"(a[3]),"r"(b[0]),"r"(b[1]));
}
__device__ __forceinline__ void mma16(float* c, const uint32_t* a, uint32_t b0, uint32_t b1){
    asm volatile("mma.sync.aligned.m16n8k16.row.col.f32.f16.f16.f32 "
        "{%0,%1,%2,%3},{%4,%5,%6,%7},{%8,%9},{%0,%1,%2,%3};\n"
        : "+f"(c[0]),"+f"(c[1]),"+f"(c[2]),"+f"(c[3])
        : "r"(a[0]),"r"(a[1]),"r"(a[2]),"r"(a[3]),"r"(b0),"r"(b1));
}
__device__ __forceinline__ void ldm4(uint32_t* r, uint32_t addr){
    asm volatile("ldmatrix.sync.aligned.m8n8.x4.shared.b16 {%0,%1,%2,%3}, [%4];"
        : "=r"(r[0]),"=r"(r[1]),"=r"(r[2]),"=r"(r[3]) : "r"(addr));
}
__device__ __forceinline__ void ldm4t(uint32_t* r, uint32_t addr){
    asm volatile("ldmatrix.sync.aligned.m8n8.x4.trans.shared.b16 {%0,%1,%2,%3}, [%4];"
        : "=r"(r[0]),"=r"(r[1]),"=r"(r[2]),"=r"(r[3]) : "r"(addr));
}

// ---------------------------------------------------------------------------
// fp32 -> fp16 streaming convert (8 elems/thread)
// ---------------------------------------------------------------------------
__global__ __launch_bounds__(256) void cvt_f2h(
    const float* __restrict__ in, __half* __restrict__ out, int n8)
{
    int i = blockIdx.x * 256 + threadIdx.x;
    if (i >= n8) return;
    float4 a = ((const float4*)in)[2*i];
    float4 b = ((const float4*)in)[2*i+1];
    __half2 h0 = __floats2half2_rn(a.x, a.y);
    __half2 h1 = __floats2half2_rn(a.z, a.w);
    __half2 h2 = __floats2half2_rn(b.x, b.y);
    __half2 h3 = __floats2half2_rn(b.z, b.w);
    uint4 u;
    u.x = *(uint32_t*)&h0; u.y = *(uint32_t*)&h1;
    u.z = *(uint32_t*)&h2; u.w = *(uint32_t*)&h3;
    ((uint4*)out)[i] = u;
}

// ---------------------------------------------------------------------------
// LayerNorm: one block per token row of 1024. Writes fp16 (+ optional fp32).
// ---------------------------------------------------------------------------
template<bool W32>
__global__ __launch_bounds__(256) void ln_kernel(
    const float* __restrict__ X, const float* __restrict__ g,
    const float* __restrict__ b, float* __restrict__ O32, __half* __restrict__ O16)
{
    int t = blockIdx.x;
    int tid = threadIdx.x;
    const float4* x4 = (const float4*)(X + (size_t)t * Dz);
    float4 xv = x4[tid];
    float s  = xv.x + xv.y + xv.z + xv.w;
    float ss = xv.x*xv.x + xv.y*xv.y + xv.z*xv.z + xv.w*xv.w;
    #pragma unroll
    for (int off = 16; off; off >>= 1) {
        s  += __shfl_xor_sync(0xffffffffu, s,  off);
        ss += __shfl_xor_sync(0xffffffffu, ss, off);
    }
    __shared__ float sh_s[8], sh_ss[8];
    if ((tid & 31) == 0) { sh_s[tid >> 5] = s; sh_ss[tid >> 5] = ss; }
    __syncthreads();
    if (tid < 32) {
        float a = (tid < 8) ? sh_s[tid]  : 0.f;
        float c = (tid < 8) ? sh_ss[tid] : 0.f;
        #pragma unroll
        for (int off = 4; off; off >>= 1) {
            a += __shfl_xor_sync(0xffffffffu, a, off);
            c += __shfl_xor_sync(0xffffffffu, c, off);
        }
        if (tid == 0) { sh_s[0] = a; sh_ss[0] = c; }
    }
    __syncthreads();
    float mu  = sh_s[0]  * (1.f / Dz);
    float var = sh_ss[0] * (1.f / Dz) - mu * mu;
    float inv = rsqrtf(var + 1e-5f);
    float4 gv = ((const float4*)g)[tid];
    float4 bv = ((const float4*)b)[tid];
    float4 o;
    o.x = (xv.x - mu) * inv * gv.x + bv.x;
    o.y = (xv.y - mu) * inv * gv.y + bv.y;
    o.z = (xv.z - mu) * inv * gv.z + bv.z;
    o.w = (xv.w - mu) * inv * gv.w + bv.w;
    if (W32) ((float4*)(O32 + (size_t)t * Dz))[tid] = o;
    __half2 p0 = __floats2half2_rn(o.x, o.y);
    __half2 p1 = __floats2half2_rn(o.z, o.w);
    uint2 u; u.x = *(uint32_t*)&p0; u.y = *(uint32_t*)&p1;
    ((uint2*)(O16 + (size_t)t * Dz))[tid] = u;
}

// ---------------------------------------------------------------------------
// fp16 tensor-core GEMM: C[M,N] = act(A @ B + bias)(+resid), optional gather.
// BM=128, BN=128, BK=64 (halves), 256 threads, 8 warps (2M x 4N), warp 64x32.
// A fp16 [M,K] (ldmatrix), B fp16 [K,N] (ldmatrix.trans). 3-stage cp.async.
// ACT: 0 none, 1 relu, 2 gelu, 3 scale-by-0.125. OUTH: fp16 output.
// smem: As[3][128][72] + Bs[3][64][136] halves = 107520 B.
// ---------------------------------------------------------------------------
#define GEMMH_SMEM (3*128*72*2 + 3*64*136*2)
template<int ACT, bool GATHER, bool RESID, bool OUTH>
__global__ void __launch_bounds__(256,2) gemm_hc(
    const __half* __restrict__ A, const __half* __restrict__ B,
    const float* __restrict__ bias, void* __restrict__ Cv,
    int M, int N, int K,
    const float* __restrict__ resid,
    const int* __restrict__ elist, const int* __restrict__ cnt, int ashift)
{
    extern __shared__ __half smh[];
    __half* As = smh;                  // [3][128][72]
    __half* Bs = smh + 3*128*72;       // [3][64][136]

    int e = blockIdx.z;
    const __half* Bp = B + (size_t)e * K * N;
    const float*  bp = bias + (size_t)e * N;
    int mcount = GATHER ? cnt[e] : M;
    int m0 = blockIdx.y * 128;
    if (m0 >= mcount) return;
    int n0 = blockIdx.x * 128;
    const int* lst = GATHER ? (elist + e * Tz) : (const int*)nullptr;

    int tid = threadIdx.x;
    int lane = tid & 31, wid = tid >> 5;
    int warpM = wid >> 2, warpN = wid & 3;

    // A staging: rows (tid>>3)+32i, col halves (tid&7)*8
    int aq = (tid & 7) * 8;
    const __half* aptr[4];
    bool aval[4];
    uint32_t adst[4];
    #pragma unroll
    for (int i = 0; i < 4; i++) {
        int r = (tid >> 3) + 32 * i;
        int m = m0 + r;
        bool v = (m < mcount);
        size_t rowg;
        if (GATHER) rowg = v ? (size_t)(lst[m] >> ashift) : 0;
        else        rowg = v ? (size_t)m : 0;
        aptr[i] = A + rowg * (size_t)K + aq;
        aval[i] = v;
        adst[i] = s2u(&As[r * 72 + aq]);
    }
    // B staging: rows tid>>2 (64), col halves (tid&3)*32 + j*8
    int brow = tid >> 2, bq = (tid & 3) * 32;
    const __half* bptr = Bp + (size_t)brow * N + n0 + bq;
    uint32_t bdst = s2u(&Bs[brow * 136 + bq]);
    const uint32_t abuf = 128*72*2, bbuf = 64*136*2;

    uint32_t as_u = s2u(As), bs_u = s2u(Bs);

    float acc[4][4][4];
    #pragma unroll
    for (int i=0;i<4;i++)
        #pragma unroll
        for (int j=0;j<4;j++)
            #pragma unroll
            for (int l=0;l<4;l++) acc[i][j][l] = 0.f;

    int KT = K / 64;

    auto stageTile = [&](int kt2, int buf){
        int k0 = kt2 * 64;
        #pragma unroll
        for (int i=0;i<4;i++) cpa16(adst[i] + buf*abuf, aptr[i] + k0, aval[i]);
        #pragma unroll
        for (int j=0;j<4;j++) cpa16(bdst + buf*bbuf + j*16,
                                    bptr + (size_t)k0*N + j*8, true);
    };

    stageTile(0, 0); cp_commit();
    if (KT > 1) stageTile(1, 1);
    cp_commit();

    int bufc = 0, bufs = 2;
    uint32_t lr = lane & 15, lc = (lane >> 4) * 8;
    for (int kt = 0; kt < KT; kt++) {
        cp_wait1();
        __syncthreads();
        if (kt + 2 < KT) stageTile(kt+2, bufs);
        cp_commit();

        uint32_t abase = as_u + ((uint32_t)bufc*(128*72) + (warpM*64 + lr)*72 + lc)*2;
        uint32_t bbase = bs_u + ((uint32_t)bufc*(64*136) + lr*136 + warpN*32 + lc)*2;
        #pragma unroll
        for (int ks = 0; ks < 4; ks++) {
            uint32_t ah[4][4];
            #pragma unroll
            for (int mt = 0; mt < 4; mt++)
                ldm4(ah[mt], abase + (mt*16*72 + ks*16)*2);
            uint32_t bt[2][4];
            #pragma unroll
            for (int pr = 0; pr < 2; pr++)
                ldm4t(bt[pr], bbase + (ks*16*136 + pr*16)*2);
            #pragma unroll
            for (int mt = 0; mt < 4; mt++) {
                mma16(acc[mt][0], ah[mt], bt[0][0], bt[0][1]);
                mma16(acc[mt][1], ah[mt], bt[0][2], bt[0][3]);
                mma16(acc[mt][2], ah[mt], bt[1][0], bt[1][1]);
                mma16(acc[mt][3], ah[mt], bt[1][2], bt[1][3]);
            }
        }
        __syncthreads();
        bufc = (bufc == 2) ? 0 : bufc + 1;
        bufs = (bufs == 2) ? 0 : bufs + 1;
    }

    // epilogue
    float2 bv[4];
    #pragma unroll
    for (int nt = 0; nt < 4; nt++)
        bv[nt] = *(const float2*)(bp + n0 + warpN*32 + (lane&3)*2 + nt*8);

    float*  Cf = (float*)Cv;
    __half* Ch = (__half*)Cv;
    #pragma unroll
    for (int mt = 0; mt < 4; mt++) {
        #pragma unroll
        for (int hf = 0; hf < 2; hf++) {
            int r = m0 + warpM*64 + mt*16 + (lane>>2) + hf*8;
            if (r >= mcount) continue;
            size_t crow = GATHER ? (size_t)lst[r] : (size_t)r;
            int coff = n0 + warpN*32 + (lane&3)*2;
            const float* Rr = RESID ? (resid + crow*(size_t)N + coff) : (const float*)nullptr;
            #pragma unroll
            for (int nt = 0; nt < 4; nt++) {
                float v0 = acc[mt][nt][hf*2+0] + bv[nt].x;
                float v1 = acc[mt][nt][hf*2+1] + bv[nt].y;
                if (ACT == 1) { v0 = fmaxf(v0, 0.f); v1 = fmaxf(v1, 0.f); }
                if (ACT == 2) {
                    v0 = 0.5f*v0*(1.f + erff(v0*0.70710678118654752f));
                    v1 = 0.5f*v1*(1.f + erff(v1*0.70710678118654752f));
                }
                if (ACT == 3) { v0 *= 0.125f; v1 *= 0.125f; }
                if (RESID) { v0 += Rr[nt*8]; v1 += Rr[nt*8+1]; }
                if (OUTH) {
                    __half2 h = __floats2half2_rn(v0, v1);
                    *(__half2*)(Ch + crow*(size_t)N + coff + nt*8) = h;
                } else {
                    float2 o; o.x = v0; o.y = v1;
                    *(float2*)(Cf + crow*(size_t)N + coff + nt*8) = o;
                }
            }
        }
    }
}

// ---------------------------------------------------------------------------
// tf32 split (near-fp32) GEMM for the gate MLP layer 1 only.
// NMMA=3 fixed, ACT=relu. smem: As[3][128][36], Bs[3][32][136] floats.
// ---------------------------------------------------------------------------
#define GEMM_SMEM (3*128*36*4 + 3*32*136*4)
__global__ void __launch_bounds__(256,2) gemm_gate(
    const float* __restrict__ A, const float* __restrict__ B,
    const float* __restrict__ bias, float* __restrict__ C,
    int M, int N, int K)
{
    extern __shared__ float smf[];
    float* As = smf;
    float* Bs = smf + 3*128*36;

    int m0 = blockIdx.y * 128;
    int n0 = blockIdx.x * 128;
    int tid = threadIdx.x;
    int lane = tid & 31, wid = tid >> 5;
    int warpM = wid >> 2, warpN = wid & 3;

    int aq = (tid & 7) * 4;
    const float* aptr[4];
    uint32_t adst[4];
    #pragma unroll
    for (int i = 0; i < 4; i++) {
        int r = (tid >> 3) + 32 * i;
        aptr[i] = A + (size_t)(m0 + r) * K + aq;
        adst[i] = s2u(&As[r * 36 + aq]);
    }
    const float* bptr = B + (size_t)(tid >> 5) * N + n0 + (tid & 31) * 4;
    uint32_t bdst = s2u(&Bs[(tid >> 5) * 136 + (tid & 31) * 4]);
    const uint32_t abuf = 128*36*4, bbuf = 32*136*4;

    uint32_t a_lrow = lane & 15;
    uint32_t a_lcol = (lane & 16) ? 4 : 0;
    uint32_t as_u = s2u(As);

    float acc[4][4][4];
    #pragma unroll
    for (int i=0;i<4;i++)
        #pragma unroll
        for (int j=0;j<4;j++)
            #pragma unroll
            for (int l=0;l<4;l++) acc[i][j][l] = 0.f;

    int KT = K / 32;
    auto stageTile = [&](int kt2, int buf){
        int k0 = kt2 * 32;
        #pragma unroll
        for (int i=0;i<4;i++) cpa16(adst[i] + buf*abuf, aptr[i] + k0, true);
        #pragma unroll
        for (int i=0;i<4;i++) cpa16(bdst + buf*bbuf + i*(8*136*4),
                                    bptr + (size_t)(k0 + 8*i)*N, true);
    };
    stageTile(0, 0); cp_commit();
    if (KT > 1) stageTile(1, 1);
    cp_commit();

    int bufc = 0, bufs = 2;
    for (int kt = 0; kt < KT; kt++) {
        cp_wait1();
        __syncthreads();
        if (kt + 2 < KT) stageTile(kt+2, bufs);
        cp_commit();

        uint32_t abase = as_u + ((uint32_t)bufc*(128*36) + (warpM*64 + a_lrow)*36 + a_lcol)*4;
        const float* Bb = Bs + bufc*(32*136) + (lane&3)*136 + warpN*32 + (lane>>2);
        #pragma unroll
        for (int ks = 0; ks < 4; ks++) {
            uint32_t ah[4][4], al[4][4], bh[4][2], bl[4][2];
            #pragma unroll
            for (int mt = 0; mt < 4; mt++) {
                ldm4(ah[mt], abase + (mt*16*36 + ks*8)*4);
                #pragma unroll
                for (int j = 0; j < 4; j++) {
                    float v = __uint_as_float(ah[mt][j]);
                    uint32_t hi = f2tf(v);
                    al[mt][j] = f2tf(v - __uint_as_float(hi));
                    ah[mt][j] = hi;
                }
            }
            #pragma unroll
            for (int nt = 0; nt < 4; nt++) {
                float w0 = Bb[(ks*8  )*136 + nt*8];
                float w1 = Bb[(ks*8+4)*136 + nt*8];
                uint32_t h0 = f2tf(w0), h1 = f2tf(w1);
                bh[nt][0] = h0; bh[nt][1] = h1;
                bl[nt][0] = f2tf(w0 - __uint_as_float(h0));
                bl[nt][1] = f2tf(w1 - __uint_as_float(h1));
            }
            #pragma unroll
            for (int mt = 0; mt < 4; mt++)
                #pragma unroll
                for (int nt = 0; nt < 4; nt++) {
                    mma8(acc[mt][nt], ah[mt], bh[nt]);
                    mma8(acc[mt][nt], al[mt], bh[nt]);
                    mma8(acc[mt][nt], ah[mt], bl[nt]);
                }
        }
        __syncthreads();
        bufc = (bufc == 2) ? 0 : bufc + 1;
        bufs = (bufs == 2) ? 0 : bufs + 1;
    }

    float2 bv[4];
    #pragma unroll
    for (int nt = 0; nt < 4; nt++)
        bv[nt] = *(const float2*)(bias + n0 + warpN*32 + (lane&3)*2 + nt*8);

    #pragma unroll
    for (int mt = 0; mt < 4; mt++)
        #pragma unroll
        for (int hf = 0; hf < 2; hf++) {
            int r = m0 + warpM*64 + mt*16 + (lane>>2) + hf*8;
            float* Cr = C + (size_t)r*N + n0 + warpN*32 + (lane&3)*2;
            #pragma unroll
            for (int nt = 0; nt < 4; nt++) {
                float v0 = fmaxf(acc[mt][nt][hf*2+0] + bv[nt].x, 0.f);
                float v1 = fmaxf(acc[mt][nt][hf*2+1] + bv[nt].y, 0.f);
                float2 o; o.x = v0; o.y = v1;
                *(float2*)(Cr + nt*8) = o;
            }
        }
}

// ---------------------------------------------------------------------------
// Fused flash attention, fp16 tensor cores, online softmax (fp32 stats).
// grid (Sz/128, B*H); 256 threads; warp owns 16 Q rows x 128-col KV tiles.
// Q pre-scaled by 0.125 at Q-projection epilogue.
// smem halves: Ps[128][136] (aliases Qs[128][72]) | Ks[2][128][72] | Vs[2][128][72]
// ---------------------------------------------------------------------------
#define FA_SMEM (128*136*2 + 4*128*72*2)
__global__ void __launch_bounds__(256,1) fa_h(
    const __half* __restrict__ Q, const __half* __restrict__ Kg,
    const __half* __restrict__ Vg, __half* __restrict__ O)
{
    extern __shared__ __half smh[];
    __half* Ps  = smh;                     // [128][136]; alias Qs [128][72]
    __half* Ks0 = smh + 128*136;
    __half* Ks1 = Ks0 + 128*72;
    __half* Vs0 = Ks1 + 128*72;
    __half* Vs1 = Vs0 + 128*72;

    int bh = blockIdx.y, b = bh >> 4, h = bh & 15, g = h >> 1;
    int q0 = blockIdx.x * 128;
    int tid = threadIdx.x, lane = tid & 31, w = tid >> 5;

    // stage Q -> Qs (alias Ps), pitch 72 halves
    const __half* Qb = Q + (size_t)(b*Sz + q0) * 512 + g*64;
    {
        int row = tid >> 1;
        #pragma unroll
        for (int j = 0; j < 4; j++) {
            int c = (tid & 1) + 2*j;   // chunk of 8 halves
            cpa16(s2u(Ps + row*72 + c*8), Qb + (size_t)row*512 + c*8, true);
        }
    }
    cp_commit();

    const __half* Kb = Kg + (size_t)(b*Sz)*1024 + h*64;
    const __half* Vb = Vg + (size_t)(b*Sz)*1024 + h*64;

    auto stageKV = [&](int kt, int buf){
        int row = tid >> 1;
        __half* Kd = (buf ? Ks1 : Ks0) + row*72;
        __half* Vd = (buf ? Vs1 : Vs0) + row*72;
        const __half* kp = Kb + (size_t)(kt*128 + row)*1024;
        const __half* vp = Vb + (size_t)(kt*128 + row)*1024;
        #pragma unroll
        for (int j = 0; j < 4; j++) {
            int c = (tid & 1) + 2*j;
            cpa16(s2u(Kd + c*8), kp + c*8, true);
            cpa16(s2u(Vd + c*8), vp + c*8, true);
        }
    };
    stageKV(0, 0); cp_commit();

    // Q fragments (wait for Q which is in the first commit group)
    asm volatile("cp.async.wait_group 1;\n");
    __syncthreads();
    uint32_t lr = lane & 15, lc = (lane >> 4) * 8;
    uint32_t qbase = s2u(Ps) + ((w*16 + lr)*72 + lc)*2;
    uint32_t qf[4][4];
    #pragma unroll
    for (int ks = 0; ks < 4; ks++) ldm4(qf[ks], qbase + ks*32);
    __syncthreads();   // Ps region now reusable

    float m0 = -INFINITY, m1 = -INFINITY, l0 = 0.f, l1 = 0.f;
    float oacc[8][4];
    #pragma unroll
    for (int i=0;i<8;i++)
        #pragma unroll
        for (int j=0;j<4;j++) oacc[i][j] = 0.f;

    uint32_t pabase = s2u(Ps) + ((w*16 + lr)*136 + lc)*2;
    __half* prow = Ps + (size_t)(w*16 + (lane>>2))*136 + (lane&3)*2;

    for (int kt = 0; kt < 8; kt++) {
        int buf = kt & 1;
        cp_wait0();
        __syncthreads();
        if (kt + 1 < 8) stageKV(kt+1, buf ^ 1);
        cp_commit();

        // ---- S = Q @ K^T ----
        float sacc[16][4];
        #pragma unroll
        for (int i=0;i<16;i++)
            #pragma unroll
            for (int j=0;j<4;j++) sacc[i][j] = 0.f;
        uint32_t kbase = s2u(buf ? Ks1 : Ks0) + (lr*72 + lc)*2;
        #pragma unroll
        for (int ks = 0; ks < 4; ks++) {
            #pragma unroll
            for (int np = 0; np < 8; np++) {
                uint32_t r[4];
                ldm4(r, kbase + (np*16*72 + ks*16)*2);
                mma16(sacc[2*np  ], qf[ks], r[0], r[2]);
                mma16(sacc[2*np+1], qf[ks], r[1], r[3]);
            }
        }

        // ---- online softmax ----
        float t0 = -INFINITY, t1 = -INFINITY;
        #pragma unroll
        for (int nt = 0; nt < 16; nt++) {
            t0 = fmaxf(t0, fmaxf(sacc[nt][0], sacc[nt][1]));
            t1 = fmaxf(t1, fmaxf(sacc[nt][2], sacc[nt][3]));
        }
        t0 = fmaxf(t0, __shfl_xor_sync(0xffffffffu, t0, 1));
        t0 = fmaxf(t0, __shfl_xor_sync(0xffffffffu, t0, 2));
        t1 = fmaxf(t1, __shfl_xor_sync(0xffffffffu, t1, 1));
        t1 = fmaxf(t1, __shfl_xor_sync(0xffffffffu, t1, 2));
        float mn0 = fmaxf(m0, t0), mn1 = fmaxf(m1, t1);
        float sc0 = __expf(m0 - mn0), sc1 = __expf(m1 - mn1);
        float s0 = 0.f, s1 = 0.f;
        #pragma unroll
        for (int nt = 0; nt < 16; nt++) {
            sacc[nt][0] = __expf(sacc[nt][0] - mn0);
            sacc[nt][1] = __expf(sacc[nt][1] - mn0);
            sacc[nt][2] = __expf(sacc[nt][2] - mn1);
            sacc[nt][3] = __expf(sacc[nt][3] - mn1);
            s0 += sacc[nt][0] + sacc[nt][1];
            s1 += sacc[nt][2] + sacc[nt][3];
        }
        s0 += __shfl_xor_sync(0xffffffffu, s0, 1);
        s0 += __shfl_xor_sync(0xffffffffu, s0, 2);
        s1 += __shfl_xor_sync(0xffffffffu, s1, 1);
        s1 += __shfl_xor_sync(0xffffffffu, s1, 2);
        l0 = l0*sc0 + s0; l1 = l1*sc1 + s1;
        m0 = mn0; m1 = mn1;
        #pragma unroll
        for (int nt = 0; nt < 8; nt++) {
            oacc[nt][0] *= sc0; oacc[nt][1] *= sc0;
            oacc[nt][2] *= sc1; oacc[nt][3] *= sc1;
        }

        // ---- P -> smem fp16 (own rows only) ----
        #pragma unroll
        for (int nt = 0; nt < 16; nt++) {
            *(__half2*)(prow + nt*8)          = __floats2half2_rn(sacc[nt][0], sacc[nt][1]);
            *(__half2*)(prow + 8*136 + nt*8)  = __floats2half2_rn(sacc[nt][2], sacc[nt][3]);
        }
        __syncwarp();

        // ---- O += P @ V ----
        uint32_t vbase = s2u(buf ? Vs1 : Vs0) + (lr*72 + lc)*2;
        #pragma unroll
        for (int k2 = 0; k2 < 8; k2++) {
            uint32_t pf[4];
            ldm4(pf, pabase + k2*32);
            #pragma unroll
            for (int hp = 0; hp < 4; hp++) {
                uint32_t vt[4];
                ldm4t(vt, vbase + (k2*16*72 + hp*16)*2);
                mma16(oacc[2*hp  ], pf, vt[0], vt[1]);
                mma16(oacc[2*hp+1], pf, vt[2], vt[3]);
            }
        }
    }

    // epilogue (fp16 out)
    float i0 = 1.f / l0, i1 = 1.f / l1;
    int r0 = q0 + w*16 + (lane >> 2);
    __half* Op = O + (size_t)(b*Sz + r0)*1024 + h*64 + (lane&3)*2;
    #pragma unroll
    for (int nt = 0; nt < 8; nt++) {
        *(__half2*)(Op + nt*8)          = __floats2half2_rn(oacc[nt][0]*i0, oacc[nt][1]*i0);
        *(__half2*)(Op + 8*1024 + nt*8) = __floats2half2_rn(oacc[nt][2]*i1, oacc[nt][3]*i1);
    }
}

// ---------------------------------------------------------------------------
// Gate head + softmax + top-2 + renorm + routing. One warp per token.
// ---------------------------------------------------------------------------
__global__ __launch_bounds__(256) void gate_route_kernel(
    const float* __restrict__ GH, const float* __restrict__ gw2,
    const float* __restrict__ gb2,
    float* __restrict__ wout, int* __restrict__ cnt, int* __restrict__ elist)
{
    int warp = threadIdx.x >> 5;
    int lane = threadIdx.x & 31;
    int t = blockIdx.x * 8 + warp;
    if (t >= Tz) return;

    float logit[Ez];
    #pragma unroll
    for (int o = 0; o < Ez; o++) {
        float s = 0.f;
        for (int i = lane; i < GHz; i += 32)
            s += GH[(size_t)t * GHz + i] * gw2[(size_t)i * Ez + o];
        #pragma unroll
        for (int off = 16; off; off >>= 1)
            s += __shfl_xor_sync(0xffffffffu, s, off);
        logit[o] = s + gb2[o];
    }
    if (lane == 0) {
        float m = logit[0];
        #pragma unroll
        for (int o = 1; o < Ez; o++) m = fmaxf(m, logit[o]);
        float w[Ez], sum = 0.f;
        #pragma unroll
        for (int o = 0; o < Ez; o++) { w[o] = expf(logit[o] - m); sum += w[o]; }
        float invs = 1.f / sum;
        #pragma unroll
        for (int o = 0; o < Ez; o++) w[o] *= invs;
        int i0 = 0; float v0 = w[0];
        #pragma unroll
        for (int o = 1; o < Ez; o++) if (w[o] > v0) { v0 = w[o]; i0 = o; }
        int i1 = -1; float v1 = -1.f;
        #pragma unroll
        for (int o = 0; o < Ez; o++)
            if (o != i0 && w[o] > v1) { v1 = w[o]; i1 = o; }
        float e1 = expf(v1 - v0);
        float den = 1.f + e1;
        wout[2*t + 0] = 1.f / den;
        wout[2*t + 1] = e1 / den;
        int p0 = atomicAdd(&cnt[i0], 1);
        elist[i0 * Tz + p0] = 2*t + 0;
        int p1 = atomicAdd(&cnt[i1], 1);
        elist[i1 * Tz + p1] = 2*t + 1;
    }
}

__global__ void zero_counts_kernel(int* cnt)
{
    if (threadIdx.x < Ez) cnt[threadIdx.x] = 0;
}

// ---------------------------------------------------------------------------
// Final combine: out = x1 + w0*eo[2t] + w1*eo[2t+1]
// ---------------------------------------------------------------------------
__global__ __launch_bounds__(256) void combine_kernel(
    const float* __restrict__ x1, const float* __restrict__ eo,
    const float* __restrict__ w, float* __restrict__ out)
{
    int idx = blockIdx.x * 256 + threadIdx.x;
    int t = idx >> 8;
    int c = idx & 255;
    float w0 = w[2*t], w1 = w[2*t + 1];
    float4 a  = ((const float4*)x1)[idx];
    float4 e0 = ((const float4*)(eo + (size_t)(2*t)     * Dz))[c];
    float4 e1 = ((const float4*)(eo + (size_t)(2*t + 1) * Dz))[c];
    float4 r;
    r.x = a.x + w0 * e0.x + w1 * e1.x;
    r.y = a.y + w0 * e0.y + w1 * e1.y;
    r.z = a.z + w0 * e0.z + w1 * e1.z;
    r.w = a.w + w0 * e0.w + w1 * e1.w;
    ((float4*)out)[idx] = r;
}

// ---------------------------------------------------------------------------
// Host launch
// ---------------------------------------------------------------------------
extern "C" void kernel_launch(void* const* d_in, const int* in_sizes, int n_in,
                              void* d_out, int out_size)
{
    const float* x    = (const float*)d_in[0];
    const float* wq   = (const float*)d_in[1];
    const float* bq   = (const float*)d_in[2];
    const float* wk   = (const float*)d_in[3];
    const float* bk   = (const float*)d_in[4];
    const float* wv   = (const float*)d_in[5];
    const float* bv   = (const float*)d_in[6];
    const float* wo   = (const float*)d_in[7];
    const float* bo   = (const float*)d_in[8];
    const float* ln1g = (const float*)d_in[9];
    const float* ln1b = (const float*)d_in[10];
    const float* ln2g = (const float*)d_in[11];
    const float* ln2b = (const float*)d_in[12];
    const float* gw1  = (const float*)d_in[13];
    const float* gb1  = (const float*)d_in[14];
    const float* gw2  = (const float*)d_in[15];
    const float* gb2  = (const float*)d_in[16];
    const float* ew1  = (const float*)d_in[17];
    const float* eb1  = (const float*)d_in[18];
    const float* ew2  = (const float*)d_in[19];
    const float* eb2  = (const float*)d_in[20];
    float* out = (float*)d_out;

    __half *h1h, *qh, *kh, *vh, *aoh, *h2h, *hidh;
    __half *wqh, *wkh, *wvh, *woh, *ew1h, *ew2h;
    float *x1, *h2, *gh, *w, *eo;
    int *cnt, *elist;
    cudaGetSymbolAddress((void**)&h1h,  g_h1h);
    cudaGetSymbolAddress((void**)&qh,   g_qh);
    cudaGetSymbolAddress((void**)&kh,   g_kh);
    cudaGetSymbolAddress((void**)&vh,   g_vh);
    cudaGetSymbolAddress((void**)&aoh,  g_aoh);
    cudaGetSymbolAddress((void**)&x1,   g_x1);
    cudaGetSymbolAddress((void**)&h2,   g_h2);
    cudaGetSymbolAddress((void**)&h2h,  g_h2h);
    cudaGetSymbolAddress((void**)&gh,   g_gh);
    cudaGetSymbolAddress((void**)&w,    g_w);
    cudaGetSymbolAddress((void**)&hidh, g_hidh);
    cudaGetSymbolAddress((void**)&eo,   g_eo);
    cudaGetSymbolAddress((void**)&cnt,  g_cnt);
    cudaGetSymbolAddress((void**)&elist,g_elist);
    cudaGetSymbolAddress((void**)&wqh,  g_wqh);
    cudaGetSymbolAddress((void**)&wkh,  g_wkh);
    cudaGetSymbolAddress((void**)&wvh,  g_wvh);
    cudaGetSymbolAddress((void**)&woh,  g_woh);
    cudaGetSymbolAddress((void**)&ew1h, g_ew1h);
    cudaGetSymbolAddress((void**)&ew2h, g_ew2h);

    cudaFuncSetAttribute(gemm_hc<3,false,false,true>, cudaFuncAttributeMaxDynamicSharedMemorySize, GEMMH_SMEM);
    cudaFuncSetAttribute(gemm_hc<0,false,false,true>, cudaFuncAttributeMaxDynamicSharedMemorySize, GEMMH_SMEM);
    cudaFuncSetAttribute(gemm_hc<0,false,true,false>, cudaFuncAttributeMaxDynamicSharedMemorySize, GEMMH_SMEM);
    cudaFuncSetAttribute(gemm_hc<2,true,false,true>,  cudaFuncAttributeMaxDynamicSharedMemorySize, GEMMH_SMEM);
    cudaFuncSetAttribute(gemm_hc<0,true,false,false>, cudaFuncAttributeMaxDynamicSharedMemorySize, GEMMH_SMEM);
    cudaFuncSetAttribute(gemm_gate, cudaFuncAttributeMaxDynamicSharedMemorySize, GEMM_SMEM);
    cudaFuncSetAttribute(fa_h, cudaFuncAttributeMaxDynamicSharedMemorySize, FA_SMEM);

    // weight conversion pre-pass
    cvt_f2h<<<(Dz*512/8 + 255)/256, 256>>>(wq, wqh, Dz*512/8);
    cvt_f2h<<<(Dz*Dz/8 + 255)/256, 256>>>(wk, wkh, Dz*Dz/8);
    cvt_f2h<<<(Dz*Dz/8 + 255)/256, 256>>>(wv, wvh, Dz*Dz/8);
    cvt_f2h<<<(Dz*Dz/8 + 255)/256, 256>>>(wo, woh, Dz*Dz/8);
    cvt_f2h<<<(Ez*Dz*EDz/8 + 255)/256, 256>>>(ew1, ew1h, Ez*Dz*EDz/8);
    cvt_f2h<<<(Ez*EDz*Dz/8 + 255)/256, 256>>>(ew2, ew2h, Ez*EDz*Dz/8);

    zero_counts_kernel<<<1, 32>>>(cnt);
    ln_kernel<false><<<Tz, 256>>>(x, ln1g, ln1b, nullptr, h1h);

    // QKV projections (fp16). Q scaled by 0.125 in epilogue.
    gemm_hc<3,false,false,true><<<dim3(4, 32, 1), 256, GEMMH_SMEM>>>(
        h1h, wqh, bq, qh, Tz, 512, Dz, nullptr, nullptr, nullptr, 0);
    gemm_hc<0,false,false,true><<<dim3(8, 32, 1), 256, GEMMH_SMEM>>>(
        h1h, wkh, bk, kh, Tz, Dz, Dz, nullptr, nullptr, nullptr, 0);
    gemm_hc<0,false,false,true><<<dim3(8, 32, 1), 256, GEMMH_SMEM>>>(
        h1h, wvh, bv, vh, Tz, Dz, Dz, nullptr, nullptr, nullptr, 0);

    fa_h<<<dim3(Sz/128, Bz*Hh), 256, FA_SMEM>>>(qh, kh, vh, aoh);

    // Output projection + residual -> x1 fp32
    gemm_hc<0,false,true,false><<<dim3(8, 32, 1), 256, GEMMH_SMEM>>>(
        aoh, woh, bo, x1, Tz, Dz, Dz, x, nullptr, nullptr, 0);

    ln_kernel<true><<<Tz, 256>>>(x1, ln2g, ln2b, h2, h2h);

    // gate layer 1: split-tf32 near-fp32 (protects top-2 selection)
    gemm_gate<<<dim3(4, 32, 1), 256, GEMM_SMEM>>>(h2, gw1, gb1, gh, Tz, GHz, Dz);

    gate_route_kernel<<<Tz/8, 256>>>(gh, gw2, gb2, w, cnt, elist);

    // Expert FFN (fp16, gathered)
    gemm_hc<2,true,false,true><<<dim3(EDz/128, Tz/128, Ez), 256, GEMMH_SMEM>>>(
        h2h, ew1h, eb1, hidh, Tz, EDz, Dz, nullptr, elist, cnt, 1);
    gemm_hc<0,true,false,false><<<dim3(Dz/128, Tz/128, Ez), 256, GEMMH_SMEM>>>(
        hidh, ew2h, eb2, eo, Tz, Dz, EDz, nullptr, elist, cnt, 0);

    combine_kernel<<<(Tz*Dz/4)/256, 256>>>(x1, eo, w, out);
}

// round 8
// speedup vs baseline: 7.3148x; 1.0170x over previous
#include <cuda_runtime.h>
#include <cuda_fp16.h>
#include <math.h>
#include <stdint.h>

// ---------------------------------------------------------------------------
// Problem constants
// ---------------------------------------------------------------------------
#define Bz   4
#define Sz   1024
#define Dz   1024
#define Hh   16
#define Gg   8
#define HDz  64
#define Ez   8
#define EDz  2048
#define GHz  512
#define Tz   (Bz*Sz)          // 4096 tokens
#define QKVN 2560             // packed q(512) | k(1024) | v(1024)

// ---------------------------------------------------------------------------
// Scratch (static device memory)
// ---------------------------------------------------------------------------
__device__ __half g_h1h [Tz*Dz];
__device__ __half g_qkvh[(size_t)Tz*QKVN];
__device__ __half g_aoh [Tz*Dz];
__device__ float  g_x1  [Tz*Dz];
__device__ float  g_h2  [Tz*Dz];
__device__ __half g_h2h [Tz*Dz];
__device__ float  g_gh  [Tz*GHz];
__device__ float  g_w   [Tz*2];
__device__ int    g_cnt [Ez];
__device__ int    g_elist[Ez*Tz];
__device__ __half g_hidh[(size_t)Tz*2*EDz];
__device__ __half g_eo  [(size_t)Tz*2*Dz];
// fp16 weights ([K][N] row-major; qkv packed) + packed qkv bias
__device__ __half g_wqkvh[(size_t)Dz*QKVN];
__device__ __half g_woh  [(size_t)Dz*Dz];
__device__ __half g_ew1h [(size_t)Ez*Dz*EDz];
__device__ __half g_ew2h [(size_t)Ez*EDz*Dz];
__device__ float  g_qkvb [QKVN];

// ---------------------------------------------------------------------------
// Helpers
// ---------------------------------------------------------------------------
__device__ __forceinline__ uint32_t s2u(const void* p){
    return (uint32_t)__cvta_generic_to_shared(p);
}
__device__ __forceinline__ void cpa16(uint32_t d, const void* s, bool v){
    asm volatile("cp.async.cg.shared.global [%0], [%1], 16, %2;\n"
                 :: "r"(d), "l"(s), "r"(v ? 16 : 0));
}
__device__ __forceinline__ void cp_commit(){ asm volatile("cp.async.commit_group;\n"); }
__device__ __forceinline__ void cp_wait0(){ asm volatile("cp.async.wait_group 0;\n"); }
__device__ __forceinline__ void cp_wait1(){ asm volatile("cp.async.wait_group 1;\n"); }
__device__ __forceinline__ uint32_t f2tf(float x){
    uint32_t r; asm("cvt.rna.tf32.f32 %0, %1;" : "=r"(r) : "f"(x)); return r;
}
__device__ __forceinline__ void mma8(float* c, const uint32_t* a, const uint32_t* b){
    asm volatile("mma.sync.aligned.m16n8k8.row.col.f32.tf32.tf32.f32 "
        "{%0,%1,%2,%3},{%4,%5,%6,%7},{%8,%9},{%0,%1,%2,%3};\n"
        : "+f"(c[0]),"+f"(c[1]),"+f"(c[2]),"+f"(c[3])
        : "r"(a[0]),"r"(a[1]),"r"(a[2]),"r"(a[3]),"r"(b[0]),"r"(b[1]));
}
__device__ __forceinline__ void mma16(float* c, const uint32_t* a, uint32_t b0, uint32_t b1){
    asm volatile("mma.sync.aligned.m16n8k16.row.col.f32.f16.f16.f32 "
        "{%0,%1,%2,%3},{%4,%5,%6,%7},{%8,%9},{%0,%1,%2,%3};\n"
        : "+f"(c[0]),"+f"(c[1]),"+f"(c[2]),"+f"(c[3])
        : "r"(a[0]),"r"(a[1]),"r"(a[2]),"r"(a[3]),"r"(b0),"r"(b1));
}
__device__ __forceinline__ void ldm4(uint32_t* r, uint32_t addr){
    asm volatile("ldmatrix.sync.aligned.m8n8.x4.shared.b16 {%0,%1,%2,%3}, [%4];"
        : "=r"(r[0]),"=r"(r[1]),"=r"(r[2]),"=r"(r[3]) : "r"(addr));
}
__device__ __forceinline__ void ldm4t(uint32_t* r, uint32_t addr){
    asm volatile("ldmatrix.sync.aligned.m8n8.x4.trans.shared.b16 {%0,%1,%2,%3}, [%4];"
        : "=r"(r[0]),"=r"(r[1]),"=r"(r[2]),"=r"(r[3]) : "r"(addr));
}

// ---------------------------------------------------------------------------
// fp32 -> fp16 convert with output stride (for packed weight layouts).
// in: [rows][N] fp32 contiguous; out row pitch = ldout halves. 4 elems/thread.
// ---------------------------------------------------------------------------
__global__ __launch_bounds__(256) void cvt_pack(
    const float* __restrict__ in, __half* __restrict__ out,
    int N, int ldout, int total4, float scale)
{
    int i = blockIdx.x * 256 + threadIdx.x;
    if (i >= total4) return;
    int row = i / (N >> 2);
    int c4  = (i - row * (N >> 2)) * 4;
    float4 a = *(const float4*)(in + (size_t)row * N + c4);
    __half2 h0 = __floats2half2_rn(a.x * scale, a.y * scale);
    __half2 h1 = __floats2half2_rn(a.z * scale, a.w * scale);
    uint2 u; u.x = *(uint32_t*)&h0; u.y = *(uint32_t*)&h1;
    *(uint2*)(out + (size_t)row * ldout + c4) = u;
}

__global__ void pack_bias(const float* __restrict__ bq, const float* __restrict__ bk,
                          const float* __restrict__ bv, float* __restrict__ o)
{
    int i = blockIdx.x * 256 + threadIdx.x;
    if (i < 512)        o[i] = bq[i] * 0.125f;
    else if (i < 1536)  o[i] = bk[i - 512];
    else if (i < QKVN)  o[i] = bv[i - 1536];
}

// ---------------------------------------------------------------------------
// LayerNorm: one block per token row of 1024. Writes fp16 (+ optional fp32).
// ---------------------------------------------------------------------------
template<bool W32>
__global__ __launch_bounds__(256) void ln_kernel(
    const float* __restrict__ X, const float* __restrict__ g,
    const float* __restrict__ b, float* __restrict__ O32, __half* __restrict__ O16)
{
    int t = blockIdx.x;
    int tid = threadIdx.x;
    const float4* x4 = (const float4*)(X + (size_t)t * Dz);
    float4 xv = x4[tid];
    float s  = xv.x + xv.y + xv.z + xv.w;
    float ss = xv.x*xv.x + xv.y*xv.y + xv.z*xv.z + xv.w*xv.w;
    #pragma unroll
    for (int off = 16; off; off >>= 1) {
        s  += __shfl_xor_sync(0xffffffffu, s,  off);
        ss += __shfl_xor_sync(0xffffffffu, ss, off);
    }
    __shared__ float sh_s[8], sh_ss[8];
    if ((tid & 31) == 0) { sh_s[tid >> 5] = s; sh_ss[tid >> 5] = ss; }
    __syncthreads();
    if (tid < 32) {
        float a = (tid < 8) ? sh_s[tid]  : 0.f;
        float c = (tid < 8) ? sh_ss[tid] : 0.f;
        #pragma unroll
        for (int off = 4; off; off >>= 1) {
            a += __shfl_xor_sync(0xffffffffu, a, off);
            c += __shfl_xor_sync(0xffffffffu, c, off);
        }
        if (tid == 0) { sh_s[0] = a; sh_ss[0] = c; }
    }
    __syncthreads();
    float mu  = sh_s[0]  * (1.f / Dz);
    float var = sh_ss[0] * (1.f / Dz) - mu * mu;
    float inv = rsqrtf(var + 1e-5f);
    float4 gv = ((const float4*)g)[tid];
    float4 bv = ((const float4*)b)[tid];
    float4 o;
    o.x = (xv.x - mu) * inv * gv.x + bv.x;
    o.y = (xv.y - mu) * inv * gv.y + bv.y;
    o.z = (xv.z - mu) * inv * gv.z + bv.z;
    o.w = (xv.w - mu) * inv * gv.w + bv.w;
    if (W32) ((float4*)(O32 + (size_t)t * Dz))[tid] = o;
    __half2 p0 = __floats2half2_rn(o.x, o.y);
    __half2 p1 = __floats2half2_rn(o.z, o.w);
    uint2 u; u.x = *(uint32_t*)&p0; u.y = *(uint32_t*)&p1;
    ((uint2*)(O16 + (size_t)t * Dz))[tid] = u;
}

// ---------------------------------------------------------------------------
// fp16 tensor-core GEMM: C[M,N] = act(A @ B + bias)(+resid), optional gather.
// BM=128, BN=128, BK=64 (halves), 256 threads, 8 warps (2M x 4N), warp 64x32.
// A fp16 [M,K] (ldmatrix), B fp16 [K,N] (ldmatrix.trans). 3-stage cp.async.
// ACT: 0 none, 1 relu, 2 gelu. OUTH: fp16 output.
// smem: As[3][128][72] + Bs[3][64][136] halves = 107520 B.
// ---------------------------------------------------------------------------
#define GEMMH_SMEM (3*128*72*2 + 3*64*136*2)
template<int ACT, bool GATHER, bool RESID, bool OUTH>
__global__ void __launch_bounds__(256,2) gemm_hc(
    const __half* __restrict__ A, const __half* __restrict__ B,
    const float* __restrict__ bias, void* __restrict__ Cv,
    int M, int N, int K,
    const float* __restrict__ resid,
    const int* __restrict__ elist, const int* __restrict__ cnt, int ashift)
{
    extern __shared__ __half smh[];
    __half* As = smh;                  // [3][128][72]
    __half* Bs = smh + 3*128*72;       // [3][64][136]

    int e = blockIdx.z;
    const __half* Bp = B + (size_t)e * K * N;
    const float*  bp = bias + (size_t)e * N;
    int mcount = GATHER ? cnt[e] : M;
    int m0 = blockIdx.y * 128;
    if (m0 >= mcount) return;
    int n0 = blockIdx.x * 128;
    const int* lst = GATHER ? (elist + e * Tz) : (const int*)nullptr;

    int tid = threadIdx.x;
    int lane = tid & 31, wid = tid >> 5;
    int warpM = wid >> 2, warpN = wid & 3;

    // A staging: rows (tid>>3)+32i, col halves (tid&7)*8
    int aq = (tid & 7) * 8;
    const __half* aptr[4];
    bool aval[4];
    uint32_t adst[4];
    #pragma unroll
    for (int i = 0; i < 4; i++) {
        int r = (tid >> 3) + 32 * i;
        int m = m0 + r;
        bool v = (m < mcount);
        size_t rowg;
        if (GATHER) rowg = v ? (size_t)(lst[m] >> ashift) : 0;
        else        rowg = v ? (size_t)m : 0;
        aptr[i] = A + rowg * (size_t)K + aq;
        aval[i] = v;
        adst[i] = s2u(&As[r * 72 + aq]);
    }
    // B staging: rows tid>>2 (64), col halves (tid&3)*32 + j*8
    int brow = tid >> 2, bq = (tid & 3) * 32;
    const __half* bptr = Bp + (size_t)brow * N + n0 + bq;
    uint32_t bdst = s2u(&Bs[brow * 136 + bq]);
    const uint32_t abuf = 128*72*2, bbuf = 64*136*2;

    uint32_t as_u = s2u(As), bs_u = s2u(Bs);

    float acc[4][4][4];
    #pragma unroll
    for (int i=0;i<4;i++)
        #pragma unroll
        for (int j=0;j<4;j++)
            #pragma unroll
            for (int l=0;l<4;l++) acc[i][j][l] = 0.f;

    int KT = K / 64;

    auto stageTile = [&](int kt2, int buf){
        int k0 = kt2 * 64;
        #pragma unroll
        for (int i=0;i<4;i++) cpa16(adst[i] + buf*abuf, aptr[i] + k0, aval[i]);
        #pragma unroll
        for (int j=0;j<4;j++) cpa16(bdst + buf*bbuf + j*16,
                                    bptr + (size_t)k0*N + j*8, true);
    };

    stageTile(0, 0); cp_commit();
    if (KT > 1) stageTile(1, 1);
    cp_commit();

    int bufc = 0, bufs = 2;
    uint32_t lr = lane & 15, lc = (lane >> 4) * 8;
    for (int kt = 0; kt < KT; kt++) {
        cp_wait1();
        __syncthreads();
        if (kt + 2 < KT) stageTile(kt+2, bufs);
        cp_commit();

        uint32_t abase = as_u + ((uint32_t)bufc*(128*72) + (warpM*64 + lr)*72 + lc)*2;
        uint32_t bbase = bs_u + ((uint32_t)bufc*(64*136) + lr*136 + warpN*32 + lc)*2;
        #pragma unroll
        for (int ks = 0; ks < 4; ks++) {
            uint32_t ah[4][4];
            #pragma unroll
            for (int mt = 0; mt < 4; mt++)
                ldm4(ah[mt], abase + (mt*16*72 + ks*16)*2);
            uint32_t bt[2][4];
            #pragma unroll
            for (int pr = 0; pr < 2; pr++)
                ldm4t(bt[pr], bbase + (ks*16*136 + pr*16)*2);
            #pragma unroll
            for (int mt = 0; mt < 4; mt++) {
                mma16(acc[mt][0], ah[mt], bt[0][0], bt[0][1]);
                mma16(acc[mt][1], ah[mt], bt[0][2], bt[0][3]);
                mma16(acc[mt][2], ah[mt], bt[1][0], bt[1][1]);
                mma16(acc[mt][3], ah[mt], bt[1][2], bt[1][3]);
            }
        }
        __syncthreads();
        bufc = (bufc == 2) ? 0 : bufc + 1;
        bufs = (bufs == 2) ? 0 : bufs + 1;
    }

    // epilogue
    float2 bv[4];
    #pragma unroll
    for (int nt = 0; nt < 4; nt++)
        bv[nt] = *(const float2*)(bp + n0 + warpN*32 + (lane&3)*2 + nt*8);

    float*  Cf = (float*)Cv;
    __half* Ch = (__half*)Cv;
    #pragma unroll
    for (int mt = 0; mt < 4; mt++) {
        #pragma unroll
        for (int hf = 0; hf < 2; hf++) {
            int r = m0 + warpM*64 + mt*16 + (lane>>2) + hf*8;
            if (r >= mcount) continue;
            size_t crow = GATHER ? (size_t)lst[r] : (size_t)r;
            int coff = n0 + warpN*32 + (lane&3)*2;
            const float* Rr = RESID ? (resid + crow*(size_t)N + coff) : (const float*)nullptr;
            #pragma unroll
            for (int nt = 0; nt < 4; nt++) {
                float v0 = acc[mt][nt][hf*2+0] + bv[nt].x;
                float v1 = acc[mt][nt][hf*2+1] + bv[nt].y;
                if (ACT == 1) { v0 = fmaxf(v0, 0.f); v1 = fmaxf(v1, 0.f); }
                if (ACT == 2) {
                    v0 = 0.5f*v0*(1.f + erff(v0*0.70710678118654752f));
                    v1 = 0.5f*v1*(1.f + erff(v1*0.70710678118654752f));
                }
                if (RESID) { v0 += Rr[nt*8]; v1 += Rr[nt*8+1]; }
                if (OUTH) {
                    __half2 h = __floats2half2_rn(v0, v1);
                    *(__half2*)(Ch + crow*(size_t)N + coff + nt*8) = h;
                } else {
                    float2 o; o.x = v0; o.y = v1;
                    *(float2*)(Cf + crow*(size_t)N + coff + nt*8) = o;
                }
            }
        }
    }
}

// ---------------------------------------------------------------------------
// tf32 split (near-fp32) GEMM for the gate MLP layer 1 only.
// smem: As[3][128][36], Bs[3][32][136] floats.
// ---------------------------------------------------------------------------
#define GEMM_SMEM (3*128*36*4 + 3*32*136*4)
__global__ void __launch_bounds__(256,2) gemm_gate(
    const float* __restrict__ A, const float* __restrict__ B,
    const float* __restrict__ bias, float* __restrict__ C,
    int M, int N, int K)
{
    extern __shared__ float smf[];
    float* As = smf;
    float* Bs = smf + 3*128*36;

    int m0 = blockIdx.y * 128;
    int n0 = blockIdx.x * 128;
    int tid = threadIdx.x;
    int lane = tid & 31, wid = tid >> 5;
    int warpM = wid >> 2, warpN = wid & 3;

    int aq = (tid & 7) * 4;
    const float* aptr[4];
    uint32_t adst[4];
    #pragma unroll
    for (int i = 0; i < 4; i++) {
        int r = (tid >> 3) + 32 * i;
        aptr[i] = A + (size_t)(m0 + r) * K + aq;
        adst[i] = s2u(&As[r * 36 + aq]);
    }
    const float* bptr = B + (size_t)(tid >> 5) * N + n0 + (tid & 31) * 4;
    uint32_t bdst = s2u(&Bs[(tid >> 5) * 136 + (tid & 31) * 4]);
    const uint32_t abuf = 128*36*4, bbuf = 32*136*4;

    uint32_t a_lrow = lane & 15;
    uint32_t a_lcol = (lane & 16) ? 4 : 0;
    uint32_t as_u = s2u(As);

    float acc[4][4][4];
    #pragma unroll
    for (int i=0;i<4;i++)
        #pragma unroll
        for (int j=0;j<4;j++)
            #pragma unroll
            for (int l=0;l<4;l++) acc[i][j][l] = 0.f;

    int KT = K / 32;
    auto stageTile = [&](int kt2, int buf){
        int k0 = kt2 * 32;
        #pragma unroll
        for (int i=0;i<4;i++) cpa16(adst[i] + buf*abuf, aptr[i] + k0, true);
        #pragma unroll
        for (int i=0;i<4;i++) cpa16(bdst + buf*bbuf + i*(8*136*4),
                                    bptr + (size_t)(k0 + 8*i)*N, true);
    };
    stageTile(0, 0); cp_commit();
    if (KT > 1) stageTile(1, 1);
    cp_commit();

    int bufc = 0, bufs = 2;
    for (int kt = 0; kt < KT; kt++) {
        cp_wait1();
        __syncthreads();
        if (kt + 2 < KT) stageTile(kt+2, bufs);
        cp_commit();

        uint32_t abase = as_u + ((uint32_t)bufc*(128*36) + (warpM*64 + a_lrow)*36 + a_lcol)*4;
        const float* Bb = Bs + bufc*(32*136) + (lane&3)*136 + warpN*32 + (lane>>2);
        #pragma unroll
        for (int ks = 0; ks < 4; ks++) {
            uint32_t ah[4][4], al[4][4], bh[4][2], bl[4][2];
            #pragma unroll
            for (int mt = 0; mt < 4; mt++) {
                ldm4(ah[mt], abase + (mt*16*36 + ks*8)*4);
                #pragma unroll
                for (int j = 0; j < 4; j++) {
                    float v = __uint_as_float(ah[mt][j]);
                    uint32_t hi = f2tf(v);
                    al[mt][j] = f2tf(v - __uint_as_float(hi));
                    ah[mt][j] = hi;
                }
            }
            #pragma unroll
            for (int nt = 0; nt < 4; nt++) {
                float w0 = Bb[(ks*8  )*136 + nt*8];
                float w1 = Bb[(ks*8+4)*136 + nt*8];
                uint32_t h0 = f2tf(w0), h1 = f2tf(w1);
                bh[nt][0] = h0; bh[nt][1] = h1;
                bl[nt][0] = f2tf(w0 - __uint_as_float(h0));
                bl[nt][1] = f2tf(w1 - __uint_as_float(h1));
            }
            #pragma unroll
            for (int mt = 0; mt < 4; mt++)
                #pragma unroll
                for (int nt = 0; nt < 4; nt++) {
                    mma8(acc[mt][nt], ah[mt], bh[nt]);
                    mma8(acc[mt][nt], al[mt], bh[nt]);
                    mma8(acc[mt][nt], ah[mt], bl[nt]);
                }
        }
        __syncthreads();
        bufc = (bufc == 2) ? 0 : bufc + 1;
        bufs = (bufs == 2) ? 0 : bufs + 1;
    }

    float2 bv[4];
    #pragma unroll
    for (int nt = 0; nt < 4; nt++)
        bv[nt] = *(const float2*)(bias + n0 + warpN*32 + (lane&3)*2 + nt*8);

    #pragma unroll
    for (int mt = 0; mt < 4; mt++)
        #pragma unroll
        for (int hf = 0; hf < 2; hf++) {
            int r = m0 + warpM*64 + mt*16 + (lane>>2) + hf*8;
            float* Cr = C + (size_t)r*N + n0 + warpN*32 + (lane&3)*2;
            #pragma unroll
            for (int nt = 0; nt < 4; nt++) {
                float v0 = fmaxf(acc[mt][nt][hf*2+0] + bv[nt].x, 0.f);
                float v1 = fmaxf(acc[mt][nt][hf*2+1] + bv[nt].y, 0.f);
                float2 o; o.x = v0; o.y = v1;
                *(float2*)(Cr + nt*8) = o;
            }
        }
}

// ---------------------------------------------------------------------------
// Fused flash attention, fp16 mma.sync, online softmax (fp32 stats).
// Reads packed QKV [T][2560] (Q pre-scaled via weights). 2 CTAs/SM.
// smem halves: Ps[128][136] (aliases Qs[128][72]) | Ks[2][128][72] | Vs[2][128][72]
// ---------------------------------------------------------------------------
#define FA_SMEM (128*136*2 + 4*128*72*2)
__global__ void __launch_bounds__(256,2) fa_h(
    const __half* __restrict__ QKV, __half* __restrict__ O)
{
    extern __shared__ __half smh[];
    __half* Ps  = smh;                     // [128][136]; alias Qs [128][72]
    __half* Ks0 = smh + 128*136;
    __half* Ks1 = Ks0 + 128*72;
    __half* Vs0 = Ks1 + 128*72;
    __half* Vs1 = Vs0 + 128*72;

    int bh = blockIdx.y, b = bh >> 4, h = bh & 15, g = h >> 1;
    int q0 = blockIdx.x * 128;
    int tid = threadIdx.x, lane = tid & 31, w = tid >> 5;

    const __half* Qb = QKV + (size_t)(b*Sz + q0) * QKVN + g*64;
    {
        int row = tid >> 1;
        #pragma unroll
        for (int j = 0; j < 4; j++) {
            int c = (tid & 1) + 2*j;
            cpa16(s2u(Ps + row*72 + c*8), Qb + (size_t)row*QKVN + c*8, true);
        }
    }
    cp_commit();

    const __half* Kb = QKV + (size_t)(b*Sz)*QKVN + 512 + h*64;
    const __half* Vb = QKV + (size_t)(b*Sz)*QKVN + 1536 + h*64;

    auto stageKV = [&](int kt, int buf){
        int row = tid >> 1;
        __half* Kd = (buf ? Ks1 : Ks0) + row*72;
        __half* Vd = (buf ? Vs1 : Vs0) + row*72;
        const __half* kp = Kb + (size_t)(kt*128 + row)*QKVN;
        const __half* vp = Vb + (size_t)(kt*128 + row)*QKVN;
        #pragma unroll
        for (int j = 0; j < 4; j++) {
            int c = (tid & 1) + 2*j;
            cpa16(s2u(Kd + c*8), kp + c*8, true);
            cpa16(s2u(Vd + c*8), vp + c*8, true);
        }
    };
    stageKV(0, 0); cp_commit();

    asm volatile("cp.async.wait_group 1;\n");
    __syncthreads();
    uint32_t lr = lane & 15, lc = (lane >> 4) * 8;
    uint32_t qbase = s2u(Ps) + ((w*16 + lr)*72 + lc)*2;
    uint32_t qf[4][4];
    #pragma unroll
    for (int ks = 0; ks < 4; ks++) ldm4(qf[ks], qbase + ks*32);
    __syncthreads();

    float m0 = -INFINITY, m1 = -INFINITY, l0 = 0.f, l1 = 0.f;
    float oacc[8][4];
    #pragma unroll
    for (int i=0;i<8;i++)
        #pragma unroll
        for (int j=0;j<4;j++) oacc[i][j] = 0.f;

    uint32_t pabase = s2u(Ps) + ((w*16 + lr)*136 + lc)*2;
    __half* prow = Ps + (size_t)(w*16 + (lane>>2))*136 + (lane&3)*2;

    for (int kt = 0; kt < 8; kt++) {
        int buf = kt & 1;
        cp_wait0();
        __syncthreads();
        if (kt + 1 < 8) stageKV(kt+1, buf ^ 1);
        cp_commit();

        float sacc[16][4];
        #pragma unroll
        for (int i=0;i<16;i++)
            #pragma unroll
            for (int j=0;j<4;j++) sacc[i][j] = 0.f;
        uint32_t kbase = s2u(buf ? Ks1 : Ks0) + (lr*72 + lc)*2;
        #pragma unroll
        for (int ks = 0; ks < 4; ks++) {
            #pragma unroll
            for (int np = 0; np < 8; np++) {
                uint32_t r[4];
                ldm4(r, kbase + (np*16*72 + ks*16)*2);
                mma16(sacc[2*np  ], qf[ks], r[0], r[2]);
                mma16(sacc[2*np+1], qf[ks], r[1], r[3]);
            }
        }

        float t0 = -INFINITY, t1 = -INFINITY;
        #pragma unroll
        for (int nt = 0; nt < 16; nt++) {
            t0 = fmaxf(t0, fmaxf(sacc[nt][0], sacc[nt][1]));
            t1 = fmaxf(t1, fmaxf(sacc[nt][2], sacc[nt][3]));
        }
        t0 = fmaxf(t0, __shfl_xor_sync(0xffffffffu, t0, 1));
        t0 = fmaxf(t0, __shfl_xor_sync(0xffffffffu, t0, 2));
        t1 = fmaxf(t1, __shfl_xor_sync(0xffffffffu, t1, 1));
        t1 = fmaxf(t1, __shfl_xor_sync(0xffffffffu, t1, 2));
        float mn0 = fmaxf(m0, t0), mn1 = fmaxf(m1, t1);
        float sc0 = __expf(m0 - mn0), sc1 = __expf(m1 - mn1);
        float s0 = 0.f, s1 = 0.f;
        #pragma unroll
        for (int nt = 0; nt < 16; nt++) {
            sacc[nt][0] = __expf(sacc[nt][0] - mn0);
            sacc[nt][1] = __expf(sacc[nt][1] - mn0);
            sacc[nt][2] = __expf(sacc[nt][2] - mn1);
            sacc[nt][3] = __expf(sacc[nt][3] - mn1);
            s0 += sacc[nt][0] + sacc[nt][1];
            s1 += sacc[nt][2] + sacc[nt][3];
        }
        s0 += __shfl_xor_sync(0xffffffffu, s0, 1);
        s0 += __shfl_xor_sync(0xffffffffu, s0, 2);
        s1 += __shfl_xor_sync(0xffffffffu, s1, 1);
        s1 += __shfl_xor_sync(0xffffffffu, s1, 2);
        l0 = l0*sc0 + s0; l1 = l1*sc1 + s1;
        m0 = mn0; m1 = mn1;
        #pragma unroll
        for (int nt = 0; nt < 8; nt++) {
            oacc[nt][0] *= sc0; oacc[nt][1] *= sc0;
            oacc[nt][2] *= sc1; oacc[nt][3] *= sc1;
        }

        #pragma unroll
        for (int nt = 0; nt < 16; nt++) {
            *(__half2*)(prow + nt*8)          = __floats2half2_rn(sacc[nt][0], sacc[nt][1]);
            *(__half2*)(prow + 8*136 + nt*8)  = __floats2half2_rn(sacc[nt][2], sacc[nt][3]);
        }
        __syncwarp();

        uint32_t vbase = s2u(buf ? Vs1 : Vs0) + (lr*72 + lc)*2;
        #pragma unroll
        for (int k2 = 0; k2 < 8; k2++) {
            uint32_t pf[4];
            ldm4(pf, pabase + k2*32);
            #pragma unroll
            for (int hp = 0; hp < 4; hp++) {
                uint32_t vt[4];
                ldm4t(vt, vbase + (k2*16*72 + hp*16)*2);
                mma16(oacc[2*hp  ], pf, vt[0], vt[1]);
                mma16(oacc[2*hp+1], pf, vt[2], vt[3]);
            }
        }
    }

    float i0 = 1.f / l0, i1 = 1.f / l1;
    int r0 = q0 + w*16 + (lane >> 2);
    __half* Op = O + (size_t)(b*Sz + r0)*1024 + h*64 + (lane&3)*2;
    #pragma unroll
    for (int nt = 0; nt < 8; nt++) {
        *(__half2*)(Op + nt*8)          = __floats2half2_rn(oacc[nt][0]*i0, oacc[nt][1]*i0);
        *(__half2*)(Op + 8*1024 + nt*8) = __floats2half2_rn(oacc[nt][2]*i1, oacc[nt][3]*i1);
    }
}

// ---------------------------------------------------------------------------
// Gate head + softmax + top-2 + renorm + routing. One warp per token.
// ---------------------------------------------------------------------------
__global__ __launch_bounds__(256) void gate_route_kernel(
    const float* __restrict__ GH, const float* __restrict__ gw2,
    const float* __restrict__ gb2,
    float* __restrict__ wout, int* __restrict__ cnt, int* __restrict__ elist)
{
    int warp = threadIdx.x >> 5;
    int lane = threadIdx.x & 31;
    int t = blockIdx.x * 8 + warp;
    if (t >= Tz) return;

    float logit[Ez];
    #pragma unroll
    for (int o = 0; o < Ez; o++) {
        float s = 0.f;
        for (int i = lane; i < GHz; i += 32)
            s += GH[(size_t)t * GHz + i] * gw2[(size_t)i * Ez + o];
        #pragma unroll
        for (int off = 16; off; off >>= 1)
            s += __shfl_xor_sync(0xffffffffu, s, off);
        logit[o] = s + gb2[o];
    }
    if (lane == 0) {
        float m = logit[0];
        #pragma unroll
        for (int o = 1; o < Ez; o++) m = fmaxf(m, logit[o]);
        float w[Ez], sum = 0.f;
        #pragma unroll
        for (int o = 0; o < Ez; o++) { w[o] = expf(logit[o] - m); sum += w[o]; }
        float invs = 1.f / sum;
        #pragma unroll
        for (int o = 0; o < Ez; o++) w[o] *= invs;
        int i0 = 0; float v0 = w[0];
        #pragma unroll
        for (int o = 1; o < Ez; o++) if (w[o] > v0) { v0 = w[o]; i0 = o; }
        int i1 = -1; float v1 = -1.f;
        #pragma unroll
        for (int o = 0; o < Ez; o++)
            if (o != i0 && w[o] > v1) { v1 = w[o]; i1 = o; }
        float e1 = expf(v1 - v0);
        float den = 1.f + e1;
        wout[2*t + 0] = 1.f / den;
        wout[2*t + 1] = e1 / den;
        int p0 = atomicAdd(&cnt[i0], 1);
        elist[i0 * Tz + p0] = 2*t + 0;
        int p1 = atomicAdd(&cnt[i1], 1);
        elist[i1 * Tz + p1] = 2*t + 1;
    }
}

__global__ void zero_counts_kernel(int* cnt)
{
    if (threadIdx.x < Ez) cnt[threadIdx.x] = 0;
}

// ---------------------------------------------------------------------------
// Final combine: out = x1 + w0*eo[2t] + w1*eo[2t+1]  (eo fp16)
// ---------------------------------------------------------------------------
__global__ __launch_bounds__(256) void combine_kernel(
    const float* __restrict__ x1, const __half* __restrict__ eo,
    const float* __restrict__ w, float* __restrict__ out)
{
    int idx = blockIdx.x * 256 + threadIdx.x;
    int t = idx >> 8;
    int c = idx & 255;
    float w0 = w[2*t], w1 = w[2*t + 1];
    float4 a  = ((const float4*)x1)[idx];
    uint2 u0 = ((const uint2*)(eo + (size_t)(2*t)     * Dz))[c];
    uint2 u1 = ((const uint2*)(eo + (size_t)(2*t + 1) * Dz))[c];
    float2 e0a = __half22float2(*(__half2*)&u0.x);
    float2 e0b = __half22float2(*(__half2*)&u0.y);
    float2 e1a = __half22float2(*(__half2*)&u1.x);
    float2 e1b = __half22float2(*(__half2*)&u1.y);
    float4 r;
    r.x = a.x + w0 * e0a.x + w1 * e1a.x;
    r.y = a.y + w0 * e0a.y + w1 * e1a.y;
    r.z = a.z + w0 * e0b.x + w1 * e1b.x;
    r.w = a.w + w0 * e0b.y + w1 * e1b.y;
    ((float4*)out)[idx] = r;
}

// ---------------------------------------------------------------------------
// Host launch
// ---------------------------------------------------------------------------
extern "C" void kernel_launch(void* const* d_in, const int* in_sizes, int n_in,
                              void* d_out, int out_size)
{
    const float* x    = (const float*)d_in[0];
    const float* wq   = (const float*)d_in[1];
    const float* bq   = (const float*)d_in[2];
    const float* wk   = (const float*)d_in[3];
    const float* bk   = (const float*)d_in[4];
    const float* wv   = (const float*)d_in[5];
    const float* bv   = (const float*)d_in[6];
    const float* wo   = (const float*)d_in[7];
    const float* bo   = (const float*)d_in[8];
    const float* ln1g = (const float*)d_in[9];
    const float* ln1b = (const float*)d_in[10];
    const float* ln2g = (const float*)d_in[11];
    const float* ln2b = (const float*)d_in[12];
    const float* gw1  = (const float*)d_in[13];
    const float* gb1  = (const float*)d_in[14];
    const float* gw2  = (const float*)d_in[15];
    const float* gb2  = (const float*)d_in[16];
    const float* ew1  = (const float*)d_in[17];
    const float* eb1  = (const float*)d_in[18];
    const float* ew2  = (const float*)d_in[19];
    const float* eb2  = (const float*)d_in[20];
    float* out = (float*)d_out;

    __half *h1h, *qkvh, *aoh, *h2h, *hidh, *eo;
    __half *wqkvh, *woh, *ew1h, *ew2h;
    float *x1, *h2, *gh, *w, *qkvb;
    int *cnt, *elist;
    cudaGetSymbolAddress((void**)&h1h,  g_h1h);
    cudaGetSymbolAddress((void**)&qkvh, g_qkvh);
    cudaGetSymbolAddress((void**)&aoh,  g_aoh);
    cudaGetSymbolAddress((void**)&x1,   g_x1);
    cudaGetSymbolAddress((void**)&h2,   g_h2);
    cudaGetSymbolAddress((void**)&h2h,  g_h2h);
    cudaGetSymbolAddress((void**)&gh,   g_gh);
    cudaGetSymbolAddress((void**)&w,    g_w);
    cudaGetSymbolAddress((void**)&hidh, g_hidh);
    cudaGetSymbolAddress((void**)&eo,   g_eo);
    cudaGetSymbolAddress((void**)&cnt,  g_cnt);
    cudaGetSymbolAddress((void**)&elist,g_elist);
    cudaGetSymbolAddress((void**)&wqkvh,g_wqkvh);
    cudaGetSymbolAddress((void**)&woh,  g_woh);
    cudaGetSymbolAddress((void**)&ew1h, g_ew1h);
    cudaGetSymbolAddress((void**)&ew2h, g_ew2h);
    cudaGetSymbolAddress((void**)&qkvb, g_qkvb);

    cudaFuncSetAttribute(gemm_hc<0,false,false,true>, cudaFuncAttributeMaxDynamicSharedMemorySize, GEMMH_SMEM);
    cudaFuncSetAttribute(gemm_hc<0,false,true,false>, cudaFuncAttributeMaxDynamicSharedMemorySize, GEMMH_SMEM);
    cudaFuncSetAttribute(gemm_hc<2,true,false,true>,  cudaFuncAttributeMaxDynamicSharedMemorySize, GEMMH_SMEM);
    cudaFuncSetAttribute(gemm_hc<0,true,false,true>,  cudaFuncAttributeMaxDynamicSharedMemorySize, GEMMH_SMEM);
    cudaFuncSetAttribute(gemm_gate, cudaFuncAttributeMaxDynamicSharedMemorySize, GEMM_SMEM);
    cudaFuncSetAttribute(fa_h, cudaFuncAttributeMaxDynamicSharedMemorySize, FA_SMEM);

    // --- weight convert pre-pass (qkv packed into [K][2560]; Q pre-scaled) ---
    cvt_pack<<<(Dz*512/4 + 255)/256, 256>>>(wq, wqkvh,        512,  QKVN, Dz*512/4,  0.125f);
    cvt_pack<<<(Dz*Dz/4 + 255)/256, 256>>>(wk, wqkvh + 512,   Dz,   QKVN, Dz*Dz/4,   1.f);
    cvt_pack<<<(Dz*Dz/4 + 255)/256, 256>>>(wv, wqkvh + 1536,  Dz,   QKVN, Dz*Dz/4,   1.f);
    cvt_pack<<<(Dz*Dz/4 + 255)/256, 256>>>(wo, woh,           Dz,   Dz,   Dz*Dz/4,   1.f);
    cvt_pack<<<((int)((size_t)Ez*Dz*EDz/4) + 255)/256, 256>>>(ew1, ew1h, EDz, EDz, (int)((size_t)Ez*Dz*EDz/4), 1.f);
    cvt_pack<<<((int)((size_t)Ez*EDz*Dz/4) + 255)/256, 256>>>(ew2, ew2h, Dz,  Dz,  (int)((size_t)Ez*EDz*Dz/4), 1.f);
    pack_bias<<<10, 256>>>(bq, bk, bv, qkvb);

    zero_counts_kernel<<<1, 32>>>(cnt);
    ln_kernel<false><<<Tz, 256>>>(x, ln1g, ln1b, nullptr, h1h);

    // Fused QKV projection (fp16), Q pre-scaled via weights/bias
    gemm_hc<0,false,false,true><<<dim3(QKVN/128, 32, 1), 256, GEMMH_SMEM>>>(
        h1h, wqkvh, qkvb, qkvh, Tz, QKVN, Dz, nullptr, nullptr, nullptr, 0);

    fa_h<<<dim3(Sz/128, Bz*Hh), 256, FA_SMEM>>>(qkvh, aoh);

    // Output projection + residual -> x1 fp32
    gemm_hc<0,false,true,false><<<dim3(8, 32, 1), 256, GEMMH_SMEM>>>(
        aoh, woh, bo, x1, Tz, Dz, Dz, x, nullptr, nullptr, 0);

    ln_kernel<true><<<Tz, 256>>>(x1, ln2g, ln2b, h2, h2h);

    // gate layer 1: split-tf32 near-fp32 (protects top-2 selection)
    gemm_gate<<<dim3(4, 32, 1), 256, GEMM_SMEM>>>(h2, gw1, gb1, gh, Tz, GHz, Dz);

    gate_route_kernel<<<Tz/8, 256>>>(gh, gw2, gb2, w, cnt, elist);

    // Expert FFN (fp16, gathered)
    gemm_hc<2,true,false,true><<<dim3(EDz/128, Tz/128, Ez), 256, GEMMH_SMEM>>>(
        h2h, ew1h, eb1, hidh, Tz, EDz, Dz, nullptr, elist, cnt, 1);
    gemm_hc<0,true,false,true><<<dim3(Dz/128, Tz/128, Ez), 256, GEMMH_SMEM>>>(
        hidh, ew2h, eb2, eo, Tz, Dz, EDz, nullptr, elist, cnt, 0);

    combine_kernel<<<(Tz*Dz/4)/256, 256>>>(x1, eo, w, out);
}

// round 9
// speedup vs baseline: 7.6848x; 1.0506x over previous
#include <cuda_runtime.h>
#include <cuda_fp16.h>
#include <math.h>
#include <stdint.h>

// ---------------------------------------------------------------------------
// Problem constants
// ---------------------------------------------------------------------------
#define Bz   4
#define Sz   1024
#define Dz   1024
#define Hh   16
#define Gg   8
#define HDz  64
#define Ez   8
#define EDz  2048
#define GHz  512
#define Tz   (Bz*Sz)          // 4096 tokens
#define QKVN 2560             // packed q(512) | k(1024) | v(1024)

// ---------------------------------------------------------------------------
// Scratch (static device memory)
// ---------------------------------------------------------------------------
__device__ __half g_h1h [Tz*Dz];
__device__ __half g_qkvh[(size_t)Tz*QKVN];
__device__ __half g_aoh [Tz*Dz];
__device__ float  g_x1  [Tz*Dz];
__device__ __half g_h2h [Tz*Dz];       // LN2 out, fp16 hi
__device__ __half g_h2l [Tz*Dz];       // LN2 out, fp16 lo (residual)
__device__ float  g_gh  [Tz*GHz];
__device__ float  g_w   [Tz*2];
__device__ int    g_cnt [Ez];
__device__ int    g_elist[Ez*Tz];
__device__ __half g_hidh[(size_t)Tz*2*EDz];
__device__ __half g_eo  [(size_t)Tz*2*Dz];
// fp16 weights ([K][N] row-major; qkv packed) + packed qkv bias
__device__ __half g_wqkvh[(size_t)Dz*QKVN];
__device__ __half g_woh  [(size_t)Dz*Dz];
__device__ __half g_ew1h [(size_t)Ez*Dz*EDz];
__device__ __half g_ew2h [(size_t)Ez*EDz*Dz];
__device__ __half g_gw1h [(size_t)Dz*GHz];   // gate w1 hi
__device__ __half g_gw1l [(size_t)Dz*GHz];   // gate w1 lo
__device__ float  g_qkvb [QKVN];

// ---------------------------------------------------------------------------
// Helpers
// ---------------------------------------------------------------------------
__device__ __forceinline__ uint32_t s2u(const void* p){
    return (uint32_t)__cvta_generic_to_shared(p);
}
__device__ __forceinline__ void cpa16(uint32_t d, const void* s, bool v){
    asm volatile("cp.async.cg.shared.global [%0], [%1], 16, %2;\n"
                 :: "r"(d), "l"(s), "r"(v ? 16 : 0));
}
__device__ __forceinline__ void cp_commit(){ asm volatile("cp.async.commit_group;\n"); }
__device__ __forceinline__ void cp_wait0(){ asm volatile("cp.async.wait_group 0;\n"); }
__device__ __forceinline__ void cp_wait1(){ asm volatile("cp.async.wait_group 1;\n"); }
__device__ __forceinline__ void mma16(float* c, const uint32_t* a, uint32_t b0, uint32_t b1){
    asm volatile("mma.sync.aligned.m16n8k16.row.col.f32.f16.f16.f32 "
        "{%0,%1,%2,%3},{%4,%5,%6,%7},{%8,%9},{%0,%1,%2,%3};\n"
        : "+f"(c[0]),"+f"(c[1]),"+f"(c[2]),"+f"(c[3])
        : "r"(a[0]),"r"(a[1]),"r"(a[2]),"r"(a[3]),"r"(b0),"r"(b1));
}
__device__ __forceinline__ void ldm4(uint32_t* r, uint32_t addr){
    asm volatile("ldmatrix.sync.aligned.m8n8.x4.shared.b16 {%0,%1,%2,%3}, [%4];"
        : "=r"(r[0]),"=r"(r[1]),"=r"(r[2]),"=r"(r[3]) : "r"(addr));
}
__device__ __forceinline__ void ldm4t(uint32_t* r, uint32_t addr){
    asm volatile("ldmatrix.sync.aligned.m8n8.x4.trans.shared.b16 {%0,%1,%2,%3}, [%4];"
        : "=r"(r[0]),"=r"(r[1]),"=r"(r[2]),"=r"(r[3]) : "r"(addr));
}

// ---------------------------------------------------------------------------
// fp32 -> fp16 convert with output stride (for packed weight layouts).
// ---------------------------------------------------------------------------
__global__ __launch_bounds__(256) void cvt_pack(
    const float* __restrict__ in, __half* __restrict__ out,
    int N, int ldout, int total4, float scale)
{
    int i = blockIdx.x * 256 + threadIdx.x;
    if (i >= total4) return;
    int row = i / (N >> 2);
    int c4  = (i - row * (N >> 2)) * 4;
    float4 a = *(const float4*)(in + (size_t)row * N + c4);
    __half2 h0 = __floats2half2_rn(a.x * scale, a.y * scale);
    __half2 h1 = __floats2half2_rn(a.z * scale, a.w * scale);
    uint2 u; u.x = *(uint32_t*)&h0; u.y = *(uint32_t*)&h1;
    *(uint2*)(out + (size_t)row * ldout + c4) = u;
}

// fp32 -> fp16 hi/lo split convert (contiguous)
__global__ __launch_bounds__(256) void cvt_split(
    const float* __restrict__ in, __half* __restrict__ hi,
    __half* __restrict__ lo, int total4)
{
    int i = blockIdx.x * 256 + threadIdx.x;
    if (i >= total4) return;
    float4 a = ((const float4*)in)[i];
    __half hx = __float2half_rn(a.x), hy = __float2half_rn(a.y);
    __half hz = __float2half_rn(a.z), hw = __float2half_rn(a.w);
    __half lx = __float2half_rn(a.x - __half2float(hx));
    __half ly = __float2half_rn(a.y - __half2float(hy));
    __half lz = __float2half_rn(a.z - __half2float(hz));
    __half lw = __float2half_rn(a.w - __half2float(hw));
    __half2 H0; H0.x = hx; H0.y = hy;
    __half2 H1; H1.x = hz; H1.y = hw;
    __half2 L0; L0.x = lx; L0.y = ly;
    __half2 L1; L1.x = lz; L1.y = lw;
    uint2 uh; uh.x = *(uint32_t*)&H0; uh.y = *(uint32_t*)&H1;
    uint2 ul; ul.x = *(uint32_t*)&L0; ul.y = *(uint32_t*)&L1;
    ((uint2*)hi)[i] = uh;
    ((uint2*)lo)[i] = ul;
}

__global__ void pack_bias(const float* __restrict__ bq, const float* __restrict__ bk,
                          const float* __restrict__ bv, float* __restrict__ o)
{
    int i = blockIdx.x * 256 + threadIdx.x;
    if (i < 512)        o[i] = bq[i] * 0.125f;
    else if (i < 1536)  o[i] = bk[i - 512];
    else if (i < QKVN)  o[i] = bv[i - 1536];
}

// ---------------------------------------------------------------------------
// LayerNorm: one block per token row of 1024.
// Writes fp16 hi; SPLIT mode additionally writes fp16 lo (x - hi).
// ---------------------------------------------------------------------------
template<bool SPLIT>
__global__ __launch_bounds__(256) void ln_kernel(
    const float* __restrict__ X, const float* __restrict__ g,
    const float* __restrict__ b, __half* __restrict__ O16, __half* __restrict__ OLO)
{
    int t = blockIdx.x;
    int tid = threadIdx.x;
    const float4* x4 = (const float4*)(X + (size_t)t * Dz);
    float4 xv = x4[tid];
    float s  = xv.x + xv.y + xv.z + xv.w;
    float ss = xv.x*xv.x + xv.y*xv.y + xv.z*xv.z + xv.w*xv.w;
    #pragma unroll
    for (int off = 16; off; off >>= 1) {
        s  += __shfl_xor_sync(0xffffffffu, s,  off);
        ss += __shfl_xor_sync(0xffffffffu, ss, off);
    }
    __shared__ float sh_s[8], sh_ss[8];
    if ((tid & 31) == 0) { sh_s[tid >> 5] = s; sh_ss[tid >> 5] = ss; }
    __syncthreads();
    if (tid < 32) {
        float a = (tid < 8) ? sh_s[tid]  : 0.f;
        float c = (tid < 8) ? sh_ss[tid] : 0.f;
        #pragma unroll
        for (int off = 4; off; off >>= 1) {
            a += __shfl_xor_sync(0xffffffffu, a, off);
            c += __shfl_xor_sync(0xffffffffu, c, off);
        }
        if (tid == 0) { sh_s[0] = a; sh_ss[0] = c; }
    }
    __syncthreads();
    float mu  = sh_s[0]  * (1.f / Dz);
    float var = sh_ss[0] * (1.f / Dz) - mu * mu;
    float inv = rsqrtf(var + 1e-5f);
    float4 gv = ((const float4*)g)[tid];
    float4 bv = ((const float4*)b)[tid];
    float4 o;
    o.x = (xv.x - mu) * inv * gv.x + bv.x;
    o.y = (xv.y - mu) * inv * gv.y + bv.y;
    o.z = (xv.z - mu) * inv * gv.z + bv.z;
    o.w = (xv.w - mu) * inv * gv.w + bv.w;
    __half hx = __float2half_rn(o.x), hy = __float2half_rn(o.y);
    __half hz = __float2half_rn(o.z), hw = __float2half_rn(o.w);
    __half2 p0; p0.x = hx; p0.y = hy;
    __half2 p1; p1.x = hz; p1.y = hw;
    uint2 u; u.x = *(uint32_t*)&p0; u.y = *(uint32_t*)&p1;
    ((uint2*)(O16 + (size_t)t * Dz))[tid] = u;
    if (SPLIT) {
        __half2 l0 = __floats2half2_rn(o.x - __half2float(hx), o.y - __half2float(hy));
        __half2 l1 = __floats2half2_rn(o.z - __half2float(hz), o.w - __half2float(hw));
        uint2 ul; ul.x = *(uint32_t*)&l0; ul.y = *(uint32_t*)&l1;
        ((uint2*)(OLO + (size_t)t * Dz))[tid] = ul;
    }
}

// ---------------------------------------------------------------------------
// fp16 tensor-core GEMM: C[M,N] = act(A @ B + bias)(+resid), optional gather.
// BM=128, BN=128, BK=64 (halves), 256 threads, 8 warps (2M x 4N), warp 64x32.
// A fp16 [M,K] (ldmatrix), B fp16 [K,N] (ldmatrix.trans). 3-stage cp.async.
// ACT: 0 none, 1 relu, 2 gelu. OUTH: fp16 output.
// ---------------------------------------------------------------------------
#define GEMMH_SMEM (3*128*72*2 + 3*64*136*2)
template<int ACT, bool GATHER, bool RESID, bool OUTH>
__global__ void __launch_bounds__(256,2) gemm_hc(
    const __half* __restrict__ A, const __half* __restrict__ B,
    const float* __restrict__ bias, void* __restrict__ Cv,
    int M, int N, int K,
    const float* __restrict__ resid,
    const int* __restrict__ elist, const int* __restrict__ cnt, int ashift)
{
    extern __shared__ __half smh[];
    __half* As = smh;                  // [3][128][72]
    __half* Bs = smh + 3*128*72;       // [3][64][136]

    int e = blockIdx.z;
    const __half* Bp = B + (size_t)e * K * N;
    const float*  bp = bias + (size_t)e * N;
    int mcount = GATHER ? cnt[e] : M;
    int m0 = blockIdx.y * 128;
    if (m0 >= mcount) return;
    int n0 = blockIdx.x * 128;
    const int* lst = GATHER ? (elist + e * Tz) : (const int*)nullptr;

    int tid = threadIdx.x;
    int lane = tid & 31, wid = tid >> 5;
    int warpM = wid >> 2, warpN = wid & 3;

    int aq = (tid & 7) * 8;
    const __half* aptr[4];
    bool aval[4];
    uint32_t adst[4];
    #pragma unroll
    for (int i = 0; i < 4; i++) {
        int r = (tid >> 3) + 32 * i;
        int m = m0 + r;
        bool v = (m < mcount);
        size_t rowg;
        if (GATHER) rowg = v ? (size_t)(lst[m] >> ashift) : 0;
        else        rowg = v ? (size_t)m : 0;
        aptr[i] = A + rowg * (size_t)K + aq;
        aval[i] = v;
        adst[i] = s2u(&As[r * 72 + aq]);
    }
    int brow = tid >> 2, bq = (tid & 3) * 32;
    const __half* bptr = Bp + (size_t)brow * N + n0 + bq;
    uint32_t bdst = s2u(&Bs[brow * 136 + bq]);
    const uint32_t abuf = 128*72*2, bbuf = 64*136*2;

    uint32_t as_u = s2u(As), bs_u = s2u(Bs);

    float acc[4][4][4];
    #pragma unroll
    for (int i=0;i<4;i++)
        #pragma unroll
        for (int j=0;j<4;j++)
            #pragma unroll
            for (int l=0;l<4;l++) acc[i][j][l] = 0.f;

    int KT = K / 64;

    auto stageTile = [&](int kt2, int buf){
        int k0 = kt2 * 64;
        #pragma unroll
        for (int i=0;i<4;i++) cpa16(adst[i] + buf*abuf, aptr[i] + k0, aval[i]);
        #pragma unroll
        for (int j=0;j<4;j++) cpa16(bdst + buf*bbuf + j*16,
                                    bptr + (size_t)k0*N + j*8, true);
    };

    stageTile(0, 0); cp_commit();
    if (KT > 1) stageTile(1, 1);
    cp_commit();

    int bufc = 0, bufs = 2;
    uint32_t lr = lane & 15, lc = (lane >> 4) * 8;
    for (int kt = 0; kt < KT; kt++) {
        cp_wait1();
        __syncthreads();
        if (kt + 2 < KT) stageTile(kt+2, bufs);
        cp_commit();

        uint32_t abase = as_u + ((uint32_t)bufc*(128*72) + (warpM*64 + lr)*72 + lc)*2;
        uint32_t bbase = bs_u + ((uint32_t)bufc*(64*136) + lr*136 + warpN*32 + lc)*2;
        #pragma unroll
        for (int ks = 0; ks < 4; ks++) {
            uint32_t ah[4][4];
            #pragma unroll
            for (int mt = 0; mt < 4; mt++)
                ldm4(ah[mt], abase + (mt*16*72 + ks*16)*2);
            uint32_t bt[2][4];
            #pragma unroll
            for (int pr = 0; pr < 2; pr++)
                ldm4t(bt[pr], bbase + (ks*16*136 + pr*16)*2);
            #pragma unroll
            for (int mt = 0; mt < 4; mt++) {
                mma16(acc[mt][0], ah[mt], bt[0][0], bt[0][1]);
                mma16(acc[mt][1], ah[mt], bt[0][2], bt[0][3]);
                mma16(acc[mt][2], ah[mt], bt[1][0], bt[1][1]);
                mma16(acc[mt][3], ah[mt], bt[1][2], bt[1][3]);
            }
        }
        __syncthreads();
        bufc = (bufc == 2) ? 0 : bufc + 1;
        bufs = (bufs == 2) ? 0 : bufs + 1;
    }

    float2 bv[4];
    #pragma unroll
    for (int nt = 0; nt < 4; nt++)
        bv[nt] = *(const float2*)(bp + n0 + warpN*32 + (lane&3)*2 + nt*8);

    float*  Cf = (float*)Cv;
    __half* Ch = (__half*)Cv;
    #pragma unroll
    for (int mt = 0; mt < 4; mt++) {
        #pragma unroll
        for (int hf = 0; hf < 2; hf++) {
            int r = m0 + warpM*64 + mt*16 + (lane>>2) + hf*8;
            if (r >= mcount) continue;
            size_t crow = GATHER ? (size_t)lst[r] : (size_t)r;
            int coff = n0 + warpN*32 + (lane&3)*2;
            const float* Rr = RESID ? (resid + crow*(size_t)N + coff) : (const float*)nullptr;
            #pragma unroll
            for (int nt = 0; nt < 4; nt++) {
                float v0 = acc[mt][nt][hf*2+0] + bv[nt].x;
                float v1 = acc[mt][nt][hf*2+1] + bv[nt].y;
                if (ACT == 1) { v0 = fmaxf(v0, 0.f); v1 = fmaxf(v1, 0.f); }
                if (ACT == 2) {
                    v0 = 0.5f*v0*(1.f + erff(v0*0.70710678118654752f));
                    v1 = 0.5f*v1*(1.f + erff(v1*0.70710678118654752f));
                }
                if (RESID) { v0 += Rr[nt*8]; v1 += Rr[nt*8+1]; }
                if (OUTH) {
                    __half2 h = __floats2half2_rn(v0, v1);
                    *(__half2*)(Ch + crow*(size_t)N + coff + nt*8) = h;
                } else {
                    float2 o; o.x = v0; o.y = v1;
                    *(float2*)(Cf + crow*(size_t)N + coff + nt*8) = o;
                }
            }
        }
    }
}

// ---------------------------------------------------------------------------
// Split-fp16 gate GEMM (near-fp32): gh = relu((Ah+Al)@(Bh+Bl) + bias)
//   = Ah@Bh + Al@Bh + Ah@Bl (Al@Bl dropped, ~2^-22 relative).
// BM=128, BN=128, BK=32, 256 threads, 8 warps (2M x 4N), warp 64x32.
// 2-stage cp.async. smem: Ah/Al[2][128][40] + Bh/Bl[2][32][136].
// ---------------------------------------------------------------------------
#define GATE_SMEM (2*2*128*40*2 + 2*2*32*136*2)
__global__ void __launch_bounds__(256,2) gemm_gate16(
    const __half* __restrict__ Ah, const __half* __restrict__ Al,
    const __half* __restrict__ Bh, const __half* __restrict__ Bl,
    const float* __restrict__ bias, float* __restrict__ C,
    int M, int N, int K)
{
    extern __shared__ __half smh[];
    __half* Ahs = smh;                        // [2][128][40]
    __half* Als = Ahs + 2*128*40;             // [2][128][40]
    __half* Bhs = Als + 2*128*40;             // [2][32][136]
    __half* Bls = Bhs + 2*32*136;             // [2][32][136]

    int m0 = blockIdx.y * 128;
    int n0 = blockIdx.x * 128;
    int tid = threadIdx.x;
    int lane = tid & 31, wid = tid >> 5;
    int warpM = wid >> 2, warpN = wid & 3;

    // A staging: row = tid>>1 (128), col halves (tid&1)*16 (+8)
    int arow = tid >> 1, acol = (tid & 1) * 16;
    const __half* ahp = Ah + (size_t)(m0 + arow) * K + acol;
    const __half* alp = Al + (size_t)(m0 + arow) * K + acol;
    uint32_t ahd = s2u(&Ahs[arow * 40 + acol]);
    uint32_t ald = s2u(&Als[arow * 40 + acol]);
    // B staging: row = tid>>3 (32), col halves (tid&7)*16 (+8)
    int brow = tid >> 3, bcol = (tid & 7) * 16;
    const __half* bhp = Bh + (size_t)brow * N + n0 + bcol;
    const __half* blp = Bl + (size_t)brow * N + n0 + bcol;
    uint32_t bhd = s2u(&Bhs[brow * 136 + bcol]);
    uint32_t bld = s2u(&Bls[brow * 136 + bcol]);

    const uint32_t abuf = 128*40*2, bbuf = 32*136*2;

    auto stage = [&](int kt, int buf){
        int k0 = kt * 32;
        cpa16(ahd + buf*abuf,      ahp + k0, true);
        cpa16(ahd + buf*abuf + 16, ahp + k0 + 8, true);
        cpa16(ald + buf*abuf,      alp + k0, true);
        cpa16(ald + buf*abuf + 16, alp + k0 + 8, true);
        cpa16(bhd + buf*bbuf,      bhp + (size_t)k0*N, true);
        cpa16(bhd + buf*bbuf + 16, bhp + (size_t)k0*N + 8, true);
        cpa16(bld + buf*bbuf,      blp + (size_t)k0*N, true);
        cpa16(bld + buf*bbuf + 16, blp + (size_t)k0*N + 8, true);
    };

    uint32_t ahs_u = s2u(Ahs), als_u = s2u(Als);
    uint32_t bhs_u = s2u(Bhs), bls_u = s2u(Bls);

    float acc[4][4][4];
    #pragma unroll
    for (int i=0;i<4;i++)
        #pragma unroll
        for (int j=0;j<4;j++)
            #pragma unroll
            for (int l=0;l<4;l++) acc[i][j][l] = 0.f;

    int KT = K / 32;
    stage(0, 0); cp_commit();

    uint32_t lr = lane & 15, lc = (lane >> 4) * 8;
    for (int kt = 0; kt < KT; kt++) {
        int buf = kt & 1;
        cp_wait0();
        __syncthreads();
        if (kt + 1 < KT) { stage(kt+1, buf ^ 1); }
        cp_commit();

        uint32_t aoff = ((uint32_t)buf*(128*40) + (warpM*64 + lr)*40 + lc)*2;
        uint32_t boff = ((uint32_t)buf*(32*136) + lr*136 + warpN*32 + lc)*2;
        #pragma unroll
        for (int ks = 0; ks < 2; ks++) {
            uint32_t ah[4][4], al[4][4];
            #pragma unroll
            for (int mt = 0; mt < 4; mt++) {
                ldm4(ah[mt], ahs_u + aoff + (mt*16*40 + ks*16)*2);
                ldm4(al[mt], als_u + aoff + (mt*16*40 + ks*16)*2);
            }
            uint32_t bth[2][4], btl[2][4];
            #pragma unroll
            for (int pr = 0; pr < 2; pr++) {
                ldm4t(bth[pr], bhs_u + boff + (ks*16*136 + pr*16)*2);
                ldm4t(btl[pr], bls_u + boff + (ks*16*136 + pr*16)*2);
            }
            #pragma unroll
            for (int mt = 0; mt < 4; mt++) {
                mma16(acc[mt][0], ah[mt], bth[0][0], bth[0][1]);
                mma16(acc[mt][1], ah[mt], bth[0][2], bth[0][3]);
                mma16(acc[mt][2], ah[mt], bth[1][0], bth[1][1]);
                mma16(acc[mt][3], ah[mt], bth[1][2], bth[1][3]);
                mma16(acc[mt][0], al[mt], bth[0][0], bth[0][1]);
                mma16(acc[mt][1], al[mt], bth[0][2], bth[0][3]);
                mma16(acc[mt][2], al[mt], bth[1][0], bth[1][1]);
                mma16(acc[mt][3], al[mt], bth[1][2], bth[1][3]);
                mma16(acc[mt][0], ah[mt], btl[0][0], btl[0][1]);
                mma16(acc[mt][1], ah[mt], btl[0][2], btl[0][3]);
                mma16(acc[mt][2], ah[mt], btl[1][0], btl[1][1]);
                mma16(acc[mt][3], ah[mt], btl[1][2], btl[1][3]);
            }
        }
        __syncthreads();
    }

    float2 bv[4];
    #pragma unroll
    for (int nt = 0; nt < 4; nt++)
        bv[nt] = *(const float2*)(bias + n0 + warpN*32 + (lane&3)*2 + nt*8);

    #pragma unroll
    for (int mt = 0; mt < 4; mt++)
        #pragma unroll
        for (int hf = 0; hf < 2; hf++) {
            int r = m0 + warpM*64 + mt*16 + (lane>>2) + hf*8;
            float* Cr = C + (size_t)r*N + n0 + warpN*32 + (lane&3)*2;
            #pragma unroll
            for (int nt = 0; nt < 4; nt++) {
                float v0 = fmaxf(acc[mt][nt][hf*2+0] + bv[nt].x, 0.f);
                float v1 = fmaxf(acc[mt][nt][hf*2+1] + bv[nt].y, 0.f);
                float2 o; o.x = v0; o.y = v1;
                *(float2*)(Cr + nt*8) = o;
            }
        }
}

// ---------------------------------------------------------------------------
// Fused flash attention, fp16 mma.sync, online softmax (fp32 stats).
// ---------------------------------------------------------------------------
#define FA_SMEM (128*136*2 + 4*128*72*2)
__global__ void __launch_bounds__(256,2) fa_h(
    const __half* __restrict__ QKV, __half* __restrict__ O)
{
    extern __shared__ __half smh[];
    __half* Ps  = smh;                     // [128][136]; alias Qs [128][72]
    __half* Ks0 = smh + 128*136;
    __half* Ks1 = Ks0 + 128*72;
    __half* Vs0 = Ks1 + 128*72;
    __half* Vs1 = Vs0 + 128*72;

    int bh = blockIdx.y, b = bh >> 4, h = bh & 15, g = h >> 1;
    int q0 = blockIdx.x * 128;
    int tid = threadIdx.x, lane = tid & 31, w = tid >> 5;

    const __half* Qb = QKV + (size_t)(b*Sz + q0) * QKVN + g*64;
    {
        int row = tid >> 1;
        #pragma unroll
        for (int j = 0; j < 4; j++) {
            int c = (tid & 1) + 2*j;
            cpa16(s2u(Ps + row*72 + c*8), Qb + (size_t)row*QKVN + c*8, true);
        }
    }
    cp_commit();

    const __half* Kb = QKV + (size_t)(b*Sz)*QKVN + 512 + h*64;
    const __half* Vb = QKV + (size_t)(b*Sz)*QKVN + 1536 + h*64;

    auto stageKV = [&](int kt, int buf){
        int row = tid >> 1;
        __half* Kd = (buf ? Ks1 : Ks0) + row*72;
        __half* Vd = (buf ? Vs1 : Vs0) + row*72;
        const __half* kp = Kb + (size_t)(kt*128 + row)*QKVN;
        const __half* vp = Vb + (size_t)(kt*128 + row)*QKVN;
        #pragma unroll
        for (int j = 0; j < 4; j++) {
            int c = (tid & 1) + 2*j;
            cpa16(s2u(Kd + c*8), kp + c*8, true);
            cpa16(s2u(Vd + c*8), vp + c*8, true);
        }
    };
    stageKV(0, 0); cp_commit();

    asm volatile("cp.async.wait_group 1;\n");
    __syncthreads();
    uint32_t lr = lane & 15, lc = (lane >> 4) * 8;
    uint32_t qbase = s2u(Ps) + ((w*16 + lr)*72 + lc)*2;
    uint32_t qf[4][4];
    #pragma unroll
    for (int ks = 0; ks < 4; ks++) ldm4(qf[ks], qbase + ks*32);
    __syncthreads();

    float m0 = -INFINITY, m1 = -INFINITY, l0 = 0.f, l1 = 0.f;
    float oacc[8][4];
    #pragma unroll
    for (int i=0;i<8;i++)
        #pragma unroll
        for (int j=0;j<4;j++) oacc[i][j] = 0.f;

    uint32_t pabase = s2u(Ps) + ((w*16 + lr)*136 + lc)*2;
    __half* prow = Ps + (size_t)(w*16 + (lane>>2))*136 + (lane&3)*2;

    for (int kt = 0; kt < 8; kt++) {
        int buf = kt & 1;
        cp_wait0();
        __syncthreads();
        if (kt + 1 < 8) stageKV(kt+1, buf ^ 1);
        cp_commit();

        float sacc[16][4];
        #pragma unroll
        for (int i=0;i<16;i++)
            #pragma unroll
            for (int j=0;j<4;j++) sacc[i][j] = 0.f;
        uint32_t kbase = s2u(buf ? Ks1 : Ks0) + (lr*72 + lc)*2;
        #pragma unroll
        for (int ks = 0; ks < 4; ks++) {
            #pragma unroll
            for (int np = 0; np < 8; np++) {
                uint32_t r[4];
                ldm4(r, kbase + (np*16*72 + ks*16)*2);
                mma16(sacc[2*np  ], qf[ks], r[0], r[2]);
                mma16(sacc[2*np+1], qf[ks], r[1], r[3]);
            }
        }

        float t0 = -INFINITY, t1 = -INFINITY;
        #pragma unroll
        for (int nt = 0; nt < 16; nt++) {
            t0 = fmaxf(t0, fmaxf(sacc[nt][0], sacc[nt][1]));
            t1 = fmaxf(t1, fmaxf(sacc[nt][2], sacc[nt][3]));
        }
        t0 = fmaxf(t0, __shfl_xor_sync(0xffffffffu, t0, 1));
        t0 = fmaxf(t0, __shfl_xor_sync(0xffffffffu, t0, 2));
        t1 = fmaxf(t1, __shfl_xor_sync(0xffffffffu, t1, 1));
        t1 = fmaxf(t1, __shfl_xor_sync(0xffffffffu, t1, 2));
        float mn0 = fmaxf(m0, t0), mn1 = fmaxf(m1, t1);
        float sc0 = __expf(m0 - mn0), sc1 = __expf(m1 - mn1);
        float s0 = 0.f, s1 = 0.f;
        #pragma unroll
        for (int nt = 0; nt < 16; nt++) {
            sacc[nt][0] = __expf(sacc[nt][0] - mn0);
            sacc[nt][1] = __expf(sacc[nt][1] - mn0);
            sacc[nt][2] = __expf(sacc[nt][2] - mn1);
            sacc[nt][3] = __expf(sacc[nt][3] - mn1);
            s0 += sacc[nt][0] + sacc[nt][1];
            s1 += sacc[nt][2] + sacc[nt][3];
        }
        s0 += __shfl_xor_sync(0xffffffffu, s0, 1);
        s0 += __shfl_xor_sync(0xffffffffu, s0, 2);
        s1 += __shfl_xor_sync(0xffffffffu, s1, 1);
        s1 += __shfl_xor_sync(0xffffffffu, s1, 2);
        l0 = l0*sc0 + s0; l1 = l1*sc1 + s1;
        m0 = mn0; m1 = mn1;
        #pragma unroll
        for (int nt = 0; nt < 8; nt++) {
            oacc[nt][0] *= sc0; oacc[nt][1] *= sc0;
            oacc[nt][2] *= sc1; oacc[nt][3] *= sc1;
        }

        #pragma unroll
        for (int nt = 0; nt < 16; nt++) {
            *(__half2*)(prow + nt*8)          = __floats2half2_rn(sacc[nt][0], sacc[nt][1]);
            *(__half2*)(prow + 8*136 + nt*8)  = __floats2half2_rn(sacc[nt][2], sacc[nt][3]);
        }
        __syncwarp();

        uint32_t vbase = s2u(buf ? Vs1 : Vs0) + (lr*72 + lc)*2;
        #pragma unroll
        for (int k2 = 0; k2 < 8; k2++) {
            uint32_t pf[4];
            ldm4(pf, pabase + k2*32);
            #pragma unroll
            for (int hp = 0; hp < 4; hp++) {
                uint32_t vt[4];
                ldm4t(vt, vbase + (k2*16*72 + hp*16)*2);
                mma16(oacc[2*hp  ], pf, vt[0], vt[1]);
                mma16(oacc[2*hp+1], pf, vt[2], vt[3]);
            }
        }
    }

    float i0 = 1.f / l0, i1 = 1.f / l1;
    int r0 = q0 + w*16 + (lane >> 2);
    __half* Op = O + (size_t)(b*Sz + r0)*1024 + h*64 + (lane&3)*2;
    #pragma unroll
    for (int nt = 0; nt < 8; nt++) {
        *(__half2*)(Op + nt*8)          = __floats2half2_rn(oacc[nt][0]*i0, oacc[nt][1]*i0);
        *(__half2*)(Op + 8*1024 + nt*8) = __floats2half2_rn(oacc[nt][2]*i1, oacc[nt][3]*i1);
    }
}

// ---------------------------------------------------------------------------
// Gate head + softmax + top-2 + renorm + routing. One warp per token.
// ---------------------------------------------------------------------------
__global__ __launch_bounds__(256) void gate_route_kernel(
    const float* __restrict__ GH, const float* __restrict__ gw2,
    const float* __restrict__ gb2,
    float* __restrict__ wout, int* __restrict__ cnt, int* __restrict__ elist)
{
    int warp = threadIdx.x >> 5;
    int lane = threadIdx.x & 31;
    int t = blockIdx.x * 8 + warp;
    if (t >= Tz) return;

    float logit[Ez];
    #pragma unroll
    for (int o = 0; o < Ez; o++) {
        float s = 0.f;
        for (int i = lane; i < GHz; i += 32)
            s += GH[(size_t)t * GHz + i] * gw2[(size_t)i * Ez + o];
        #pragma unroll
        for (int off = 16; off; off >>= 1)
            s += __shfl_xor_sync(0xffffffffu, s, off);
        logit[o] = s + gb2[o];
    }
    if (lane == 0) {
        float m = logit[0];
        #pragma unroll
        for (int o = 1; o < Ez; o++) m = fmaxf(m, logit[o]);
        float w[Ez], sum = 0.f;
        #pragma unroll
        for (int o = 0; o < Ez; o++) { w[o] = expf(logit[o] - m); sum += w[o]; }
        float invs = 1.f / sum;
        #pragma unroll
        for (int o = 0; o < Ez; o++) w[o] *= invs;
        int i0 = 0; float v0 = w[0];
        #pragma unroll
        for (int o = 1; o < Ez; o++) if (w[o] > v0) { v0 = w[o]; i0 = o; }
        int i1 = -1; float v1 = -1.f;
        #pragma unroll
        for (int o = 0; o < Ez; o++)
            if (o != i0 && w[o] > v1) { v1 = w[o]; i1 = o; }
        float e1 = expf(v1 - v0);
        float den = 1.f + e1;
        wout[2*t + 0] = 1.f / den;
        wout[2*t + 1] = e1 / den;
        int p0 = atomicAdd(&cnt[i0], 1);
        elist[i0 * Tz + p0] = 2*t + 0;
        int p1 = atomicAdd(&cnt[i1], 1);
        elist[i1 * Tz + p1] = 2*t + 1;
    }
}

__global__ void zero_counts_kernel(int* cnt)
{
    if (threadIdx.x < Ez) cnt[threadIdx.x] = 0;
}

// ---------------------------------------------------------------------------
// Final combine: out = x1 + w0*eo[2t] + w1*eo[2t+1]  (eo fp16)
// ---------------------------------------------------------------------------
__global__ __launch_bounds__(256) void combine_kernel(
    const float* __restrict__ x1, const __half* __restrict__ eo,
    const float* __restrict__ w, float* __restrict__ out)
{
    int idx = blockIdx.x * 256 + threadIdx.x;
    int t = idx >> 8;
    int c = idx & 255;
    float w0 = w[2*t], w1 = w[2*t + 1];
    float4 a  = ((const float4*)x1)[idx];
    uint2 u0 = ((const uint2*)(eo + (size_t)(2*t)     * Dz))[c];
    uint2 u1 = ((const uint2*)(eo + (size_t)(2*t + 1) * Dz))[c];
    float2 e0a = __half22float2(*(__half2*)&u0.x);
    float2 e0b = __half22float2(*(__half2*)&u0.y);
    float2 e1a = __half22float2(*(__half2*)&u1.x);
    float2 e1b = __half22float2(*(__half2*)&u1.y);
    float4 r;
    r.x = a.x + w0 * e0a.x + w1 * e1a.x;
    r.y = a.y + w0 * e0a.y + w1 * e1a.y;
    r.z = a.z + w0 * e0b.x + w1 * e1b.x;
    r.w = a.w + w0 * e0b.y + w1 * e1b.y;
    ((float4*)out)[idx] = r;
}

// ---------------------------------------------------------------------------
// Host launch
// ---------------------------------------------------------------------------
extern "C" void kernel_launch(void* const* d_in, const int* in_sizes, int n_in,
                              void* d_out, int out_size)
{
    const float* x    = (const float*)d_in[0];
    const float* wq   = (const float*)d_in[1];
    const float* bq   = (const float*)d_in[2];
    const float* wk   = (const float*)d_in[3];
    const float* bk   = (const float*)d_in[4];
    const float* wv   = (const float*)d_in[5];
    const float* bv   = (const float*)d_in[6];
    const float* wo   = (const float*)d_in[7];
    const float* bo   = (const float*)d_in[8];
    const float* ln1g = (const float*)d_in[9];
    const float* ln1b = (const float*)d_in[10];
    const float* ln2g = (const float*)d_in[11];
    const float* ln2b = (const float*)d_in[12];
    const float* gw1  = (const float*)d_in[13];
    const float* gb1  = (const float*)d_in[14];
    const float* gw2  = (const float*)d_in[15];
    const float* gb2  = (const float*)d_in[16];
    const float* ew1  = (const float*)d_in[17];
    const float* eb1  = (const float*)d_in[18];
    const float* ew2  = (const float*)d_in[19];
    const float* eb2  = (const float*)d_in[20];
    float* out = (float*)d_out;

    __half *h1h, *qkvh, *aoh, *h2h, *h2l, *hidh, *eo;
    __half *wqkvh, *woh, *ew1h, *ew2h, *gw1h, *gw1l;
    float *x1, *gh, *w, *qkvb;
    int *cnt, *elist;
    cudaGetSymbolAddress((void**)&h1h,  g_h1h);
    cudaGetSymbolAddress((void**)&qkvh, g_qkvh);
    cudaGetSymbolAddress((void**)&aoh,  g_aoh);
    cudaGetSymbolAddress((void**)&x1,   g_x1);
    cudaGetSymbolAddress((void**)&h2h,  g_h2h);
    cudaGetSymbolAddress((void**)&h2l,  g_h2l);
    cudaGetSymbolAddress((void**)&gh,   g_gh);
    cudaGetSymbolAddress((void**)&w,    g_w);
    cudaGetSymbolAddress((void**)&hidh, g_hidh);
    cudaGetSymbolAddress((void**)&eo,   g_eo);
    cudaGetSymbolAddress((void**)&cnt,  g_cnt);
    cudaGetSymbolAddress((void**)&elist,g_elist);
    cudaGetSymbolAddress((void**)&wqkvh,g_wqkvh);
    cudaGetSymbolAddress((void**)&woh,  g_woh);
    cudaGetSymbolAddress((void**)&ew1h, g_ew1h);
    cudaGetSymbolAddress((void**)&ew2h, g_ew2h);
    cudaGetSymbolAddress((void**)&gw1h, g_gw1h);
    cudaGetSymbolAddress((void**)&gw1l, g_gw1l);
    cudaGetSymbolAddress((void**)&qkvb, g_qkvb);

    cudaFuncSetAttribute(gemm_hc<0,false,false,true>, cudaFuncAttributeMaxDynamicSharedMemorySize, GEMMH_SMEM);
    cudaFuncSetAttribute(gemm_hc<0,false,true,false>, cudaFuncAttributeMaxDynamicSharedMemorySize, GEMMH_SMEM);
    cudaFuncSetAttribute(gemm_hc<2,true,false,true>,  cudaFuncAttributeMaxDynamicSharedMemorySize, GEMMH_SMEM);
    cudaFuncSetAttribute(gemm_hc<0,true,false,true>,  cudaFuncAttributeMaxDynamicSharedMemorySize, GEMMH_SMEM);
    cudaFuncSetAttribute(gemm_gate16, cudaFuncAttributeMaxDynamicSharedMemorySize, GATE_SMEM);
    cudaFuncSetAttribute(fa_h, cudaFuncAttributeMaxDynamicSharedMemorySize, FA_SMEM);

    // --- weight convert pre-pass ---
    cvt_pack<<<(Dz*512/4 + 255)/256, 256>>>(wq, wqkvh,        512,  QKVN, Dz*512/4,  0.125f);
    cvt_pack<<<(Dz*Dz/4 + 255)/256, 256>>>(wk, wqkvh + 512,   Dz,   QKVN, Dz*Dz/4,   1.f);
    cvt_pack<<<(Dz*Dz/4 + 255)/256, 256>>>(wv, wqkvh + 1536,  Dz,   QKVN, Dz*Dz/4,   1.f);
    cvt_pack<<<(Dz*Dz/4 + 255)/256, 256>>>(wo, woh,           Dz,   Dz,   Dz*Dz/4,   1.f);
    cvt_pack<<<((int)((size_t)Ez*Dz*EDz/4) + 255)/256, 256>>>(ew1, ew1h, EDz, EDz, (int)((size_t)Ez*Dz*EDz/4), 1.f);
    cvt_pack<<<((int)((size_t)Ez*EDz*Dz/4) + 255)/256, 256>>>(ew2, ew2h, Dz,  Dz,  (int)((size_t)Ez*EDz*Dz/4), 1.f);
    cvt_split<<<(Dz*GHz/4 + 255)/256, 256>>>(gw1, gw1h, gw1l, Dz*GHz/4);
    pack_bias<<<10, 256>>>(bq, bk, bv, qkvb);

    zero_counts_kernel<<<1, 32>>>(cnt);
    ln_kernel<false><<<Tz, 256>>>(x, ln1g, ln1b, h1h, nullptr);

    // Fused QKV projection (fp16), Q pre-scaled via weights/bias
    gemm_hc<0,false,false,true><<<dim3(QKVN/128, 32, 1), 256, GEMMH_SMEM>>>(
        h1h, wqkvh, qkvb, qkvh, Tz, QKVN, Dz, nullptr, nullptr, nullptr, 0);

    fa_h<<<dim3(Sz/128, Bz*Hh), 256, FA_SMEM>>>(qkvh, aoh);

    // Output projection + residual -> x1 fp32
    gemm_hc<0,false,true,false><<<dim3(8, 32, 1), 256, GEMMH_SMEM>>>(
        aoh, woh, bo, x1, Tz, Dz, Dz, x, nullptr, nullptr, 0);

    // LN2 -> fp16 hi + lo (no fp32 buffer)
    ln_kernel<true><<<Tz, 256>>>(x1, ln2g, ln2b, h2h, h2l);

    // gate layer 1: split-fp16 near-fp32 (protects top-2 selection)
    gemm_gate16<<<dim3(GHz/128, Tz/128, 1), 256, GATE_SMEM>>>(
        h2h, h2l, gw1h, gw1l, gb1, gh, Tz, GHz, Dz);

    gate_route_kernel<<<Tz/8, 256>>>(gh, gw2, gb2, w, cnt, elist);

    // Expert FFN (fp16, gathered)
    gemm_hc<2,true,false,true><<<dim3(EDz/128, Tz/128, Ez), 256, GEMMH_SMEM>>>(
        h2h, ew1h, eb1, hidh, Tz, EDz, Dz, nullptr, elist, cnt, 1);
    gemm_hc<0,true,false,true><<<dim3(Dz/128, Tz/128, Ez), 256, GEMMH_SMEM>>>(
        hidh, ew2h, eb2, eo, Tz, Dz, EDz, nullptr, elist, cnt, 0);

    combine_kernel<<<(Tz*Dz/4)/256, 256>>>(x1, eo, w, out);
}

// round 11
// speedup vs baseline: 7.8954x; 1.0274x over previous
#include <cuda_runtime.h>
#include <cuda_fp16.h>
#include <math.h>
#include <stdint.h>

// ---------------------------------------------------------------------------
// Problem constants
// ---------------------------------------------------------------------------
#define Bz   4
#define Sz   1024
#define Dz   1024
#define Hh   16
#define Gg   8
#define HDz  64
#define Ez   8
#define EDz  2048
#define GHz  512
#define Tz   (Bz*Sz)          // 4096 tokens
#define QKVN 2560             // packed q(512) | k(1024) | v(1024)

// ---------------------------------------------------------------------------
// Scratch (static device memory)
// ---------------------------------------------------------------------------
__device__ __half g_h1h [Tz*Dz];
__device__ __half g_qkvh[(size_t)Tz*QKVN];
__device__ __half g_aoh [Tz*Dz];
__device__ float  g_x1  [Tz*Dz];
__device__ __half g_h2h [Tz*Dz];       // LN2 out, fp16 hi
__device__ __half g_h2l [Tz*Dz];       // LN2 out, fp16 lo (residual)
__device__ float  g_gh  [Tz*GHz];
__device__ float  g_w   [Tz*2];
__device__ int    g_cnt [Ez];
__device__ int    g_elist[Ez*Tz];
__device__ __half g_hidh[(size_t)Tz*2*EDz];
__device__ __half g_eo  [(size_t)Tz*2*Dz];
// fp16 weights ([K][N] row-major; qkv packed) + packed qkv bias
__device__ __half g_wqkvh[(size_t)Dz*QKVN];
__device__ __half g_woh  [(size_t)Dz*Dz];
__device__ __half g_ew1h [(size_t)Ez*Dz*EDz];
__device__ __half g_ew2h [(size_t)Ez*EDz*Dz];
__device__ __half g_gw1h [(size_t)Dz*GHz];   // gate w1 hi
__device__ __half g_gw1l [(size_t)Dz*GHz];   // gate w1 lo
__device__ float  g_qkvb [QKVN];

// ---------------------------------------------------------------------------
// Helpers
// ---------------------------------------------------------------------------
__device__ __forceinline__ uint32_t s2u(const void* p){
    return (uint32_t)__cvta_generic_to_shared(p);
}
__device__ __forceinline__ void cpa16(uint32_t d, const void* s, bool v){
    asm volatile("cp.async.cg.shared.global [%0], [%1], 16, %2;\n"
                 :: "r"(d), "l"(s), "r"(v ? 16 : 0));
}
__device__ __forceinline__ void cp_commit(){ asm volatile("cp.async.commit_group;\n"); }
__device__ __forceinline__ void cp_wait0(){ asm volatile("cp.async.wait_group 0;\n"); }
__device__ __forceinline__ void cp_wait1(){ asm volatile("cp.async.wait_group 1;\n"); }
__device__ __forceinline__ void mma16(float* c, const uint32_t* a, uint32_t b0, uint32_t b1){
    asm volatile("mma.sync.aligned.m16n8k16.row.col.f32.f16.f16.f32 "
        "{%0,%1,%2,%3},{%4,%5,%6,%7},{%8,%9},{%0,%1,%2,%3};\n"
        : "+f"(c[0]),"+f"(c[1]),"+f"(c[2]),"+f"(c[3])
        : "r"(a[0]),"r"(a[1]),"r"(a[2]),"r"(a[3]),"r"(b0),"r"(b1));
}
__device__ __forceinline__ void ldm4(uint32_t* r, uint32_t addr){
    asm volatile("ldmatrix.sync.aligned.m8n8.x4.shared.b16 {%0,%1,%2,%3}, [%4];"
        : "=r"(r[0]),"=r"(r[1]),"=r"(r[2]),"=r"(r[3]) : "r"(addr));
}
__device__ __forceinline__ void ldm4t(uint32_t* r, uint32_t addr){
    asm volatile("ldmatrix.sync.aligned.m8n8.x4.trans.shared.b16 {%0,%1,%2,%3}, [%4];"
        : "=r"(r[0]),"=r"(r[1]),"=r"(r[2]),"=r"(r[3]) : "r"(addr));
}

// ---------------------------------------------------------------------------
// Fused QKV weight convert + bias pack + count zero (single launch).
// Weights: wq/wk/wv [K][*] fp32 -> packed [K][2560] fp16 (wq scaled 0.125).
// ---------------------------------------------------------------------------
#define QKV_W4 (Dz*QKVN/4)
__global__ __launch_bounds__(256) void cvt_qkv(
    const float* __restrict__ wq, const float* __restrict__ wk,
    const float* __restrict__ wv,
    const float* __restrict__ bq, const float* __restrict__ bk,
    const float* __restrict__ bv,
    __half* __restrict__ out, float* __restrict__ qkvb, int* __restrict__ cnt)
{
    int i = blockIdx.x * 256 + threadIdx.x;
    if (i < QKV_W4) {
        int row = i / (QKVN/4);
        int c4  = (i - row * (QKVN/4)) * 4;
        const float* src;
        float scale = 1.f;
        if (c4 < 512)       { src = wq + (size_t)row*512  + c4;         scale = 0.125f; }
        else if (c4 < 1536) { src = wk + (size_t)row*1024 + (c4-512);  }
        else                { src = wv + (size_t)row*1024 + (c4-1536); }
        float4 a = *(const float4*)src;
        __half2 h0 = __floats2half2_rn(a.x*scale, a.y*scale);
        __half2 h1 = __floats2half2_rn(a.z*scale, a.w*scale);
        uint2 u; u.x = *(uint32_t*)&h0; u.y = *(uint32_t*)&h1;
        *(uint2*)(out + (size_t)row * QKVN + c4) = u;
    } else {
        int j = i - QKV_W4;
        if (j < 512)        qkvb[j] = bq[j] * 0.125f;
        else if (j < 1536)  qkvb[j] = bk[j - 512];
        else if (j < QKVN)  qkvb[j] = bv[j - 1536];
        else if (j < QKVN + Ez) cnt[j - QKVN] = 0;
    }
}

// Contiguous fp32 -> fp16 convert (used for wo)
__global__ __launch_bounds__(256) void cvt_c(
    const float* __restrict__ in, __half* __restrict__ out, int total4)
{
    int i = blockIdx.x * 256 + threadIdx.x;
    if (i >= total4) return;
    float4 a = ((const float4*)in)[i];
    __half2 h0 = __floats2half2_rn(a.x, a.y);
    __half2 h1 = __floats2half2_rn(a.z, a.w);
    uint2 u; u.x = *(uint32_t*)&h0; u.y = *(uint32_t*)&h1;
    ((uint2*)out)[i] = u;
}

// Dual contiguous convert (ew1 and ew2 in one launch)
__global__ __launch_bounds__(256) void cvt_c2(
    const float* __restrict__ in1, __half* __restrict__ o1,
    const float* __restrict__ in2, __half* __restrict__ o2, int t4)
{
    int i = blockIdx.x * 256 + threadIdx.x;
    const float* in; __half* o; int k;
    if (i < t4)            { in = in1; o = o1; k = i; }
    else if (i < 2*t4)     { in = in2; o = o2; k = i - t4; }
    else return;
    float4 a = ((const float4*)in)[k];
    __half2 h0 = __floats2half2_rn(a.x, a.y);
    __half2 h1 = __floats2half2_rn(a.z, a.w);
    uint2 u; u.x = *(uint32_t*)&h0; u.y = *(uint32_t*)&h1;
    ((uint2*)o)[k] = u;
}

// fp32 -> fp16 hi/lo split convert (contiguous, gate w1)
__global__ __launch_bounds__(256) void cvt_split(
    const float* __restrict__ in, __half* __restrict__ hi,
    __half* __restrict__ lo, int total4)
{
    int i = blockIdx.x * 256 + threadIdx.x;
    if (i >= total4) return;
    float4 a = ((const float4*)in)[i];
    __half hx = __float2half_rn(a.x), hy = __float2half_rn(a.y);
    __half hz = __float2half_rn(a.z), hw = __float2half_rn(a.w);
    __half2 H0; H0.x = hx; H0.y = hy;
    __half2 H1; H1.x = hz; H1.y = hw;
    __half2 L0 = __floats2half2_rn(a.x - __half2float(hx), a.y - __half2float(hy));
    __half2 L1 = __floats2half2_rn(a.z - __half2float(hz), a.w - __half2float(hw));
    uint2 uh; uh.x = *(uint32_t*)&H0; uh.y = *(uint32_t*)&H1;
    uint2 ul; ul.x = *(uint32_t*)&L0; ul.y = *(uint32_t*)&L1;
    ((uint2*)hi)[i] = uh;
    ((uint2*)lo)[i] = ul;
}

// ---------------------------------------------------------------------------
// LayerNorm: one block per token row of 1024.
// Writes fp16 hi; SPLIT mode additionally writes fp16 lo (x - hi).
// ---------------------------------------------------------------------------
template<bool SPLIT>
__global__ __launch_bounds__(256) void ln_kernel(
    const float* __restrict__ X, const float* __restrict__ g,
    const float* __restrict__ b, __half* __restrict__ O16, __half* __restrict__ OLO)
{
    int t = blockIdx.x;
    int tid = threadIdx.x;
    const float4* x4 = (const float4*)(X + (size_t)t * Dz);
    float4 xv = x4[tid];
    float s  = xv.x + xv.y + xv.z + xv.w;
    float ss = xv.x*xv.x + xv.y*xv.y + xv.z*xv.z + xv.w*xv.w;
    #pragma unroll
    for (int off = 16; off; off >>= 1) {
        s  += __shfl_xor_sync(0xffffffffu, s,  off);
        ss += __shfl_xor_sync(0xffffffffu, ss, off);
    }
    __shared__ float sh_s[8], sh_ss[8];
    if ((tid & 31) == 0) { sh_s[tid >> 5] = s; sh_ss[tid >> 5] = ss; }
    __syncthreads();
    if (tid < 32) {
        float a = (tid < 8) ? sh_s[tid]  : 0.f;
        float c = (tid < 8) ? sh_ss[tid] : 0.f;
        #pragma unroll
        for (int off = 4; off; off >>= 1) {
            a += __shfl_xor_sync(0xffffffffu, a, off);
            c += __shfl_xor_sync(0xffffffffu, c, off);
        }
        if (tid == 0) { sh_s[0] = a; sh_ss[0] = c; }
    }
    __syncthreads();
    float mu  = sh_s[0]  * (1.f / Dz);
    float var = sh_ss[0] * (1.f / Dz) - mu * mu;
    float inv = rsqrtf(var + 1e-5f);
    float4 gv = ((const float4*)g)[tid];
    float4 bv = ((const float4*)b)[tid];
    float4 o;
    o.x = (xv.x - mu) * inv * gv.x + bv.x;
    o.y = (xv.y - mu) * inv * gv.y + bv.y;
    o.z = (xv.z - mu) * inv * gv.z + bv.z;
    o.w = (xv.w - mu) * inv * gv.w + bv.w;
    __half hx = __float2half_rn(o.x), hy = __float2half_rn(o.y);
    __half hz = __float2half_rn(o.z), hw = __float2half_rn(o.w);
    __half2 p0; p0.x = hx; p0.y = hy;
    __half2 p1; p1.x = hz; p1.y = hw;
    uint2 u; u.x = *(uint32_t*)&p0; u.y = *(uint32_t*)&p1;
    ((uint2*)(O16 + (size_t)t * Dz))[tid] = u;
    if (SPLIT) {
        __half2 l0 = __floats2half2_rn(o.x - __half2float(hx), o.y - __half2float(hy));
        __half2 l1 = __floats2half2_rn(o.z - __half2float(hz), o.w - __half2float(hw));
        uint2 ul; ul.x = *(uint32_t*)&l0; ul.y = *(uint32_t*)&l1;
        ((uint2*)(OLO + (size_t)t * Dz))[tid] = ul;
    }
}

// ---------------------------------------------------------------------------
// fp16 tensor-core GEMM: C[M,N] = act(A @ B + bias)(+resid), optional gather.
// BM=128, BN=128, BK=64 (halves), 256 threads, 8 warps (2M x 4N), warp 64x32.
// A fp16 [M,K] (ldmatrix), B fp16 [K,N] (ldmatrix.trans). 3-stage cp.async.
// Single __syncthreads per k-tile (trailing barrier proven redundant: the
// buffer staged at iteration kt was last read at kt-1, and every warp passes
// the top barrier of kt only after finishing kt-1's reads).
// ---------------------------------------------------------------------------
#define GEMMH_SMEM (3*128*72*2 + 3*64*136*2)
template<int ACT, bool GATHER, bool RESID, bool OUTH>
__global__ void __launch_bounds__(256,2) gemm_hc(
    const __half* __restrict__ A, const __half* __restrict__ B,
    const float* __restrict__ bias, void* __restrict__ Cv,
    int M, int N, int K,
    const float* __restrict__ resid,
    const int* __restrict__ elist, const int* __restrict__ cnt, int ashift)
{
    extern __shared__ __half smh[];
    __half* As = smh;                  // [3][128][72]
    __half* Bs = smh + 3*128*72;       // [3][64][136]

    int e = blockIdx.z;
    const __half* Bp = B + (size_t)e * K * N;
    const float*  bp = bias + (size_t)e * N;
    int mcount = GATHER ? cnt[e] : M;
    int m0 = blockIdx.y * 128;
    if (m0 >= mcount) return;
    int n0 = blockIdx.x * 128;
    const int* lst = GATHER ? (elist + e * Tz) : (const int*)nullptr;

    int tid = threadIdx.x;
    int lane = tid & 31, wid = tid >> 5;
    int warpM = wid >> 2, warpN = wid & 3;

    int aq = (tid & 7) * 8;
    const __half* aptr[4];
    bool aval[4];
    uint32_t adst[4];
    #pragma unroll
    for (int i = 0; i < 4; i++) {
        int r = (tid >> 3) + 32 * i;
        int m = m0 + r;
        bool v = (m < mcount);
        size_t rowg;
        if (GATHER) rowg = v ? (size_t)(lst[m] >> ashift) : 0;
        else        rowg = v ? (size_t)m : 0;
        aptr[i] = A + rowg * (size_t)K + aq;
        aval[i] = v;
        adst[i] = s2u(&As[r * 72 + aq]);
    }
    int brow = tid >> 2, bq = (tid & 3) * 32;
    const __half* bptr = Bp + (size_t)brow * N + n0 + bq;
    uint32_t bdst = s2u(&Bs[brow * 136 + bq]);
    const uint32_t abuf = 128*72*2, bbuf = 64*136*2;

    uint32_t as_u = s2u(As), bs_u = s2u(Bs);

    float acc[4][4][4];
    #pragma unroll
    for (int i=0;i<4;i++)
        #pragma unroll
        for (int j=0;j<4;j++)
            #pragma unroll
            for (int l=0;l<4;l++) acc[i][j][l] = 0.f;

    int KT = K / 64;

    auto stageTile = [&](int kt2, int buf){
        int k0 = kt2 * 64;
        #pragma unroll
        for (int i=0;i<4;i++) cpa16(adst[i] + buf*abuf, aptr[i] + k0, aval[i]);
        #pragma unroll
        for (int j=0;j<4;j++) cpa16(bdst + buf*bbuf + j*16,
                                    bptr + (size_t)k0*N + j*8, true);
    };

    stageTile(0, 0); cp_commit();
    if (KT > 1) stageTile(1, 1);
    cp_commit();

    int bufc = 0, bufs = 2;
    uint32_t lr = lane & 15, lc = (lane >> 4) * 8;
    for (int kt = 0; kt < KT; kt++) {
        cp_wait1();
        __syncthreads();
        if (kt + 2 < KT) stageTile(kt+2, bufs);
        cp_commit();

        uint32_t abase = as_u + ((uint32_t)bufc*(128*72) + (warpM*64 + lr)*72 + lc)*2;
        uint32_t bbase = bs_u + ((uint32_t)bufc*(64*136) + lr*136 + warpN*32 + lc)*2;
        #pragma unroll
        for (int ks = 0; ks < 4; ks++) {
            uint32_t ah[4][4];
            #pragma unroll
            for (int mt = 0; mt < 4; mt++)
                ldm4(ah[mt], abase + (mt*16*72 + ks*16)*2);
            uint32_t bt[2][4];
            #pragma unroll
            for (int pr = 0; pr < 2; pr++)
                ldm4t(bt[pr], bbase + (ks*16*136 + pr*16)*2);
            #pragma unroll
            for (int mt = 0; mt < 4; mt++) {
                mma16(acc[mt][0], ah[mt], bt[0][0], bt[0][1]);
                mma16(acc[mt][1], ah[mt], bt[0][2], bt[0][3]);
                mma16(acc[mt][2], ah[mt], bt[1][0], bt[1][1]);
                mma16(acc[mt][3], ah[mt], bt[1][2], bt[1][3]);
            }
        }
        bufc = (bufc == 2) ? 0 : bufc + 1;
        bufs = (bufs == 2) ? 0 : bufs + 1;
    }

    float2 bv[4];
    #pragma unroll
    for (int nt = 0; nt < 4; nt++)
        bv[nt] = *(const float2*)(bp + n0 + warpN*32 + (lane&3)*2 + nt*8);

    float*  Cf = (float*)Cv;
    __half* Ch = (__half*)Cv;
    #pragma unroll
    for (int mt = 0; mt < 4; mt++) {
        #pragma unroll
        for (int hf = 0; hf < 2; hf++) {
            int r = m0 + warpM*64 + mt*16 + (lane>>2) + hf*8;
            if (r >= mcount) continue;
            size_t crow = GATHER ? (size_t)lst[r] : (size_t)r;
            int coff = n0 + warpN*32 + (lane&3)*2;
            const float* Rr = RESID ? (resid + crow*(size_t)N + coff) : (const float*)nullptr;
            #pragma unroll
            for (int nt = 0; nt < 4; nt++) {
                float v0 = acc[mt][nt][hf*2+0] + bv[nt].x;
                float v1 = acc[mt][nt][hf*2+1] + bv[nt].y;
                if (ACT == 1) { v0 = fmaxf(v0, 0.f); v1 = fmaxf(v1, 0.f); }
                if (ACT == 2) {
                    v0 = 0.5f*v0*(1.f + erff(v0*0.70710678118654752f));
                    v1 = 0.5f*v1*(1.f + erff(v1*0.70710678118654752f));
                }
                if (RESID) { v0 += Rr[nt*8]; v1 += Rr[nt*8+1]; }
                if (OUTH) {
                    __half2 h = __floats2half2_rn(v0, v1);
                    *(__half2*)(Ch + crow*(size_t)N + coff + nt*8) = h;
                } else {
                    float2 o; o.x = v0; o.y = v1;
                    *(float2*)(Cf + crow*(size_t)N + coff + nt*8) = o;
                }
            }
        }
    }
}

// ---------------------------------------------------------------------------
// Split-fp16 gate GEMM (near-fp32): gh = relu((Ah+Al)@(Bh+Bl) + bias)
//   = Ah@Bh + Al@Bh + Ah@Bl (Al@Bl dropped, ~2^-22 relative).
// Single __syncthreads per k-tile (same redundancy argument).
// ---------------------------------------------------------------------------
#define GATE_SMEM (2*2*128*40*2 + 2*2*32*136*2)
__global__ void __launch_bounds__(256,2) gemm_gate16(
    const __half* __restrict__ Ah, const __half* __restrict__ Al,
    const __half* __restrict__ Bh, const __half* __restrict__ Bl,
    const float* __restrict__ bias, float* __restrict__ C,
    int M, int N, int K)
{
    extern __shared__ __half smh[];
    __half* Ahs = smh;                        // [2][128][40]
    __half* Als = Ahs + 2*128*40;             // [2][128][40]
    __half* Bhs = Als + 2*128*40;             // [2][32][136]
    __half* Bls = Bhs + 2*32*136;             // [2][32][136]

    int m0 = blockIdx.y * 128;
    int n0 = blockIdx.x * 128;
    int tid = threadIdx.x;
    int lane = tid & 31, wid = tid >> 5;
    int warpM = wid >> 2, warpN = wid & 3;

    int arow = tid >> 1, acol = (tid & 1) * 16;
    const __half* ahp = Ah + (size_t)(m0 + arow) * K + acol;
    const __half* alp = Al + (size_t)(m0 + arow) * K + acol;
    uint32_t ahd = s2u(&Ahs[arow * 40 + acol]);
    uint32_t ald = s2u(&Als[arow * 40 + acol]);
    int brow = tid >> 3, bcol = (tid & 7) * 16;
    const __half* bhp = Bh + (size_t)brow * N + n0 + bcol;
    const __half* blp = Bl + (size_t)brow * N + n0 + bcol;
    uint32_t bhd = s2u(&Bhs[brow * 136 + bcol]);
    uint32_t bld = s2u(&Bls[brow * 136 + bcol]);

    const uint32_t abuf = 128*40*2, bbuf = 32*136*2;

    auto stage = [&](int kt, int buf){
        int k0 = kt * 32;
        cpa16(ahd + buf*abuf,      ahp + k0, true);
        cpa16(ahd + buf*abuf + 16, ahp + k0 + 8, true);
        cpa16(ald + buf*abuf,      alp + k0, true);
        cpa16(ald + buf*abuf + 16, alp + k0 + 8, true);
        cpa16(bhd + buf*bbuf,      bhp + (size_t)k0*N, true);
        cpa16(bhd + buf*bbuf + 16, bhp + (size_t)k0*N + 8, true);
        cpa16(bld + buf*bbuf,      blp + (size_t)k0*N, true);
        cpa16(bld + buf*bbuf + 16, blp + (size_t)k0*N + 8, true);
    };

    uint32_t ahs_u = s2u(Ahs), als_u = s2u(Als);
    uint32_t bhs_u = s2u(Bhs), bls_u = s2u(Bls);

    float acc[4][4][4];
    #pragma unroll
    for (int i=0;i<4;i++)
        #pragma unroll
        for (int j=0;j<4;j++)
            #pragma unroll
            for (int l=0;l<4;l++) acc[i][j][l] = 0.f;

    int KT = K / 32;
    stage(0, 0); cp_commit();

    uint32_t lr = lane & 15, lc = (lane >> 4) * 8;
    for (int kt = 0; kt < KT; kt++) {
        int buf = kt & 1;
        cp_wait0();
        __syncthreads();
        if (kt + 1 < KT) { stage(kt+1, buf ^ 1); }
        cp_commit();

        uint32_t aoff = ((uint32_t)buf*(128*40) + (warpM*64 + lr)*40 + lc)*2;
        uint32_t boff = ((uint32_t)buf*(32*136) + lr*136 + warpN*32 + lc)*2;
        #pragma unroll
        for (int ks = 0; ks < 2; ks++) {
            uint32_t ah[4][4], al[4][4];
            #pragma unroll
            for (int mt = 0; mt < 4; mt++) {
                ldm4(ah[mt], ahs_u + aoff + (mt*16*40 + ks*16)*2);
                ldm4(al[mt], als_u + aoff + (mt*16*40 + ks*16)*2);
            }
            uint32_t bth[2][4], btl[2][4];
            #pragma unroll
            for (int pr = 0; pr < 2; pr++) {
                ldm4t(bth[pr], bhs_u + boff + (ks*16*136 + pr*16)*2);
                ldm4t(btl[pr], bls_u + boff + (ks*16*136 + pr*16)*2);
            }
            #pragma unroll
            for (int mt = 0; mt < 4; mt++) {
                mma16(acc[mt][0], ah[mt], bth[0][0], bth[0][1]);
                mma16(acc[mt][1], ah[mt], bth[0][2], bth[0][3]);
                mma16(acc[mt][2], ah[mt], bth[1][0], bth[1][1]);
                mma16(acc[mt][3], ah[mt], bth[1][2], bth[1][3]);
                mma16(acc[mt][0], al[mt], bth[0][0], bth[0][1]);
                mma16(acc[mt][1], al[mt], bth[0][2], bth[0][3]);
                mma16(acc[mt][2], al[mt], bth[1][0], bth[1][1]);
                mma16(acc[mt][3], al[mt], bth[1][2], bth[1][3]);
                mma16(acc[mt][0], ah[mt], btl[0][0], btl[0][1]);
                mma16(acc[mt][1], ah[mt], btl[0][2], btl[0][3]);
                mma16(acc[mt][2], ah[mt], btl[1][0], btl[1][1]);
                mma16(acc[mt][3], ah[mt], btl[1][2], btl[1][3]);
            }
        }
    }

    float2 bv[4];
    #pragma unroll
    for (int nt = 0; nt < 4; nt++)
        bv[nt] = *(const float2*)(bias + n0 + warpN*32 + (lane&3)*2 + nt*8);

    #pragma unroll
    for (int mt = 0; mt < 4; mt++)
        #pragma unroll
        for (int hf = 0; hf < 2; hf++) {
            int r = m0 + warpM*64 + mt*16 + (lane>>2) + hf*8;
            float* Cr = C + (size_t)r*N + n0 + warpN*32 + (lane&3)*2;
            #pragma unroll
            for (int nt = 0; nt < 4; nt++) {
                float v0 = fmaxf(acc[mt][nt][hf*2+0] + bv[nt].x, 0.f);
                float v1 = fmaxf(acc[mt][nt][hf*2+1] + bv[nt].y, 0.f);
                float2 o; o.x = v0; o.y = v1;
                *(float2*)(Cr + nt*8) = o;
            }
        }
}

// ---------------------------------------------------------------------------
// Fused flash attention, fp16 mma.sync, online softmax (fp32 stats).
// ---------------------------------------------------------------------------
#define FA_SMEM (128*136*2 + 4*128*72*2)
__global__ void __launch_bounds__(256,2) fa_h(
    const __half* __restrict__ QKV, __half* __restrict__ O)
{
    extern __shared__ __half smh[];
    __half* Ps  = smh;                     // [128][136]; alias Qs [128][72]
    __half* Ks0 = smh + 128*136;
    __half* Ks1 = Ks0 + 128*72;
    __half* Vs0 = Ks1 + 128*72;
    __half* Vs1 = Vs0 + 128*72;

    int bh = blockIdx.y, b = bh >> 4, h = bh & 15, g = h >> 1;
    int q0 = blockIdx.x * 128;
    int tid = threadIdx.x, lane = tid & 31, w = tid >> 5;

    const __half* Qb = QKV + (size_t)(b*Sz + q0) * QKVN + g*64;
    {
        int row = tid >> 1;
        #pragma unroll
        for (int j = 0; j < 4; j++) {
            int c = (tid & 1) + 2*j;
            cpa16(s2u(Ps + row*72 + c*8), Qb + (size_t)row*QKVN + c*8, true);
        }
    }
    cp_commit();

    const __half* Kb = QKV + (size_t)(b*Sz)*QKVN + 512 + h*64;
    const __half* Vb = QKV + (size_t)(b*Sz)*QKVN + 1536 + h*64;

    auto stageKV = [&](int kt, int buf){
        int row = tid >> 1;
        __half* Kd = (buf ? Ks1 : Ks0) + row*72;
        __half* Vd = (buf ? Vs1 : Vs0) + row*72;
        const __half* kp = Kb + (size_t)(kt*128 + row)*QKVN;
        const __half* vp = Vb + (size_t)(kt*128 + row)*QKVN;
        #pragma unroll
        for (int j = 0; j < 4; j++) {
            int c = (tid & 1) + 2*j;
            cpa16(s2u(Kd + c*8), kp + c*8, true);
            cpa16(s2u(Vd + c*8), vp + c*8, true);
        }
    };
    stageKV(0, 0); cp_commit();

    asm volatile("cp.async.wait_group 1;\n");
    __syncthreads();
    uint32_t lr = lane & 15, lc = (lane >> 4) * 8;
    uint32_t qbase = s2u(Ps) + ((w*16 + lr)*72 + lc)*2;
    uint32_t qf[4][4];
    #pragma unroll
    for (int ks = 0; ks < 4; ks++) ldm4(qf[ks], qbase + ks*32);
    __syncthreads();

    float m0 = -INFINITY, m1 = -INFINITY, l0 = 0.f, l1 = 0.f;
    float oacc[8][4];
    #pragma unroll
    for (int i=0;i<8;i++)
        #pragma unroll
        for (int j=0;j<4;j++) oacc[i][j] = 0.f;

    uint32_t pabase = s2u(Ps) + ((w*16 + lr)*136 + lc)*2;
    __half* prow = Ps + (size_t)(w*16 + (lane>>2))*136 + (lane&3)*2;

    for (int kt = 0; kt < 8; kt++) {
        int buf = kt & 1;
        cp_wait0();
        __syncthreads();
        if (kt + 1 < 8) stageKV(kt+1, buf ^ 1);
        cp_commit();

        float sacc[16][4];
        #pragma unroll
        for (int i=0;i<16;i++)
            #pragma unroll
            for (int j=0;j<4;j++) sacc[i][j] = 0.f;
        uint32_t kbase = s2u(buf ? Ks1 : Ks0) + (lr*72 + lc)*2;
        #pragma unroll
        for (int ks = 0; ks < 4; ks++) {
            #pragma unroll
            for (int np = 0; np < 8; np++) {
                uint32_t r[4];
                ldm4(r, kbase + (np*16*72 + ks*16)*2);
                mma16(sacc[2*np  ], qf[ks], r[0], r[2]);
                mma16(sacc[2*np+1], qf[ks], r[1], r[3]);
            }
        }

        float t0 = -INFINITY, t1 = -INFINITY;
        #pragma unroll
        for (int nt = 0; nt < 16; nt++) {
            t0 = fmaxf(t0, fmaxf(sacc[nt][0], sacc[nt][1]));
            t1 = fmaxf(t1, fmaxf(sacc[nt][2], sacc[nt][3]));
        }
        t0 = fmaxf(t0, __shfl_xor_sync(0xffffffffu, t0, 1));
        t0 = fmaxf(t0, __shfl_xor_sync(0xffffffffu, t0, 2));
        t1 = fmaxf(t1, __shfl_xor_sync(0xffffffffu, t1, 1));
        t1 = fmaxf(t1, __shfl_xor_sync(0xffffffffu, t1, 2));
        float mn0 = fmaxf(m0, t0), mn1 = fmaxf(m1, t1);
        float sc0 = __expf(m0 - mn0), sc1 = __expf(m1 - mn1);
        float s0 = 0.f, s1 = 0.f;
        #pragma unroll
        for (int nt = 0; nt < 16; nt++) {
            sacc[nt][0] = __expf(sacc[nt][0] - mn0);
            sacc[nt][1] = __expf(sacc[nt][1] - mn0);
            sacc[nt][2] = __expf(sacc[nt][2] - mn1);
            sacc[nt][3] = __expf(sacc[nt][3] - mn1);
            s0 += sacc[nt][0] + sacc[nt][1];
            s1 += sacc[nt][2] + sacc[nt][3];
        }
        s0 += __shfl_xor_sync(0xffffffffu, s0, 1);
        s0 += __shfl_xor_sync(0xffffffffu, s0, 2);
        s1 += __shfl_xor_sync(0xffffffffu, s1, 1);
        s1 += __shfl_xor_sync(0xffffffffu, s1, 2);
        l0 = l0*sc0 + s0; l1 = l1*sc1 + s1;
        m0 = mn0; m1 = mn1;
        #pragma unroll
        for (int nt = 0; nt < 8; nt++) {
            oacc[nt][0] *= sc0; oacc[nt][1] *= sc0;
            oacc[nt][2] *= sc1; oacc[nt][3] *= sc1;
        }

        #pragma unroll
        for (int nt = 0; nt < 16; nt++) {
            *(__half2*)(prow + nt*8)          = __floats2half2_rn(sacc[nt][0], sacc[nt][1]);
            *(__half2*)(prow + 8*136 + nt*8)  = __floats2half2_rn(sacc[nt][2], sacc[nt][3]);
        }
        __syncwarp();

        uint32_t vbase = s2u(buf ? Vs1 : Vs0) + (lr*72 + lc)*2;
        #pragma unroll
        for (int k2 = 0; k2 < 8; k2++) {
            uint32_t pf[4];
            ldm4(pf, pabase + k2*32);
            #pragma unroll
            for (int hp = 0; hp < 4; hp++) {
                uint32_t vt[4];
                ldm4t(vt, vbase + (k2*16*72 + hp*16)*2);
                mma16(oacc[2*hp  ], pf, vt[0], vt[1]);
                mma16(oacc[2*hp+1], pf, vt[2], vt[3]);
            }
        }
    }

    float i0 = 1.f / l0, i1 = 1.f / l1;
    int r0 = q0 + w*16 + (lane >> 2);
    __half* Op = O + (size_t)(b*Sz + r0)*1024 + h*64 + (lane&3)*2;
    #pragma unroll
    for (int nt = 0; nt < 8; nt++) {
        *(__half2*)(Op + nt*8)          = __floats2half2_rn(oacc[nt][0]*i0, oacc[nt][1]*i0);
        *(__half2*)(Op + 8*1024 + nt*8) = __floats2half2_rn(oacc[nt][2]*i1, oacc[nt][3]*i1);
    }
}

// ---------------------------------------------------------------------------
// Gate head + softmax + top-2 + renorm + routing. One warp per token.
// ---------------------------------------------------------------------------
__global__ __launch_bounds__(256) void gate_route_kernel(
    const float* __restrict__ GH, const float* __restrict__ gw2,
    const float* __restrict__ gb2,
    float* __restrict__ wout, int* __restrict__ cnt, int* __restrict__ elist)
{
    int warp = threadIdx.x >> 5;
    int lane = threadIdx.x & 31;
    int t = blockIdx.x * 8 + warp;
    if (t >= Tz) return;

    float logit[Ez];
    #pragma unroll
    for (int o = 0; o < Ez; o++) {
        float s = 0.f;
        for (int i = lane; i < GHz; i += 32)
            s += GH[(size_t)t * GHz + i] * gw2[(size_t)i * Ez + o];
        #pragma unroll
        for (int off = 16; off; off >>= 1)
            s += __shfl_xor_sync(0xffffffffu, s, off);
        logit[o] = s + gb2[o];
    }
    if (lane == 0) {
        float m = logit[0];
        #pragma unroll
        for (int o = 1; o < Ez; o++) m = fmaxf(m, logit[o]);
        float w[Ez], sum = 0.f;
        #pragma unroll
        for (int o = 0; o < Ez; o++) { w[o] = expf(logit[o] - m); sum += w[o]; }
        float invs = 1.f / sum;
        #pragma unroll
        for (int o = 0; o < Ez; o++) w[o] *= invs;
        int i0 = 0; float v0 = w[0];
        #pragma unroll
        for (int o = 1; o < Ez; o++) if (w[o] > v0) { v0 = w[o]; i0 = o; }
        int i1 = -1; float v1 = -1.f;
        #pragma unroll
        for (int o = 0; o < Ez; o++)
            if (o != i0 && w[o] > v1) { v1 = w[o]; i1 = o; }
        float e1 = expf(v1 - v0);
        float den = 1.f + e1;
        wout[2*t + 0] = 1.f / den;
        wout[2*t + 1] = e1 / den;
        int p0 = atomicAdd(&cnt[i0], 1);
        elist[i0 * Tz + p0] = 2*t + 0;
        int p1 = atomicAdd(&cnt[i1], 1);
        elist[i1 * Tz + p1] = 2*t + 1;
    }
}

// ---------------------------------------------------------------------------
// Final combine: out = x1 + w0*eo[2t] + w1*eo[2t+1]  (eo fp16)
// ---------------------------------------------------------------------------
__global__ __launch_bounds__(256) void combine_kernel(
    const float* __restrict__ x1, const __half* __restrict__ eo,
    const float* __restrict__ w, float* __restrict__ out)
{
    int idx = blockIdx.x * 256 + threadIdx.x;
    int t = idx >> 8;
    int c = idx & 255;
    float w0 = w[2*t], w1 = w[2*t + 1];
    float4 a  = ((const float4*)x1)[idx];
    uint2 u0 = ((const uint2*)(eo + (size_t)(2*t)     * Dz))[c];
    uint2 u1 = ((const uint2*)(eo + (size_t)(2*t + 1) * Dz))[c];
    float2 e0a = __half22float2(*(__half2*)&u0.x);
    float2 e0b = __half22float2(*(__half2*)&u0.y);
    float2 e1a = __half22float2(*(__half2*)&u1.x);
    float2 e1b = __half22float2(*(__half2*)&u1.y);
    float4 r;
    r.x = a.x + w0 * e0a.x + w1 * e1a.x;
    r.y = a.y + w0 * e0a.y + w1 * e1a.y;
    r.z = a.z + w0 * e0b.x + w1 * e1b.x;
    r.w = a.w + w0 * e0b.y + w1 * e1b.y;
    ((float4*)out)[idx] = r;
}

// ---------------------------------------------------------------------------
// Host launch (single stream — graph-capture safe)
// ---------------------------------------------------------------------------
extern "C" void kernel_launch(void* const* d_in, const int* in_sizes, int n_in,
                              void* d_out, int out_size)
{
    const float* x    = (const float*)d_in[0];
    const float* wq   = (const float*)d_in[1];
    const float* bq   = (const float*)d_in[2];
    const float* wk   = (const float*)d_in[3];
    const float* bk   = (const float*)d_in[4];
    const float* wv   = (const float*)d_in[5];
    const float* bv   = (const float*)d_in[6];
    const float* wo   = (const float*)d_in[7];
    const float* bo   = (const float*)d_in[8];
    const float* ln1g = (const float*)d_in[9];
    const float* ln1b = (const float*)d_in[10];
    const float* ln2g = (const float*)d_in[11];
    const float* ln2b = (const float*)d_in[12];
    const float* gw1  = (const float*)d_in[13];
    const float* gb1  = (const float*)d_in[14];
    const float* gw2  = (const float*)d_in[15];
    const float* gb2  = (const float*)d_in[16];
    const float* ew1  = (const float*)d_in[17];
    const float* eb1  = (const float*)d_in[18];
    const float* ew2  = (const float*)d_in[19];
    const float* eb2  = (const float*)d_in[20];
    float* out = (float*)d_out;

    __half *h1h, *qkvh, *aoh, *h2h, *h2l, *hidh, *eo;
    __half *wqkvh, *woh, *ew1h, *ew2h, *gw1h, *gw1l;
    float *x1, *gh, *w, *qkvb;
    int *cnt, *elist;
    cudaGetSymbolAddress((void**)&h1h,  g_h1h);
    cudaGetSymbolAddress((void**)&qkvh, g_qkvh);
    cudaGetSymbolAddress((void**)&aoh,  g_aoh);
    cudaGetSymbolAddress((void**)&x1,   g_x1);
    cudaGetSymbolAddress((void**)&h2h,  g_h2h);
    cudaGetSymbolAddress((void**)&h2l,  g_h2l);
    cudaGetSymbolAddress((void**)&gh,   g_gh);
    cudaGetSymbolAddress((void**)&w,    g_w);
    cudaGetSymbolAddress((void**)&hidh, g_hidh);
    cudaGetSymbolAddress((void**)&eo,   g_eo);
    cudaGetSymbolAddress((void**)&cnt,  g_cnt);
    cudaGetSymbolAddress((void**)&elist,g_elist);
    cudaGetSymbolAddress((void**)&wqkvh,g_wqkvh);
    cudaGetSymbolAddress((void**)&woh,  g_woh);
    cudaGetSymbolAddress((void**)&ew1h, g_ew1h);
    cudaGetSymbolAddress((void**)&ew2h, g_ew2h);
    cudaGetSymbolAddress((void**)&gw1h, g_gw1h);
    cudaGetSymbolAddress((void**)&gw1l, g_gw1l);
    cudaGetSymbolAddress((void**)&qkvb, g_qkvb);

    cudaFuncSetAttribute(gemm_hc<0,false,false,true>, cudaFuncAttributeMaxDynamicSharedMemorySize, GEMMH_SMEM);
    cudaFuncSetAttribute(gemm_hc<0,false,true,false>, cudaFuncAttributeMaxDynamicSharedMemorySize, GEMMH_SMEM);
    cudaFuncSetAttribute(gemm_hc<2,true,false,true>,  cudaFuncAttributeMaxDynamicSharedMemorySize, GEMMH_SMEM);
    cudaFuncSetAttribute(gemm_hc<0,true,false,true>,  cudaFuncAttributeMaxDynamicSharedMemorySize, GEMMH_SMEM);
    cudaFuncSetAttribute(gemm_gate16, cudaFuncAttributeMaxDynamicSharedMemorySize, GATE_SMEM);
    cudaFuncSetAttribute(fa_h, cudaFuncAttributeMaxDynamicSharedMemorySize, FA_SMEM);

    // launch 0: fused qkv weight convert + bias pack + count zero
    cvt_qkv<<<(QKV_W4 + QKVN + Ez + 255)/256, 256>>>(
        wq, wk, wv, bq, bk, bv, wqkvh, qkvb, cnt);
    // launch 1-3: remaining weight converts
    cvt_c<<<(Dz*Dz/4 + 255)/256, 256>>>(wo, woh, Dz*Dz/4);
    cvt_split<<<(Dz*GHz/4 + 255)/256, 256>>>(gw1, gw1h, gw1l, Dz*GHz/4);
    cvt_c2<<<(2*(int)((size_t)Ez*Dz*EDz/4) + 255)/256, 256>>>(
        ew1, ew1h, ew2, ew2h, (int)((size_t)Ez*Dz*EDz/4));

    // launch 4: LN1
    ln_kernel<false><<<Tz, 256>>>(x, ln1g, ln1b, h1h, nullptr);

    // launch 5 (ncu -s 5 -c 1 target): fused QKV projection
    gemm_hc<0,false,false,true><<<dim3(QKVN/128, 32, 1), 256, GEMMH_SMEM>>>(
        h1h, wqkvh, qkvb, qkvh, Tz, QKVN, Dz, nullptr, nullptr, nullptr, 0);

    fa_h<<<dim3(Sz/128, Bz*Hh), 256, FA_SMEM>>>(qkvh, aoh);

    gemm_hc<0,false,true,false><<<dim3(8, 32, 1), 256, GEMMH_SMEM>>>(
        aoh, woh, bo, x1, Tz, Dz, Dz, x, nullptr, nullptr, 0);

    ln_kernel<true><<<Tz, 256>>>(x1, ln2g, ln2b, h2h, h2l);

    gemm_gate16<<<dim3(GHz/128, Tz/128, 1), 256, GATE_SMEM>>>(
        h2h, h2l, gw1h, gw1l, gb1, gh, Tz, GHz, Dz);

    gate_route_kernel<<<Tz/8, 256>>>(gh, gw2, gb2, w, cnt, elist);

    gemm_hc<2,true,false,true><<<dim3(EDz/128, Tz/128, Ez), 256, GEMMH_SMEM>>>(
        h2h, ew1h, eb1, hidh, Tz, EDz, Dz, nullptr, elist, cnt, 1);
    gemm_hc<0,true,false,true><<<dim3(Dz/128, Tz/128, Ez), 256, GEMMH_SMEM>>>(
        hidh, ew2h, eb2, eo, Tz, Dz, EDz, nullptr, elist, cnt, 0);

    combine_kernel<<<(Tz*Dz/4)/256, 256>>>(x1, eo, w, out);
}